// round 3
// baseline (speedup 1.0000x reference)
#include <cuda_runtime.h>
#include <cuda_bf16.h>
#include <cstdint>
#include <cstddef>

// Problem dims (fixed for this instance)
#define BB    256     // batch
#define TT    64      // time steps (seq_lens[0] == TT by construction)
#define DIN   1024
#define HH    1024
#define EE    256
#define VV    8192
#define FOURH 4096
#define KCAT  2304    // DIN + EE + HH
#define KSPL  1152    // split-K boundary for gates GEMM (multiple of 16)

// ---------------- scratch (no allocation allowed -> __device__ globals) ----
__device__ float g_h[BB * HH];
__device__ float g_c[BB * HH];
__device__ float g_prev[BB * EE];
__device__ float g_gatesP[2 * BB * FOURH];   // split-K partials
__device__ float g_pval[BB * 64];            // per-(row, n-tile) argmax partial
__device__ int   g_pidx[BB * 64];
__device__ int   g_off[BB];                  // exclusive prefix of seq_lens

// ---------------- packed f32x2 helpers (FFMA2: only reachable via PTX) -----
__device__ __forceinline__ unsigned long long pk2(float x, float y) {
    unsigned long long r;
    asm("mov.b64 %0, {%1, %2};" : "=l"(r) : "f"(x), "f"(y));
    return r;
}
__device__ __forceinline__ void upk2(unsigned long long v, float& x, float& y) {
    asm("mov.b64 {%0, %1}, %2;" : "=f"(x), "=f"(y) : "l"(v));
}
__device__ __forceinline__ void ffma2(unsigned long long& d,
                                      unsigned long long a,
                                      unsigned long long b) {
    asm("fma.rn.f32x2 %0, %1, %2, %0;" : "+l"(d) : "l"(a), "l"(b));
}

__device__ __forceinline__ float sigm(float x) {
    return 1.0f / (1.0f + expf(-x));
}

// ---------------- init: h=c=0, prev=broadcast(init_tensor) -----------------
__global__ void k_init(const float* __restrict__ init_tensor) {
    int idx = blockIdx.x * 256 + threadIdx.x;   // grid covers 262144
    if (idx < BB * HH) { g_h[idx] = 0.0f; g_c[idx] = 0.0f; }
    if (idx < BB * EE) { g_prev[idx] = init_tensor[idx & (EE - 1)]; }
}

// ---------------- exclusive prefix sum of seq_lens (tiny) ------------------
__global__ void k_scan(const int* __restrict__ seq_lens) {
    if (threadIdx.x == 0) {
        int acc = 0;
        for (int b = 0; b < BB; b++) { g_off[b] = acc; acc += seq_lens[b]; }
    }
}

// ---------------- GEMM 1: gates = [x_t | prev | h] @ [W_ih | W_hh]^T -------
// Tiles: BM=128, BN=128, BK=16, 256 threads, 8x8 micro held as f32x2 pairs.
// Grid: (4096/128, 256/128, 2 split-K) = (32, 2, 2) = 128 CTAs.
#define BK   16
#define SSTR 136   // smem row stride (floats): 136*4B = 16B-aligned, bank-spread

__global__ __launch_bounds__(256, 2)
void k_gates(const float* __restrict__ enc,
             const float* __restrict__ W_ih,
             const float* __restrict__ W_hh,
             int t) {
    __shared__ float As[BK * SSTR];
    __shared__ float Bs[BK * SSTR];

    const int tid = threadIdx.x;
    const int tx  = tid & 15;       // n-direction (16 threads)
    const int ty  = tid >> 4;       // m-direction (16 threads)
    const int bn  = blockIdx.x * 128;
    const int bm  = blockIdx.y * 128;
    const int kz  = blockIdx.z;
    const int kbeg = kz * KSPL, kend = kbeg + KSPL;

    unsigned long long acc[8][4];
#pragma unroll
    for (int r = 0; r < 8; r++)
#pragma unroll
        for (int p = 0; p < 4; p++) acc[r][p] = 0ull;

    const int aIdx = tid * 2;   // two float4 loads each for A and B

    for (int k0 = kbeg; k0 < kend; k0 += BK) {
        float4 av[2], bv[2];
#pragma unroll
        for (int j = 0; j < 2; j++) {
            int idx  = aIdx + j;
            int row  = idx >> 2;      // 0..127
            int kq   = idx & 3;
            int kk   = k0 + kq * 4;
            int gm   = bm + row;
            const float* pa;
            if (kk < DIN)             pa = enc    + ((size_t)gm * TT + t) * DIN + kk;
            else if (kk < DIN + EE)   pa = g_prev + (size_t)gm * EE + (kk - DIN);
            else                      pa = g_h    + (size_t)gm * HH + (kk - DIN - EE);
            av[j] = *(const float4*)pa;
            int gn = bn + row;
            const float* pb;
            if (kk < DIN + EE)        pb = W_ih + (size_t)gn * (DIN + EE) + kk;
            else                      pb = W_hh + (size_t)gn * HH + (kk - DIN - EE);
            bv[j] = *(const float4*)pb;
        }
        __syncthreads();
#pragma unroll
        for (int j = 0; j < 2; j++) {
            int idx = aIdx + j;
            int row = idx >> 2;
            int kq  = idx & 3;
            float* as = &As[(kq * 4) * SSTR + row];
            as[0 * SSTR] = av[j].x; as[1 * SSTR] = av[j].y;
            as[2 * SSTR] = av[j].z; as[3 * SSTR] = av[j].w;
            float* bs = &Bs[(kq * 4) * SSTR + row];
            bs[0 * SSTR] = bv[j].x; bs[1 * SSTR] = bv[j].y;
            bs[2 * SSTR] = bv[j].z; bs[3 * SSTR] = bv[j].w;
        }
        __syncthreads();
#pragma unroll
        for (int k = 0; k < BK; k++) {
            float4 a0 = *(const float4*)&As[k * SSTR + ty * 8];
            float4 a1 = *(const float4*)&As[k * SSTR + ty * 8 + 4];
            float4 b0 = *(const float4*)&Bs[k * SSTR + tx * 4];
            float4 b1 = *(const float4*)&Bs[k * SSTR + 64 + tx * 4];
            unsigned long long bp0 = pk2(b0.x, b0.y), bp1 = pk2(b0.z, b0.w);
            unsigned long long bp2 = pk2(b1.x, b1.y), bp3 = pk2(b1.z, b1.w);
            float am[8] = {a0.x, a0.y, a0.z, a0.w, a1.x, a1.y, a1.z, a1.w};
#pragma unroll
            for (int r = 0; r < 8; r++) {
                unsigned long long ad = pk2(am[r], am[r]);
                ffma2(acc[r][0], ad, bp0);
                ffma2(acc[r][1], ad, bp1);
                ffma2(acc[r][2], ad, bp2);
                ffma2(acc[r][3], ad, bp3);
            }
        }
    }

    float* dst = g_gatesP + (size_t)kz * BB * FOURH;
#pragma unroll
    for (int r = 0; r < 8; r++) {
        int gm = bm + ty * 8 + r;
        float4 o0, o1;
        upk2(acc[r][0], o0.x, o0.y); upk2(acc[r][1], o0.z, o0.w);
        upk2(acc[r][2], o1.x, o1.y); upk2(acc[r][3], o1.z, o1.w);
        *(float4*)&dst[(size_t)gm * FOURH + bn + tx * 4]      = o0;
        *(float4*)&dst[(size_t)gm * FOURH + bn + 64 + tx * 4] = o1;
    }
}

// ---------------- LSTM cell: c,h update (adds split-K partials + biases) ---
__global__ void k_cell(const float* __restrict__ b_ih,
                       const float* __restrict__ b_hh) {
    int idx = blockIdx.x * 256 + threadIdx.x;   // < 262144
    int b = idx >> 10, j = idx & 1023;
    size_t base = (size_t)b * FOURH;
    const float* P0 = g_gatesP;
    const float* P1 = g_gatesP + (size_t)BB * FOURH;
    float i_ = P0[base + j]        + P1[base + j]        + b_ih[j]        + b_hh[j];
    float f_ = P0[base + 1024 + j] + P1[base + 1024 + j] + b_ih[1024 + j] + b_hh[1024 + j];
    float gg = P0[base + 2048 + j] + P1[base + 2048 + j] + b_ih[2048 + j] + b_hh[2048 + j];
    float o_ = P0[base + 3072 + j] + P1[base + 3072 + j] + b_ih[3072 + j] + b_hh[3072 + j];
    float c = sigm(f_) * g_c[idx] + sigm(i_) * tanhf(gg);
    float h = sigm(o_) * tanhf(c);
    g_c[idx] = c;
    g_h[idx] = h;
}

// ---------------- GEMM 2: logits = h @ lin_W^T + lin_b; write-out + argmax -
// Grid: (8192/128, 256/128) = (64, 2) = 128 CTAs.
__global__ __launch_bounds__(256, 2)
void k_logits(const float* __restrict__ lin_W,
              const float* __restrict__ lin_b,
              const int*   __restrict__ seq_lens,
              float* __restrict__ out,
              int t) {
    __shared__ float As[BK * SSTR];
    __shared__ float Bs[BK * SSTR];

    const int tid = threadIdx.x;
    const int tx  = tid & 15;
    const int ty  = tid >> 4;
    const int bn  = blockIdx.x * 128;
    const int bm  = blockIdx.y * 128;

    unsigned long long acc[8][4];
#pragma unroll
    for (int r = 0; r < 8; r++)
#pragma unroll
        for (int p = 0; p < 4; p++) acc[r][p] = 0ull;

    const int aIdx = tid * 2;

    for (int k0 = 0; k0 < HH; k0 += BK) {
        float4 av[2], bv[2];
#pragma unroll
        for (int j = 0; j < 2; j++) {
            int idx = aIdx + j;
            int row = idx >> 2;
            int kq  = idx & 3;
            int kk  = k0 + kq * 4;
            av[j] = *(const float4*)&g_h[(size_t)(bm + row) * HH + kk];
            bv[j] = *(const float4*)&lin_W[(size_t)(bn + row) * HH + kk];
        }
        __syncthreads();
#pragma unroll
        for (int j = 0; j < 2; j++) {
            int idx = aIdx + j;
            int row = idx >> 2;
            int kq  = idx & 3;
            float* as = &As[(kq * 4) * SSTR + row];
            as[0 * SSTR] = av[j].x; as[1 * SSTR] = av[j].y;
            as[2 * SSTR] = av[j].z; as[3 * SSTR] = av[j].w;
            float* bs = &Bs[(kq * 4) * SSTR + row];
            bs[0 * SSTR] = bv[j].x; bs[1 * SSTR] = bv[j].y;
            bs[2 * SSTR] = bv[j].z; bs[3 * SSTR] = bv[j].w;
        }
        __syncthreads();
#pragma unroll
        for (int k = 0; k < BK; k++) {
            float4 a0 = *(const float4*)&As[k * SSTR + ty * 8];
            float4 a1 = *(const float4*)&As[k * SSTR + ty * 8 + 4];
            float4 b0 = *(const float4*)&Bs[k * SSTR + tx * 4];
            float4 b1 = *(const float4*)&Bs[k * SSTR + 64 + tx * 4];
            unsigned long long bp0 = pk2(b0.x, b0.y), bp1 = pk2(b0.z, b0.w);
            unsigned long long bp2 = pk2(b1.x, b1.y), bp3 = pk2(b1.z, b1.w);
            float am[8] = {a0.x, a0.y, a0.z, a0.w, a1.x, a1.y, a1.z, a1.w};
#pragma unroll
            for (int r = 0; r < 8; r++) {
                unsigned long long ad = pk2(am[r], am[r]);
                ffma2(acc[r][0], ad, bp0);
                ffma2(acc[r][1], ad, bp1);
                ffma2(acc[r][2], ad, bp2);
                ffma2(acc[r][3], ad, bp3);
            }
        }
    }

    // epilogue: + lin_b, conditional ragged write-out, per-tile argmax partial
    float4 lb0 = *(const float4*)&lin_b[bn + tx * 4];
    float4 lb1 = *(const float4*)&lin_b[bn + 64 + tx * 4];

#pragma unroll
    for (int r = 0; r < 8; r++) {
        int gm = bm + ty * 8 + r;
        float4 o0, o1;
        upk2(acc[r][0], o0.x, o0.y); upk2(acc[r][1], o0.z, o0.w);
        upk2(acc[r][2], o1.x, o1.y); upk2(acc[r][3], o1.z, o1.w);
        o0.x += lb0.x; o0.y += lb0.y; o0.z += lb0.z; o0.w += lb0.w;
        o1.x += lb1.x; o1.y += lb1.y; o1.z += lb1.z; o1.w += lb1.w;

        int len = seq_lens[gm];
        if (t < len) {
            float* orow = out + (size_t)(g_off[gm] + t) * VV;
            *(float4*)&orow[bn + tx * 4]      = o0;
            *(float4*)&orow[bn + 64 + tx * 4] = o1;
        }

        // per-thread argmax over its 8 columns (first-max tie rule = lower idx)
        float bvv = o0.x; int bii = bn + tx * 4;
        float vv[7]  = {o0.y, o0.z, o0.w, o1.x, o1.y, o1.z, o1.w};
        int   ii[7]  = {bn + tx * 4 + 1, bn + tx * 4 + 2, bn + tx * 4 + 3,
                        bn + 64 + tx * 4, bn + 64 + tx * 4 + 1,
                        bn + 64 + tx * 4 + 2, bn + 64 + tx * 4 + 3};
#pragma unroll
        for (int q = 0; q < 7; q++) {
            if (vv[q] > bvv || (vv[q] == bvv && ii[q] < bii)) { bvv = vv[q]; bii = ii[q]; }
        }
        // reduce across the 16 n-threads of this row (width-16 butterfly)
#pragma unroll
        for (int off = 8; off; off >>= 1) {
            float ov = __shfl_xor_sync(0xffffffffu, bvv, off, 16);
            int   oi = __shfl_xor_sync(0xffffffffu, bii, off, 16);
            if (ov > bvv || (ov == bvv && oi < bii)) { bvv = ov; bii = oi; }
        }
        if (tx == 0) {
            g_pval[(size_t)gm * 64 + blockIdx.x] = bvv;
            g_pidx[(size_t)gm * 64 + blockIdx.x] = bii;
        }
    }
}

// ---------------- final argmax across 64 n-tiles + embedding gather --------
__global__ void k_final(const float* __restrict__ embedding) {
    int b   = blockIdx.x;
    int tid = threadIdx.x;   // 64 threads
    float v = g_pval[(size_t)b * 64 + tid];
    int   i = g_pidx[(size_t)b * 64 + tid];
#pragma unroll
    for (int off = 16; off; off >>= 1) {
        float ov = __shfl_xor_sync(0xffffffffu, v, off);
        int   oi = __shfl_xor_sync(0xffffffffu, i, off);
        if (ov > v || (ov == v && oi < i)) { v = ov; i = oi; }
    }
    __shared__ float sv[2];
    __shared__ int   si[2];
    if ((tid & 31) == 0) { sv[tid >> 5] = v; si[tid >> 5] = i; }
    __syncthreads();
    float v0 = sv[0], v1 = sv[1];
    int   i0 = si[0], i1 = si[1];
    int best = (v1 > v0 || (v1 == v0 && i1 < i0)) ? i1 : i0;
    for (int e = tid; e < EE; e += 64)
        g_prev[(size_t)b * EE + e] = embedding[(size_t)best * EE + e];
}

// ---------------- launch ----------------------------------------------------
extern "C" void kernel_launch(void* const* d_in, const int* in_sizes, int n_in,
                              void* d_out, int out_size) {
    const float* enc      = (const float*)d_in[0];
    const float* emb      = (const float*)d_in[1];
    const float* init_t   = (const float*)d_in[2];
    const float* W_ih     = (const float*)d_in[3];
    const float* W_hh     = (const float*)d_in[4];
    const float* b_ih     = (const float*)d_in[5];
    const float* b_hh     = (const float*)d_in[6];
    const float* lin_W    = (const float*)d_in[7];
    const float* lin_b    = (const float*)d_in[8];
    const int*   seq_lens = (const int*)d_in[9];
    float*       out      = (float*)d_out;

    k_init<<<(BB * HH + 255) / 256, 256>>>(init_t);
    k_scan<<<1, 32>>>(seq_lens);

    for (int t = 0; t < TT; t++) {
        k_gates<<<dim3(FOURH / 128, BB / 128, 2), 256>>>(enc, W_ih, W_hh, t);
        k_cell<<<(BB * HH + 255) / 256, 256>>>(b_ih, b_hh);
        k_logits<<<dim3(VV / 128, BB / 128), 256>>>(lin_W, lin_b, seq_lens, out, t);
        k_final<<<BB, 64>>>(emb);
    }
}

// round 5
// speedup vs baseline: 1.3310x; 1.3310x over previous
#include <cuda_runtime.h>
#include <cstdint>
#include <cstddef>

// Problem dims (fixed)
#define BB    256
#define TT    64
#define DIN   1024
#define HH    1024
#define EE    256
#define VV    8192
#define FOURH 4096
#define KCAT  2304
#define KSPL  1152            // gates split-K half
#define BK    16
#define NCG   (KSPL / BK)     // 72 chunks
#define NCL   (HH / BK)       // 64 chunks
#define SR    20              // smem row stride in floats (16B-aligned rows, bank-perfect)
#define MS    (128 * SR)      // floats per matrix tile (2560)

// ---------------- scratch ----------------------------------------------------
__device__ float g_h[BB * HH];
__device__ float g_c[BB * HH];
__device__ float g_prev[BB * EE];
__device__ float g_gatesP[2 * BB * FOURH];
__device__ float g_pval[BB * 256];
__device__ int   g_pidx[BB * 256];
__device__ int   g_off[BB];

// ---------------- helpers -----------------------------------------------------
__device__ __forceinline__ float tf32r(float x) {
    uint32_t u;
    asm("cvt.rna.tf32.f32 %0, %1;" : "=r"(u) : "f"(x));
    return __uint_as_float(u);
}
__device__ __forceinline__ void split4(float4 v, float4& h, float4& l) {
    h.x = tf32r(v.x); h.y = tf32r(v.y); h.z = tf32r(v.z); h.w = tf32r(v.w);
    l.x = tf32r(v.x - h.x); l.y = tf32r(v.y - h.y);
    l.z = tf32r(v.z - h.z); l.w = tf32r(v.w - h.w);
}
__device__ __forceinline__ void mma8(float* c, const uint32_t* a, const uint32_t* b) {
    asm volatile(
        "mma.sync.aligned.m16n8k8.row.col.f32.tf32.tf32.f32 "
        "{%0,%1,%2,%3}, {%4,%5,%6,%7}, {%8,%9}, {%0,%1,%2,%3};"
        : "+f"(c[0]), "+f"(c[1]), "+f"(c[2]), "+f"(c[3])
        : "r"(a[0]), "r"(a[1]), "r"(a[2]), "r"(a[3]), "r"(b[0]), "r"(b[1]));
}
__device__ __forceinline__ float sigm(float x) { return 1.0f / (1.0f + expf(-x)); }

// ---------------- init / scan -------------------------------------------------
__global__ void k_init(const float* __restrict__ init_tensor) {
    int idx = blockIdx.x * 256 + threadIdx.x;
    if (idx < BB * HH) { g_h[idx] = 0.0f; g_c[idx] = 0.0f; }
    if (idx < BB * EE) { g_prev[idx] = init_tensor[idx & (EE - 1)]; }
}
__global__ void k_scan(const int* __restrict__ seq_lens) {
    if (threadIdx.x == 0) {
        int acc = 0;
        for (int b = 0; b < BB; b++) { g_off[b] = acc; acc += seq_lens[b]; }
    }
}

// ============ shared compute core (fragment loads + 3-pass mma) ===============
// S layout (floats): AHI=0, ALO=MS, BHI=2*MS, BLO=3*MS
struct Frag { uint32_t ah[4][4], al[4][4], bh[4][2], bl[4][2]; };

__device__ __forceinline__ void compute_chunk(const float* S, int wm, int wn,
                                              int g, int tig, float acc[4][4][4]) {
    const float* AHI = S;
    const float* ALO = S + MS;
    const float* BHI = S + 2 * MS;
    const float* BLO = S + 3 * MS;
#pragma unroll
    for (int ks = 0; ks < 2; ks++) {
        int kb = ks * 8;
        Frag f;
#pragma unroll
        for (int mt = 0; mt < 4; mt++) {
            int r0 = (wm * 64 + mt * 16 + g) * SR + kb + tig;
            int r1 = r0 + 8 * SR;
            f.ah[mt][0] = __float_as_uint(AHI[r0]);
            f.ah[mt][1] = __float_as_uint(AHI[r1]);
            f.ah[mt][2] = __float_as_uint(AHI[r0 + 4]);
            f.ah[mt][3] = __float_as_uint(AHI[r1 + 4]);
            f.al[mt][0] = __float_as_uint(ALO[r0]);
            f.al[mt][1] = __float_as_uint(ALO[r1]);
            f.al[mt][2] = __float_as_uint(ALO[r0 + 4]);
            f.al[mt][3] = __float_as_uint(ALO[r1 + 4]);
        }
#pragma unroll
        for (int nt = 0; nt < 4; nt++) {
            int n0 = (wn * 32 + nt * 8 + g) * SR + kb + tig;
            f.bh[nt][0] = __float_as_uint(BHI[n0]);
            f.bh[nt][1] = __float_as_uint(BHI[n0 + 4]);
            f.bl[nt][0] = __float_as_uint(BLO[n0]);
            f.bl[nt][1] = __float_as_uint(BLO[n0 + 4]);
        }
#pragma unroll
        for (int mt = 0; mt < 4; mt++)
#pragma unroll
            for (int nt = 0; nt < 4; nt++) mma8(acc[mt][nt], f.ah[mt], f.bh[nt]);
#pragma unroll
        for (int mt = 0; mt < 4; mt++)
#pragma unroll
            for (int nt = 0; nt < 4; nt++) mma8(acc[mt][nt], f.ah[mt], f.bl[nt]);
#pragma unroll
        for (int mt = 0; mt < 4; mt++)
#pragma unroll
            for (int nt = 0; nt < 4; nt++) mma8(acc[mt][nt], f.al[mt], f.bh[nt]);
    }
}

__device__ __forceinline__ void sts_chunk(float* S, int tid,
                                          const float4* av, const float4* bv) {
#pragma unroll
    for (int j = 0; j < 2; j++) {
        int idx = j * 256 + tid;
        int row = idx >> 2;
        int kq  = idx & 3;
        int o   = row * SR + kq * 4;
        float4 h, l;
        split4(av[j], h, l);
        *(float4*)&S[o]      = h;
        *(float4*)&S[MS + o] = l;
        split4(bv[j], h, l);
        *(float4*)&S[2 * MS + o] = h;
        *(float4*)&S[3 * MS + o] = l;
    }
}

// ---------------- GEMM 1: gates partials (split-K=2) --------------------------
// grid (32, 2, 2) = 128 CTAs
__global__ __launch_bounds__(256, 1)
void k_gates(const float* __restrict__ enc,
             const float* __restrict__ W_ih,
             const float* __restrict__ W_hh,
             int t) {
    __shared__ float S[4 * MS];
    const int tid = threadIdx.x;
    const int wid = tid >> 5;
    const int wm  = wid >> 2, wn = wid & 3;
    const int g   = (tid & 31) >> 2, tig = tid & 3;
    const int bn  = blockIdx.x * 128;
    const int bm  = blockIdx.y * 128;
    const int kz  = blockIdx.z;
    const int kbeg = kz * KSPL;

    float acc[4][4][4];
#pragma unroll
    for (int a = 0; a < 4; a++)
#pragma unroll
        for (int b = 0; b < 4; b++)
#pragma unroll
            for (int c = 0; c < 4; c++) acc[a][b][c] = 0.0f;

    float4 av[2], bv[2];
    auto load_g = [&](int ch) {
        int kkb = kbeg + ch * BK;
#pragma unroll
        for (int j = 0; j < 2; j++) {
            int idx = j * 256 + tid;
            int row = idx >> 2;
            int kq  = idx & 3;
            int kk  = kkb + kq * 4;
            int gm  = bm + row;
            const float* pa;
            if (kk < DIN)            pa = enc    + ((size_t)gm * TT + t) * DIN + kk;
            else if (kk < DIN + EE)  pa = g_prev + (size_t)gm * EE + (kk - DIN);
            else                     pa = g_h    + (size_t)gm * HH + (kk - DIN - EE);
            av[j] = *(const float4*)pa;
            int gn = bn + row;
            const float* pb = (kk < DIN + EE)
                ? (W_ih + (size_t)gn * (DIN + EE) + kk)
                : (W_hh + (size_t)gn * HH + (kk - DIN - EE));
            bv[j] = *(const float4*)pb;
        }
    };

    load_g(0);
    for (int i = 0; i < NCG; i++) {
        __syncthreads();
        sts_chunk(S, tid, av, bv);
        __syncthreads();
        if (i + 1 < NCG) load_g(i + 1);
        compute_chunk(S, wm, wn, g, tig, acc);
    }

    // epilogue: write split-K partials
    float* dst = g_gatesP + (size_t)kz * BB * FOURH;
#pragma unroll
    for (int mt = 0; mt < 4; mt++) {
        int r0 = bm + wm * 64 + mt * 16 + g;
        int r1 = r0 + 8;
#pragma unroll
        for (int nt = 0; nt < 4; nt++) {
            int col = bn + wn * 32 + nt * 8 + 2 * tig;
            *(float2*)&dst[(size_t)r0 * FOURH + col] =
                make_float2(acc[mt][nt][0], acc[mt][nt][1]);
            *(float2*)&dst[(size_t)r1 * FOURH + col] =
                make_float2(acc[mt][nt][2], acc[mt][nt][3]);
        }
    }
}

// ---------------- LSTM cell ---------------------------------------------------
__global__ void k_cell(const float* __restrict__ b_ih,
                       const float* __restrict__ b_hh) {
    int idx = blockIdx.x * 256 + threadIdx.x;
    int b = idx >> 10, j = idx & 1023;
    size_t base = (size_t)b * FOURH;
    const float* P0 = g_gatesP;
    const float* P1 = g_gatesP + (size_t)BB * FOURH;
    float i_ = P0[base + j]        + P1[base + j]        + b_ih[j]        + b_hh[j];
    float f_ = P0[base + 1024 + j] + P1[base + 1024 + j] + b_ih[1024 + j] + b_hh[1024 + j];
    float gg = P0[base + 2048 + j] + P1[base + 2048 + j] + b_ih[2048 + j] + b_hh[2048 + j];
    float o_ = P0[base + 3072 + j] + P1[base + 3072 + j] + b_ih[3072 + j] + b_hh[3072 + j];
    float c = sigm(f_) * g_c[idx] + sigm(i_) * tanhf(gg);
    float h = sigm(o_) * tanhf(c);
    g_c[idx] = c;
    g_h[idx] = h;
}

// ---------------- GEMM 2: logits + ragged out + argmax ------------------------
// grid (64, 2) = 128 CTAs
__global__ __launch_bounds__(256, 1)
void k_logits(const float* __restrict__ lin_W,
              const float* __restrict__ lin_b,
              const int*   __restrict__ seq_lens,
              float* __restrict__ out,
              int t) {
    __shared__ float S[4 * MS];
    const int tid = threadIdx.x;
    const int wid = tid >> 5;
    const int wm  = wid >> 2, wn = wid & 3;
    const int g   = (tid & 31) >> 2, tig = tid & 3;
    const int bn  = blockIdx.x * 128;
    const int bm  = blockIdx.y * 128;

    float acc[4][4][4];
#pragma unroll
    for (int a = 0; a < 4; a++)
#pragma unroll
        for (int b = 0; b < 4; b++)
#pragma unroll
            for (int c = 0; c < 4; c++) acc[a][b][c] = 0.0f;

    float4 av[2], bv[2];
    auto load_g = [&](int ch) {
        int kkb = ch * BK;
#pragma unroll
        for (int j = 0; j < 2; j++) {
            int idx = j * 256 + tid;
            int row = idx >> 2;
            int kq  = idx & 3;
            int kk  = kkb + kq * 4;
            av[j] = *(const float4*)&g_h[(size_t)(bm + row) * HH + kk];
            bv[j] = *(const float4*)&lin_W[(size_t)(bn + row) * HH + kk];
        }
    };

    load_g(0);
    for (int i = 0; i < NCL; i++) {
        __syncthreads();
        sts_chunk(S, tid, av, bv);
        __syncthreads();
        if (i + 1 < NCL) load_g(i + 1);
        compute_chunk(S, wm, wn, g, tig, acc);
    }

    // epilogue: +bias, ragged store, argmax partials (2 rows per lane)
#pragma unroll
    for (int half = 0; half < 2; half++) {   // half 0 -> rows +g, half 1 -> rows +g+8
#pragma unroll
        for (int mt = 0; mt < 4; mt++) {
            int gm = bm + wm * 64 + mt * 16 + g + half * 8;
            int len = seq_lens[gm];
            bool wr = (t < len);
            float* orow = out + (size_t)(g_off[gm] + t) * VV;

            float bvv = -3.4e38f;
            int   bii = 0;
#pragma unroll
            for (int nt = 0; nt < 4; nt++) {
                int col = bn + wn * 32 + nt * 8 + 2 * tig;
                float v0 = acc[mt][nt][half * 2 + 0] + lin_b[col];
                float v1 = acc[mt][nt][half * 2 + 1] + lin_b[col + 1];
                if (wr) *(float2*)&orow[col] = make_float2(v0, v1);
                if (v0 > bvv) { bvv = v0; bii = col; }
                if (v1 > bvv) { bvv = v1; bii = col + 1; }
            }
            // reduce across the 4 lanes (tig) sharing this row
#pragma unroll
            for (int off = 1; off < 4; off <<= 1) {
                float ov = __shfl_xor_sync(0xffffffffu, bvv, off, 4);
                int   oi = __shfl_xor_sync(0xffffffffu, bii, off, 4);
                if (ov > bvv || (ov == bvv && oi < bii)) { bvv = ov; bii = oi; }
            }
            if (tig == 0) {
                int slot = blockIdx.x * 4 + wn;   // 256 n-partials per row
                g_pval[(size_t)gm * 256 + slot] = bvv;
                g_pidx[(size_t)gm * 256 + slot] = bii;
            }
        }
    }
}

// ---------------- final argmax (256 partials/row) + embedding gather ----------
__global__ void k_final(const float* __restrict__ embedding) {
    int b    = blockIdx.x;
    int tid  = threadIdx.x;   // 256 threads
    int lane = tid & 31;
    int w    = tid >> 5;
    float v = g_pval[(size_t)b * 256 + tid];
    int   i = g_pidx[(size_t)b * 256 + tid];
#pragma unroll
    for (int off = 16; off; off >>= 1) {
        float ov = __shfl_xor_sync(0xffffffffu, v, off);
        int   oi = __shfl_xor_sync(0xffffffffu, i, off);
        if (ov > v || (ov == v && oi < i)) { v = ov; i = oi; }
    }
    __shared__ float sv[8];
    __shared__ int   si[8];
    __shared__ int   sbest;
    if (lane == 0) { sv[w] = v; si[w] = i; }
    __syncthreads();
    if (tid == 0) {
        float bvv = sv[0]; int bii = si[0];
#pragma unroll
        for (int q = 1; q < 8; q++)
            if (sv[q] > bvv || (sv[q] == bvv && si[q] < bii)) { bvv = sv[q]; bii = si[q]; }
        sbest = bii;
    }
    __syncthreads();
    int best = sbest;
    g_prev[(size_t)b * EE + tid] = embedding[(size_t)best * EE + tid];
}

// ---------------- launch ------------------------------------------------------
extern "C" void kernel_launch(void* const* d_in, const int* in_sizes, int n_in,
                              void* d_out, int out_size) {
    const float* enc      = (const float*)d_in[0];
    const float* emb      = (const float*)d_in[1];
    const float* init_t   = (const float*)d_in[2];
    const float* W_ih     = (const float*)d_in[3];
    const float* W_hh     = (const float*)d_in[4];
    const float* b_ih     = (const float*)d_in[5];
    const float* b_hh     = (const float*)d_in[6];
    const float* lin_W    = (const float*)d_in[7];
    const float* lin_b    = (const float*)d_in[8];
    const int*   seq_lens = (const int*)d_in[9];
    float*       out      = (float*)d_out;

    k_init<<<(BB * HH + 255) / 256, 256>>>(init_t);
    k_scan<<<1, 32>>>(seq_lens);

    for (int t = 0; t < TT; t++) {
        k_gates<<<dim3(FOURH / 128, BB / 128, 2), 256>>>(enc, W_ih, W_hh, t);
        k_cell<<<(BB * HH + 255) / 256, 256>>>(b_ih, b_hh);
        k_logits<<<dim3(VV / 128, BB / 128), 256>>>(lin_W, lin_b, seq_lens, out, t);
        k_final<<<BB, 256>>>(emb);
    }
}

// round 6
// speedup vs baseline: 1.3343x; 1.0025x over previous
#include <cuda_runtime.h>
#include <cstdint>
#include <cstddef>

// Problem dims (fixed)
#define BB    256
#define TT    64
#define DIN   1024
#define HH    1024
#define EE    256
#define VV    8192
#define FOURH 4096
#define KCAT  2304            // DIN + EE + HH
#define BK    16
#define SR    20              // smem row stride (floats), bank-perfect
#define MSL   (128 * SR)      // logits tile floats per matrix

// ---------------- scratch ----------------------------------------------------
__device__ float g_h[BB * HH];
__device__ float g_c[BB * HH];
__device__ float g_prev[BB * EE];
__device__ float g_P[4][64][FOURH];      // gates partials: [q][local row][4H]
__device__ float g_logP[2][128][VV];     // logits split-K partials
__device__ int   g_lcnt[64];             // logits combine counters (zero-init)
__device__ float g_pval[BB * 256];
__device__ int   g_pidx[BB * 256];
__device__ int   g_off[BB];
__device__ int   g_nb[TT];               // active rows per step

// ---------------- helpers -----------------------------------------------------
__device__ __forceinline__ float tf32r(float x) {
    uint32_t u;
    asm("cvt.rna.tf32.f32 %0, %1;" : "=r"(u) : "f"(x));
    return __uint_as_float(u);
}
__device__ __forceinline__ void split4(float4 v, float4& h, float4& l) {
    h.x = tf32r(v.x); h.y = tf32r(v.y); h.z = tf32r(v.z); h.w = tf32r(v.w);
    l.x = tf32r(v.x - h.x); l.y = tf32r(v.y - h.y);
    l.z = tf32r(v.z - h.z); l.w = tf32r(v.w - h.w);
}
__device__ __forceinline__ void mma8(float* c, const uint32_t* a, const uint32_t* b) {
    asm volatile(
        "mma.sync.aligned.m16n8k8.row.col.f32.tf32.tf32.f32 "
        "{%0,%1,%2,%3}, {%4,%5,%6,%7}, {%8,%9}, {%0,%1,%2,%3};"
        : "+f"(c[0]), "+f"(c[1]), "+f"(c[2]), "+f"(c[3])
        : "r"(a[0]), "r"(a[1]), "r"(a[2]), "r"(a[3]), "r"(b[0]), "r"(b[1]));
}
__device__ __forceinline__ float sigm(float x) { return 1.0f / (1.0f + expf(-x)); }

// ---------------- init / scan -------------------------------------------------
__global__ void k_init(const float* __restrict__ init_tensor) {
    int idx = blockIdx.x * 256 + threadIdx.x;
    if (idx < BB * HH) { g_h[idx] = 0.0f; g_c[idx] = 0.0f; }
    if (idx < BB * EE) { g_prev[idx] = init_tensor[idx & (EE - 1)]; }
}
__global__ void k_scan(const int* __restrict__ seq_lens) {
    int t = threadIdx.x;  // 64 threads
    if (t == 0) {
        int acc = 0;
        for (int b = 0; b < BB; b++) { g_off[b] = acc; acc += seq_lens[b]; }
    }
    if (t < TT) {
        int c = 0;
        for (int b = 0; b < BB; b++) c += (seq_lens[b] > t) ? 1 : 0;
        g_nb[t] = c;
    }
}

// ================= GEMM 1: gates (BM=64, mode-adaptive) =======================
// grid (32 n-tiles, 4) = 128 CTAs. 8 warps: wm=wid>>2 (2x32 rows), wn=wid&3.
// smem: AHI 64*SR | ALO 64*SR | BHI 128*SR | BLO 128*SR
__global__ __launch_bounds__(256, 1)
void k_gates(const float* __restrict__ enc,
             const float* __restrict__ W_ih,
             const float* __restrict__ W_hh,
             int t) {
    const int nbt = g_nb[t];
    const int q   = blockIdx.y;
    int mt, kbeg, kend;
    if (nbt > 128) {                 // mode 4: one m-tile per CTA, full K
        mt = q; kbeg = 0; kend = KCAT;
        if (mt * 64 >= nbt) return;  // fully inactive tile
    } else if (nbt > 64) {           // mode 2: 2 m-tiles x K/2
        mt = q >> 1; kbeg = (q & 1) * (KCAT / 2); kend = kbeg + KCAT / 2;
    } else {                         // mode 1: 1 m-tile x K/4
        mt = 0; kbeg = q * (KCAT / 4); kend = kbeg + KCAT / 4;
    }
    const int bm = mt * 64;
    const int bn = blockIdx.x * 128;
    const int nch = (kend - kbeg) >> 4;

    __shared__ float S[384 * SR];
    float* AHI = S;
    float* ALO = S + 64 * SR;
    float* BHI = S + 128 * SR;
    float* BLO = S + 256 * SR;

    const int tid = threadIdx.x;
    const int wid = tid >> 5;
    const int wm  = wid >> 2, wn = wid & 3;
    const int g   = (tid & 31) >> 2, tig = tid & 3;

    float acc[2][4][4];
#pragma unroll
    for (int a = 0; a < 2; a++)
#pragma unroll
        for (int b = 0; b < 4; b++)
#pragma unroll
            for (int c = 0; c < 4; c++) acc[a][b][c] = 0.0f;

    float4 av, bv[2];
    auto load_g = [&](int ch) {
        int kkb = kbeg + ch * BK;
        {   // A: 64 rows x 16 -> 1 float4/thread
            int row = tid >> 2, kq = tid & 3;
            int kk = kkb + kq * 4;
            int gm = bm + row;
            const float* pa;
            if (kk < DIN)            pa = enc    + ((size_t)gm * TT + t) * DIN + kk;
            else if (kk < DIN + EE)  pa = g_prev + (size_t)gm * EE + (kk - DIN);
            else                     pa = g_h    + (size_t)gm * HH + (kk - DIN - EE);
            av = *(const float4*)pa;
        }
#pragma unroll
        for (int j = 0; j < 2; j++) {  // B: 128 rows x 16 -> 2 float4/thread
            int idx = j * 256 + tid;
            int row = idx >> 2, kq = idx & 3;
            int kk = kkb + kq * 4;
            int gn = bn + row;
            const float* pb = (kk < DIN + EE)
                ? (W_ih + (size_t)gn * (DIN + EE) + kk)
                : (W_hh + (size_t)gn * HH + (kk - DIN - EE));
            bv[j] = *(const float4*)pb;
        }
    };

    load_g(0);
    for (int i = 0; i < nch; i++) {
        __syncthreads();
        {   // STS with split
            int row = tid >> 2, kq = tid & 3;
            int o = row * SR + kq * 4;
            float4 h, l;
            split4(av, h, l);
            *(float4*)&AHI[o] = h; *(float4*)&ALO[o] = l;
#pragma unroll
            for (int j = 0; j < 2; j++) {
                int idx = j * 256 + tid;
                int rowb = idx >> 2, kqb = idx & 3;
                int ob = rowb * SR + kqb * 4;
                split4(bv[j], h, l);
                *(float4*)&BHI[ob] = h; *(float4*)&BLO[ob] = l;
            }
        }
        __syncthreads();
        if (i + 1 < nch) load_g(i + 1);
        // compute
#pragma unroll
        for (int ks = 0; ks < 2; ks++) {
            int kb = ks * 8;
            uint32_t ah[2][4], al[2][4], bh[4][2], bl[4][2];
#pragma unroll
            for (int m = 0; m < 2; m++) {
                int r0 = (wm * 32 + m * 16 + g) * SR + kb + tig;
                int r1 = r0 + 8 * SR;
                ah[m][0] = __float_as_uint(AHI[r0]);
                ah[m][1] = __float_as_uint(AHI[r1]);
                ah[m][2] = __float_as_uint(AHI[r0 + 4]);
                ah[m][3] = __float_as_uint(AHI[r1 + 4]);
                al[m][0] = __float_as_uint(ALO[r0]);
                al[m][1] = __float_as_uint(ALO[r1]);
                al[m][2] = __float_as_uint(ALO[r0 + 4]);
                al[m][3] = __float_as_uint(ALO[r1 + 4]);
            }
#pragma unroll
            for (int n = 0; n < 4; n++) {
                int n0 = (wn * 32 + n * 8 + g) * SR + kb + tig;
                bh[n][0] = __float_as_uint(BHI[n0]);
                bh[n][1] = __float_as_uint(BHI[n0 + 4]);
                bl[n][0] = __float_as_uint(BLO[n0]);
                bl[n][1] = __float_as_uint(BLO[n0 + 4]);
            }
#pragma unroll
            for (int m = 0; m < 2; m++)
#pragma unroll
                for (int n = 0; n < 4; n++) mma8(acc[m][n], ah[m], bh[n]);
#pragma unroll
            for (int m = 0; m < 2; m++)
#pragma unroll
                for (int n = 0; n < 4; n++) mma8(acc[m][n], ah[m], bl[n]);
#pragma unroll
            for (int m = 0; m < 2; m++)
#pragma unroll
                for (int n = 0; n < 4; n++) mma8(acc[m][n], al[m], bh[n]);
        }
    }

    // epilogue: write partial to g_P[q][local row][col]
#pragma unroll
    for (int m = 0; m < 2; m++) {
        int lr0 = wm * 32 + m * 16 + g;
        int lr1 = lr0 + 8;
#pragma unroll
        for (int n = 0; n < 4; n++) {
            int col = bn + wn * 32 + n * 8 + 2 * tig;
            *(float2*)&g_P[q][lr0][col] = make_float2(acc[m][n][0], acc[m][n][1]);
            *(float2*)&g_P[q][lr1][col] = make_float2(acc[m][n][2], acc[m][n][3]);
        }
    }
}

// ---------------- LSTM cell (mode-aware partial gather) -----------------------
__global__ void k_cell(const float* __restrict__ b_ih,
                       const float* __restrict__ b_hh,
                       int t) {
    int idx = blockIdx.x * 256 + threadIdx.x;
    int b = idx >> 10, j = idx & 1023;
    int nbt = g_nb[t];
    int na = (nbt + 63) & ~63;
    if (b >= na) return;

    float i_, f_, gg, o_;
    if (nbt > 128) {
        const float* P = g_P[b >> 6][b & 63];
        i_ = P[j]; f_ = P[1024 + j]; gg = P[2048 + j]; o_ = P[3072 + j];
    } else if (nbt > 64) {
        int q0 = (b >> 6) * 2;
        const float* P0 = g_P[q0][b & 63];
        const float* P1 = g_P[q0 + 1][b & 63];
        i_ = P0[j] + P1[j];
        f_ = P0[1024 + j] + P1[1024 + j];
        gg = P0[2048 + j] + P1[2048 + j];
        o_ = P0[3072 + j] + P1[3072 + j];
    } else {
        const float* P0 = g_P[0][b];
        const float* P1 = g_P[1][b];
        const float* P2 = g_P[2][b];
        const float* P3 = g_P[3][b];
        i_ = (P0[j] + P1[j]) + (P2[j] + P3[j]);
        f_ = (P0[1024 + j] + P1[1024 + j]) + (P2[1024 + j] + P3[1024 + j]);
        gg = (P0[2048 + j] + P1[2048 + j]) + (P2[2048 + j] + P3[2048 + j]);
        o_ = (P0[3072 + j] + P1[3072 + j]) + (P2[3072 + j] + P3[3072 + j]);
    }
    i_ += b_ih[j] + b_hh[j];
    f_ += b_ih[1024 + j] + b_hh[1024 + j];
    gg += b_ih[2048 + j] + b_hh[2048 + j];
    o_ += b_ih[3072 + j] + b_hh[3072 + j];
    float c = sigm(f_) * g_c[idx] + sigm(i_) * tanhf(gg);
    float h = sigm(o_) * tanhf(c);
    g_c[idx] = c;
    g_h[idx] = h;
}

// ================= GEMM 2: logits (BM=128, adaptive split-K) ==================
// grid (64 n-tiles, 2) = 128 CTAs. 8 warps: wm=wid>>2 (2x64 rows), wn=wid&3.
__device__ __forceinline__ void logits_out(
    float acc[4][4][4], const float* OP,   // other partial base (or null)
    const float* __restrict__ lin_b, const int* __restrict__ seq_lens,
    float* __restrict__ out, int t,
    int bm, int bn, int wm, int wn, int g, int tig, int bx) {
#pragma unroll
    for (int half = 0; half < 2; half++) {
#pragma unroll
        for (int mt = 0; mt < 4; mt++) {
            int lr = wm * 64 + mt * 16 + g + half * 8;
            int gm = bm + lr;
            int len = seq_lens[gm];
            bool wr = (t < len);
            float* orow = out + (size_t)(g_off[gm] + t) * VV;

            float bvv = -3.4e38f;
            int   bii = 0;
#pragma unroll
            for (int nt = 0; nt < 4; nt++) {
                int col = bn + wn * 32 + nt * 8 + 2 * tig;
                float v0 = acc[mt][nt][half * 2 + 0];
                float v1 = acc[mt][nt][half * 2 + 1];
                if (OP) {
                    v0 += __ldcg(&OP[(size_t)lr * VV + col]);
                    v1 += __ldcg(&OP[(size_t)lr * VV + col + 1]);
                }
                v0 += lin_b[col];
                v1 += lin_b[col + 1];
                if (wr) *(float2*)&orow[col] = make_float2(v0, v1);
                if (v0 > bvv) { bvv = v0; bii = col; }
                if (v1 > bvv) { bvv = v1; bii = col + 1; }
            }
#pragma unroll
            for (int off = 1; off < 4; off <<= 1) {
                float ov = __shfl_xor_sync(0xffffffffu, bvv, off, 4);
                int   oi = __shfl_xor_sync(0xffffffffu, bii, off, 4);
                if (ov > bvv || (ov == bvv && oi < bii)) { bvv = ov; bii = oi; }
            }
            if (tig == 0) {
                int slot = bx * 4 + wn;
                g_pval[(size_t)gm * 256 + slot] = bvv;
                g_pidx[(size_t)gm * 256 + slot] = bii;
            }
        }
    }
}

__global__ __launch_bounds__(256, 1)
void k_logits(const float* __restrict__ lin_W,
              const float* __restrict__ lin_b,
              const int*   __restrict__ seq_lens,
              float* __restrict__ out,
              int t) {
    const int nbt = g_nb[t];
    const bool split = (nbt <= 128);
    const int by = blockIdx.y;
    const int bm = split ? 0 : by * 128;
    const int kbeg = split ? by * (HH / 2) : 0;
    const int nch = (split ? (HH / 2) : HH) >> 4;
    const int bn = blockIdx.x * 128;

    __shared__ float S[4 * MSL];
    float* AHI = S;
    float* ALO = S + MSL;
    float* BHI = S + 2 * MSL;
    float* BLO = S + 3 * MSL;

    const int tid = threadIdx.x;
    const int wid = tid >> 5;
    const int wm  = wid >> 2, wn = wid & 3;
    const int g   = (tid & 31) >> 2, tig = tid & 3;

    float acc[4][4][4];
#pragma unroll
    for (int a = 0; a < 4; a++)
#pragma unroll
        for (int b = 0; b < 4; b++)
#pragma unroll
            for (int c = 0; c < 4; c++) acc[a][b][c] = 0.0f;

    float4 av[2], bv[2];
    auto load_g = [&](int ch) {
        int kkb = kbeg + ch * BK;
#pragma unroll
        for (int j = 0; j < 2; j++) {
            int idx = j * 256 + tid;
            int row = idx >> 2, kq = idx & 3;
            int kk = kkb + kq * 4;
            av[j] = *(const float4*)&g_h[(size_t)(bm + row) * HH + kk];
            bv[j] = *(const float4*)&lin_W[(size_t)(bn + row) * HH + kk];
        }
    };

    load_g(0);
    for (int i = 0; i < nch; i++) {
        __syncthreads();
#pragma unroll
        for (int j = 0; j < 2; j++) {
            int idx = j * 256 + tid;
            int row = idx >> 2, kq = idx & 3;
            int o = row * SR + kq * 4;
            float4 h, l;
            split4(av[j], h, l);
            *(float4*)&AHI[o] = h; *(float4*)&ALO[o] = l;
            split4(bv[j], h, l);
            *(float4*)&BHI[o] = h; *(float4*)&BLO[o] = l;
        }
        __syncthreads();
        if (i + 1 < nch) load_g(i + 1);
#pragma unroll
        for (int ks = 0; ks < 2; ks++) {
            int kb = ks * 8;
            uint32_t ah[4][4], al[4][4], bh[4][2], bl[4][2];
#pragma unroll
            for (int m = 0; m < 4; m++) {
                int r0 = (wm * 64 + m * 16 + g) * SR + kb + tig;
                int r1 = r0 + 8 * SR;
                ah[m][0] = __float_as_uint(AHI[r0]);
                ah[m][1] = __float_as_uint(AHI[r1]);
                ah[m][2] = __float_as_uint(AHI[r0 + 4]);
                ah[m][3] = __float_as_uint(AHI[r1 + 4]);
                al[m][0] = __float_as_uint(ALO[r0]);
                al[m][1] = __float_as_uint(ALO[r1]);
                al[m][2] = __float_as_uint(ALO[r0 + 4]);
                al[m][3] = __float_as_uint(ALO[r1 + 4]);
            }
#pragma unroll
            for (int n = 0; n < 4; n++) {
                int n0 = (wn * 32 + n * 8 + g) * SR + kb + tig;
                bh[n][0] = __float_as_uint(BHI[n0]);
                bh[n][1] = __float_as_uint(BHI[n0 + 4]);
                bl[n][0] = __float_as_uint(BLO[n0]);
                bl[n][1] = __float_as_uint(BLO[n0 + 4]);
            }
#pragma unroll
            for (int m = 0; m < 4; m++)
#pragma unroll
                for (int n = 0; n < 4; n++) mma8(acc[m][n], ah[m], bh[n]);
#pragma unroll
            for (int m = 0; m < 4; m++)
#pragma unroll
                for (int n = 0; n < 4; n++) mma8(acc[m][n], ah[m], bl[n]);
#pragma unroll
            for (int m = 0; m < 4; m++)
#pragma unroll
                for (int n = 0; n < 4; n++) mma8(acc[m][n], al[m], bh[n]);
        }
    }

    if (!split) {
        logits_out(acc, nullptr, lin_b, seq_lens, out, t,
                   bm, bn, wm, wn, g, tig, blockIdx.x);
        return;
    }

    // split path: store my partial, last arriver combines
    {
        float* MP = &g_logP[by][0][0];
#pragma unroll
        for (int half = 0; half < 2; half++)
#pragma unroll
            for (int mt = 0; mt < 4; mt++) {
                int lr = wm * 64 + mt * 16 + g + half * 8;
#pragma unroll
                for (int nt = 0; nt < 4; nt++) {
                    int col = bn + wn * 32 + nt * 8 + 2 * tig;
                    *(float2*)&MP[(size_t)lr * VV + col] =
                        make_float2(acc[mt][nt][half * 2], acc[mt][nt][half * 2 + 1]);
                }
            }
    }
    __syncthreads();
    __shared__ int swin;
    if (tid == 0) {
        __threadfence();
        int old = atomicAdd(&g_lcnt[blockIdx.x], 1);
        swin = (old == 1);
        if (old == 1) g_lcnt[blockIdx.x] = 0;   // reset for next split step
    }
    __syncthreads();
    if (!swin) return;
    __threadfence();
    const float* OP = &g_logP[1 - by][0][0];
    logits_out(acc, OP, lin_b, seq_lens, out, t,
               bm, bn, wm, wn, g, tig, blockIdx.x);
}

// ---------------- final argmax (256 partials/row) + embedding gather ----------
__global__ void k_final(const float* __restrict__ embedding) {
    int b    = blockIdx.x;
    int tid  = threadIdx.x;   // 256 threads
    int lane = tid & 31;
    int w    = tid >> 5;
    float v = g_pval[(size_t)b * 256 + tid];
    int   i = g_pidx[(size_t)b * 256 + tid];
#pragma unroll
    for (int off = 16; off; off >>= 1) {
        float ov = __shfl_xor_sync(0xffffffffu, v, off);
        int   oi = __shfl_xor_sync(0xffffffffu, i, off);
        if (ov > v || (ov == v && oi < i)) { v = ov; i = oi; }
    }
    __shared__ float sv[8];
    __shared__ int   si[8];
    __shared__ int   sbest;
    if (lane == 0) { sv[w] = v; si[w] = i; }
    __syncthreads();
    if (tid == 0) {
        float bvv = sv[0]; int bii = si[0];
#pragma unroll
        for (int q = 1; q < 8; q++)
            if (sv[q] > bvv || (sv[q] == bvv && si[q] < bii)) { bvv = sv[q]; bii = si[q]; }
        sbest = bii;
    }
    __syncthreads();
    g_prev[(size_t)b * EE + tid] = embedding[(size_t)sbest * EE + tid];
}

// ---------------- launch ------------------------------------------------------
extern "C" void kernel_launch(void* const* d_in, const int* in_sizes, int n_in,
                              void* d_out, int out_size) {
    const float* enc      = (const float*)d_in[0];
    const float* emb      = (const float*)d_in[1];
    const float* init_t   = (const float*)d_in[2];
    const float* W_ih     = (const float*)d_in[3];
    const float* W_hh     = (const float*)d_in[4];
    const float* b_ih     = (const float*)d_in[5];
    const float* b_hh     = (const float*)d_in[6];
    const float* lin_W    = (const float*)d_in[7];
    const float* lin_b    = (const float*)d_in[8];
    const int*   seq_lens = (const int*)d_in[9];
    float*       out      = (float*)d_out;

    k_init<<<(BB * HH + 255) / 256, 256>>>(init_t);
    k_scan<<<1, 64>>>(seq_lens);

    for (int t = 0; t < TT; t++) {
        k_gates<<<dim3(32, 4), 256>>>(enc, W_ih, W_hh, t);
        k_cell<<<(BB * HH + 255) / 256, 256>>>(b_ih, b_hh, t);
        k_logits<<<dim3(64, 2), 256>>>(lin_W, lin_b, seq_lens, out, t);
        k_final<<<BB, 256>>>(emb);
    }
}

// round 7
// speedup vs baseline: 1.3891x; 1.0411x over previous
#include <cuda_runtime.h>
#include <cstdint>
#include <cstddef>

// Problem dims (fixed)
#define BB    256
#define TT    64
#define DIN   1024
#define HH    1024
#define EE    256
#define VV    8192
#define FOURH 4096
#define KCAT  2304            // DIN + EE + HH
#define BK    16
#define SR    20              // smem row stride (floats), bank-perfect
#define MSL   (128 * SR)      // 128-row tile floats per matrix

// ---------------- scratch ----------------------------------------------------
__device__ float g_h[BB * HH];
__device__ float g_c[BB * HH];
__device__ float g_prev[BB * EE];
__device__ float g_P[4][128][FOURH];     // gates partials [q][local row][4H]
__device__ float g_logP[2][128][VV];     // logits split-K partials
__device__ int   g_lcnt[64];             // logits combine counters (zero-init)
__device__ int   g_fcnt[2];              // final-argmax counters (zero-init)
__device__ float g_pval[BB * 256];
__device__ int   g_pidx[BB * 256];
__device__ int   g_off[BB];
__device__ int   g_nb[TT];               // active rows per step

// ---------------- helpers -----------------------------------------------------
__device__ __forceinline__ float tf32r(float x) {
    uint32_t u;
    asm("cvt.rna.tf32.f32 %0, %1;" : "=r"(u) : "f"(x));
    return __uint_as_float(u);
}
__device__ __forceinline__ void split4(float4 v, float4& h, float4& l) {
    h.x = tf32r(v.x); h.y = tf32r(v.y); h.z = tf32r(v.z); h.w = tf32r(v.w);
    l.x = tf32r(v.x - h.x); l.y = tf32r(v.y - h.y);
    l.z = tf32r(v.z - h.z); l.w = tf32r(v.w - h.w);
}
__device__ __forceinline__ void mma8(float* c, const uint32_t* a, const uint32_t* b) {
    asm volatile(
        "mma.sync.aligned.m16n8k8.row.col.f32.tf32.tf32.f32 "
        "{%0,%1,%2,%3}, {%4,%5,%6,%7}, {%8,%9}, {%0,%1,%2,%3};"
        : "+f"(c[0]), "+f"(c[1]), "+f"(c[2]), "+f"(c[3])
        : "r"(a[0]), "r"(a[1]), "r"(a[2]), "r"(a[3]), "r"(b[0]), "r"(b[1]));
}
__device__ __forceinline__ float sigm(float x) { return 1.0f / (1.0f + expf(-x)); }

// ---------------- init / scan -------------------------------------------------
__global__ void k_init(const float* __restrict__ init_tensor) {
    int idx = blockIdx.x * 256 + threadIdx.x;
    if (idx < BB * HH) { g_h[idx] = 0.0f; g_c[idx] = 0.0f; }
    if (idx < BB * EE) { g_prev[idx] = init_tensor[idx & (EE - 1)]; }
}
__global__ void k_scan(const int* __restrict__ seq_lens) {
    int t = threadIdx.x;  // 64 threads
    if (t == 0) {
        int acc = 0;
        for (int b = 0; b < BB; b++) { g_off[b] = acc; acc += seq_lens[b]; }
    }
    if (t < TT) {
        int c = 0;
        for (int b = 0; b < BB; b++) c += (seq_lens[b] > t) ? 1 : 0;
        g_nb[t] = c;
    }
}

// ================= GEMM 1: gates (BM=128, mode-adaptive split-K) ==============
// grid (32 n-tiles, 2, 2) = 128 CTAs.
// nbt>128: m-tile = by, split-K half = kz (R5 layout).
// nbt<=128: all CTAs on m-tile 0, split-K quarter q = by*2+kz.
__global__ __launch_bounds__(256, 1)
void k_gates(const float* __restrict__ enc,
             const float* __restrict__ W_ih,
             const float* __restrict__ W_hh,
             int t) {
    const int nbt = g_nb[t];
    const int q   = blockIdx.y * 2 + blockIdx.z;
    int bm, kbeg, nch;
    if (nbt > 128) {
        bm = blockIdx.y * 128;
        kbeg = blockIdx.z * (KCAT / 2);
        nch = (KCAT / 2) / BK;    // 72
    } else {
        bm = 0;
        kbeg = q * (KCAT / 4);
        nch = (KCAT / 4) / BK;    // 36
    }
    const int bn = blockIdx.x * 128;

    __shared__ float S[4 * MSL];
    float* AHI = S;
    float* ALO = S + MSL;
    float* BHI = S + 2 * MSL;
    float* BLO = S + 3 * MSL;

    const int tid = threadIdx.x;
    const int wid = tid >> 5;
    const int wm  = wid >> 2, wn = wid & 3;
    const int g   = (tid & 31) >> 2, tig = tid & 3;

    float acc[4][4][4];
#pragma unroll
    for (int a = 0; a < 4; a++)
#pragma unroll
        for (int b = 0; b < 4; b++)
#pragma unroll
            for (int c = 0; c < 4; c++) acc[a][b][c] = 0.0f;

    float4 av[2], bv[2];
    auto load_g = [&](int ch) {
        int kkb = kbeg + ch * BK;
#pragma unroll
        for (int j = 0; j < 2; j++) {
            int idx = j * 256 + tid;
            int row = idx >> 2, kq = idx & 3;
            int kk = kkb + kq * 4;
            int gm = bm + row;
            const float* pa;
            if (kk < DIN)            pa = enc    + ((size_t)gm * TT + t) * DIN + kk;
            else if (kk < DIN + EE)  pa = g_prev + (size_t)gm * EE + (kk - DIN);
            else                     pa = g_h    + (size_t)gm * HH + (kk - DIN - EE);
            av[j] = *(const float4*)pa;
            int gn = bn + row;
            const float* pb = (kk < DIN + EE)
                ? (W_ih + (size_t)gn * (DIN + EE) + kk)
                : (W_hh + (size_t)gn * HH + (kk - DIN - EE));
            bv[j] = *(const float4*)pb;
        }
    };

    load_g(0);
    for (int i = 0; i < nch; i++) {
        __syncthreads();
#pragma unroll
        for (int j = 0; j < 2; j++) {
            int idx = j * 256 + tid;
            int row = idx >> 2, kq = idx & 3;
            int o = row * SR + kq * 4;
            float4 h, l;
            split4(av[j], h, l);
            *(float4*)&AHI[o] = h; *(float4*)&ALO[o] = l;
            split4(bv[j], h, l);
            *(float4*)&BHI[o] = h; *(float4*)&BLO[o] = l;
        }
        __syncthreads();
        if (i + 1 < nch) load_g(i + 1);
#pragma unroll
        for (int ks = 0; ks < 2; ks++) {
            int kb = ks * 8;
            uint32_t ah[4][4], al[4][4], bh[4][2], bl[4][2];
#pragma unroll
            for (int m = 0; m < 4; m++) {
                int r0 = (wm * 64 + m * 16 + g) * SR + kb + tig;
                int r1 = r0 + 8 * SR;
                ah[m][0] = __float_as_uint(AHI[r0]);
                ah[m][1] = __float_as_uint(AHI[r1]);
                ah[m][2] = __float_as_uint(AHI[r0 + 4]);
                ah[m][3] = __float_as_uint(AHI[r1 + 4]);
                al[m][0] = __float_as_uint(ALO[r0]);
                al[m][1] = __float_as_uint(ALO[r1]);
                al[m][2] = __float_as_uint(ALO[r0 + 4]);
                al[m][3] = __float_as_uint(ALO[r1 + 4]);
            }
#pragma unroll
            for (int n = 0; n < 4; n++) {
                int n0 = (wn * 32 + n * 8 + g) * SR + kb + tig;
                bh[n][0] = __float_as_uint(BHI[n0]);
                bh[n][1] = __float_as_uint(BHI[n0 + 4]);
                bl[n][0] = __float_as_uint(BLO[n0]);
                bl[n][1] = __float_as_uint(BLO[n0 + 4]);
            }
#pragma unroll
            for (int m = 0; m < 4; m++)
#pragma unroll
                for (int n = 0; n < 4; n++) mma8(acc[m][n], ah[m], bh[n]);
#pragma unroll
            for (int m = 0; m < 4; m++)
#pragma unroll
                for (int n = 0; n < 4; n++) mma8(acc[m][n], ah[m], bl[n]);
#pragma unroll
            for (int m = 0; m < 4; m++)
#pragma unroll
                for (int n = 0; n < 4; n++) mma8(acc[m][n], al[m], bh[n]);
        }
    }

    // epilogue: partial to g_P[q][local row][col]
#pragma unroll
    for (int m = 0; m < 4; m++) {
        int lr0 = wm * 64 + m * 16 + g;
        int lr1 = lr0 + 8;
#pragma unroll
        for (int n = 0; n < 4; n++) {
            int col = bn + wn * 32 + n * 8 + 2 * tig;
            *(float2*)&g_P[q][lr0][col] = make_float2(acc[m][n][0], acc[m][n][1]);
            *(float2*)&g_P[q][lr1][col] = make_float2(acc[m][n][2], acc[m][n][3]);
        }
    }
}

// ---------------- LSTM cell (mode-aware) --------------------------------------
__global__ void k_cell(const float* __restrict__ b_ih,
                       const float* __restrict__ b_hh,
                       int t) {
    int idx = blockIdx.x * 256 + threadIdx.x;
    int b = idx >> 10, j = idx & 1023;
    int nbt = g_nb[t];

    float i_, f_, gg, o_;
    if (nbt > 128) {
        int q0 = (b >> 7) * 2, lr = b & 127;
        const float* P0 = g_P[q0][lr];
        const float* P1 = g_P[q0 + 1][lr];
        i_ = P0[j] + P1[j];
        f_ = P0[1024 + j] + P1[1024 + j];
        gg = P0[2048 + j] + P1[2048 + j];
        o_ = P0[3072 + j] + P1[3072 + j];
    } else {
        if (b >= 128) return;
        const float* P0 = g_P[0][b];
        const float* P1 = g_P[1][b];
        const float* P2 = g_P[2][b];
        const float* P3 = g_P[3][b];
        i_ = (P0[j] + P1[j]) + (P2[j] + P3[j]);
        f_ = (P0[1024 + j] + P1[1024 + j]) + (P2[1024 + j] + P3[1024 + j]);
        gg = (P0[2048 + j] + P1[2048 + j]) + (P2[2048 + j] + P3[2048 + j]);
        o_ = (P0[3072 + j] + P1[3072 + j]) + (P2[3072 + j] + P3[3072 + j]);
    }
    i_ += b_ih[j] + b_hh[j];
    f_ += b_ih[1024 + j] + b_hh[1024 + j];
    gg += b_ih[2048 + j] + b_hh[2048 + j];
    o_ += b_ih[3072 + j] + b_hh[3072 + j];
    float c = sigm(f_) * g_c[idx] + sigm(i_) * tanhf(gg);
    float h = sigm(o_) * tanhf(c);
    g_c[idx] = c;
    g_h[idx] = h;
}

// ================= GEMM 2: logits (adaptive split-K) + fused final ============
__device__ __forceinline__ void logits_out(
    float acc[4][4][4], const float* OP,
    const float* __restrict__ lin_b, const int* __restrict__ seq_lens,
    float* __restrict__ out, int t,
    int bm, int bn, int wm, int wn, int g, int tig, int bx) {
#pragma unroll
    for (int half = 0; half < 2; half++) {
#pragma unroll
        for (int mt = 0; mt < 4; mt++) {
            int lr = wm * 64 + mt * 16 + g + half * 8;
            int gm = bm + lr;
            int len = seq_lens[gm];
            bool wr = (t < len);
            float* orow = out + (size_t)(g_off[gm] + t) * VV;

            float bvv = -3.4e38f;
            int   bii = 0;
#pragma unroll
            for (int nt = 0; nt < 4; nt++) {
                int col = bn + wn * 32 + nt * 8 + 2 * tig;
                float v0 = acc[mt][nt][half * 2 + 0];
                float v1 = acc[mt][nt][half * 2 + 1];
                if (OP) {
                    v0 += __ldcg(&OP[(size_t)lr * VV + col]);
                    v1 += __ldcg(&OP[(size_t)lr * VV + col + 1]);
                }
                v0 += lin_b[col];
                v1 += lin_b[col + 1];
                if (wr) *(float2*)&orow[col] = make_float2(v0, v1);
                if (v0 > bvv) { bvv = v0; bii = col; }
                if (v1 > bvv) { bvv = v1; bii = col + 1; }
            }
#pragma unroll
            for (int off = 1; off < 4; off <<= 1) {
                float ov = __shfl_xor_sync(0xffffffffu, bvv, off, 4);
                int   oi = __shfl_xor_sync(0xffffffffu, bii, off, 4);
                if (ov > bvv || (ov == bvv && oi < bii)) { bvv = ov; bii = oi; }
            }
            if (tig == 0) {
                int slot = bx * 4 + wn;
                g_pval[(size_t)gm * 256 + slot] = bvv;
                g_pidx[(size_t)gm * 256 + slot] = bii;
            }
        }
    }
}

__global__ __launch_bounds__(256, 1)
void k_logits(const float* __restrict__ lin_W,
              const float* __restrict__ lin_b,
              const int*   __restrict__ seq_lens,
              const float* __restrict__ emb,
              float* __restrict__ out,
              int t) {
    const int nbt = g_nb[t];
    const bool split = (nbt <= 128);
    const int by = blockIdx.y;
    const int bm = split ? 0 : by * 128;
    const int kbeg = split ? by * (HH / 2) : 0;
    const int nch = (split ? (HH / 2) : HH) >> 4;
    const int bn = blockIdx.x * 128;

    __shared__ float S[4 * MSL];
    float* AHI = S;
    float* ALO = S + MSL;
    float* BHI = S + 2 * MSL;
    float* BLO = S + 3 * MSL;

    const int tid = threadIdx.x;
    const int wid = tid >> 5;
    const int wm  = wid >> 2, wn = wid & 3;
    const int g   = (tid & 31) >> 2, tig = tid & 3;

    float acc[4][4][4];
#pragma unroll
    for (int a = 0; a < 4; a++)
#pragma unroll
        for (int b = 0; b < 4; b++)
#pragma unroll
            for (int c = 0; c < 4; c++) acc[a][b][c] = 0.0f;

    float4 av[2], bv[2];
    auto load_g = [&](int ch) {
        int kkb = kbeg + ch * BK;
#pragma unroll
        for (int j = 0; j < 2; j++) {
            int idx = j * 256 + tid;
            int row = idx >> 2, kq = idx & 3;
            int kk = kkb + kq * 4;
            av[j] = *(const float4*)&g_h[(size_t)(bm + row) * HH + kk];
            bv[j] = *(const float4*)&lin_W[(size_t)(bn + row) * HH + kk];
        }
    };

    load_g(0);
    for (int i = 0; i < nch; i++) {
        __syncthreads();
#pragma unroll
        for (int j = 0; j < 2; j++) {
            int idx = j * 256 + tid;
            int row = idx >> 2, kq = idx & 3;
            int o = row * SR + kq * 4;
            float4 h, l;
            split4(av[j], h, l);
            *(float4*)&AHI[o] = h; *(float4*)&ALO[o] = l;
            split4(bv[j], h, l);
            *(float4*)&BHI[o] = h; *(float4*)&BLO[o] = l;
        }
        __syncthreads();
        if (i + 1 < nch) load_g(i + 1);
#pragma unroll
        for (int ks = 0; ks < 2; ks++) {
            int kb = ks * 8;
            uint32_t ah[4][4], al[4][4], bh[4][2], bl[4][2];
#pragma unroll
            for (int m = 0; m < 4; m++) {
                int r0 = (wm * 64 + m * 16 + g) * SR + kb + tig;
                int r1 = r0 + 8 * SR;
                ah[m][0] = __float_as_uint(AHI[r0]);
                ah[m][1] = __float_as_uint(AHI[r1]);
                ah[m][2] = __float_as_uint(AHI[r0 + 4]);
                ah[m][3] = __float_as_uint(AHI[r1 + 4]);
                al[m][0] = __float_as_uint(ALO[r0]);
                al[m][1] = __float_as_uint(ALO[r1]);
                al[m][2] = __float_as_uint(ALO[r0 + 4]);
                al[m][3] = __float_as_uint(ALO[r1 + 4]);
            }
#pragma unroll
            for (int n = 0; n < 4; n++) {
                int n0 = (wn * 32 + n * 8 + g) * SR + kb + tig;
                bh[n][0] = __float_as_uint(BHI[n0]);
                bh[n][1] = __float_as_uint(BHI[n0 + 4]);
                bl[n][0] = __float_as_uint(BLO[n0]);
                bl[n][1] = __float_as_uint(BLO[n0 + 4]);
            }
#pragma unroll
            for (int m = 0; m < 4; m++)
#pragma unroll
                for (int n = 0; n < 4; n++) mma8(acc[m][n], ah[m], bh[n]);
#pragma unroll
            for (int m = 0; m < 4; m++)
#pragma unroll
                for (int n = 0; n < 4; n++) mma8(acc[m][n], ah[m], bl[n]);
#pragma unroll
            for (int m = 0; m < 4; m++)
#pragma unroll
                for (int n = 0; n < 4; n++) mma8(acc[m][n], al[m], bh[n]);
        }
    }

    if (!split) {
        logits_out(acc, nullptr, lin_b, seq_lens, out, t,
                   bm, bn, wm, wn, g, tig, blockIdx.x);
    } else {
        // store my partial; last arriver per n-tile combines
        float* MP = &g_logP[by][0][0];
#pragma unroll
        for (int half = 0; half < 2; half++)
#pragma unroll
            for (int mt = 0; mt < 4; mt++) {
                int lr = wm * 64 + mt * 16 + g + half * 8;
#pragma unroll
                for (int nt = 0; nt < 4; nt++) {
                    int col = bn + wn * 32 + nt * 8 + 2 * tig;
                    *(float2*)&MP[(size_t)lr * VV + col] =
                        make_float2(acc[mt][nt][half * 2], acc[mt][nt][half * 2 + 1]);
                }
            }
        __syncthreads();
        __shared__ int swin;
        if (tid == 0) {
            __threadfence();
            int old = atomicAdd(&g_lcnt[blockIdx.x], 1);
            swin = (old == 1);
            if (old == 1) g_lcnt[blockIdx.x] = 0;
        }
        __syncthreads();
        if (!swin) return;
        __threadfence();
        const float* OP = &g_logP[1 - by][0][0];
        logits_out(acc, OP, lin_b, seq_lens, out, t,
                   bm, bn, wm, wn, g, tig, blockIdx.x);
    }

    // ---- fused final argmax + embedding gather ----
    // Executors per m-tile: full mode = its 64 n-CTAs; split mode = 64 winners.
    __syncthreads();
    __shared__ int lastf;
    if (tid == 0) {
        __threadfence();
        int fi = split ? 0 : by;
        int old = atomicAdd(&g_fcnt[fi], 1);
        lastf = (old == 63);
        if (old == 63) g_fcnt[fi] = 0;
    }
    __syncthreads();
    if (!lastf) return;
    __threadfence();

    {
        int wv = tid >> 5, lane = tid & 31;
#pragma unroll 1
        for (int i = 0; i < 16; i++) {
            int b = bm + wv * 16 + i;
            float v = -3.4e38f;
            int   bi = 0x7fffffff;
            for (int s = lane; s < 256; s += 32) {
                float pv = __ldcg(&g_pval[(size_t)b * 256 + s]);
                int   pi = __ldcg(&g_pidx[(size_t)b * 256 + s]);
                if (pv > v || (pv == v && pi < bi)) { v = pv; bi = pi; }
            }
#pragma unroll
            for (int off = 16; off; off >>= 1) {
                float ov = __shfl_xor_sync(0xffffffffu, v, off);
                int   oi = __shfl_xor_sync(0xffffffffu, bi, off);
                if (ov > v || (ov == v && oi < bi)) { v = ov; bi = oi; }
            }
            int best = __shfl_sync(0xffffffffu, bi, 0);
            const float4* es = (const float4*)(emb + (size_t)best * EE);
            float4* ed = (float4*)(g_prev + (size_t)b * EE);
            ed[lane]      = es[lane];
            ed[lane + 32] = es[lane + 32];
        }
    }
}

// ---------------- launch ------------------------------------------------------
extern "C" void kernel_launch(void* const* d_in, const int* in_sizes, int n_in,
                              void* d_out, int out_size) {
    const float* enc      = (const float*)d_in[0];
    const float* emb      = (const float*)d_in[1];
    const float* init_t   = (const float*)d_in[2];
    const float* W_ih     = (const float*)d_in[3];
    const float* W_hh     = (const float*)d_in[4];
    const float* b_ih     = (const float*)d_in[5];
    const float* b_hh     = (const float*)d_in[6];
    const float* lin_W    = (const float*)d_in[7];
    const float* lin_b    = (const float*)d_in[8];
    const int*   seq_lens = (const int*)d_in[9];
    float*       out      = (float*)d_out;

    k_init<<<(BB * HH + 255) / 256, 256>>>(init_t);
    k_scan<<<1, 64>>>(seq_lens);

    for (int t = 0; t < TT; t++) {
        k_gates<<<dim3(32, 2, 2), 256>>>(enc, W_ih, W_hh, t);
        k_cell<<<(BB * HH + 255) / 256, 256>>>(b_ih, b_hh, t);
        k_logits<<<dim3(64, 2), 256>>>(lin_W, lin_b, seq_lens, emb, out, t);
    }
}

// round 8
// speedup vs baseline: 1.4762x; 1.0627x over previous
#include <cuda_runtime.h>
#include <cstdint>
#include <cstddef>

// Problem dims (fixed)
#define BB    256
#define TT    64
#define DIN   1024
#define HH    1024
#define EE    256
#define VV    8192
#define FOURH 4096
#define BK    16
#define SR    20              // smem row stride (floats), bank-perfect
#define MSL   (128 * SR)

// ---------------- scratch ----------------------------------------------------
__device__ float g_h[BB * HH];
__device__ float g_c[BB * HH];
__device__ float g_XW[BB * TT * FOURH];   // packed x_t @ W_ih_x^T  (268 MB)
__device__ float g_EW[VV * FOURH];        // emb @ W_ih_e^T         (134 MB)
__device__ float g_I0[FOURH];             // init_tensor @ W_ih_e^T
__device__ int   g_amax[BB];              // greedy index from previous step
__device__ float g_P[4][128][FOURH];      // gates partials
__device__ float g_logP[2][128][VV];      // logits split-K partials
__device__ int   g_lcnt[64];
__device__ int   g_fcnt[2];
__device__ float g_pval[BB * 256];
__device__ int   g_pidx[BB * 256];
__device__ int   g_off[BB];
__device__ int   g_nb[TT];
__device__ int   g_nrows;                 // total packed rows
__device__ int   g_rbt[BB * TT];          // packed row -> (b<<6)|t

// ---------------- helpers -----------------------------------------------------
__device__ __forceinline__ float tf32r(float x) {
    uint32_t u;
    asm("cvt.rna.tf32.f32 %0, %1;" : "=r"(u) : "f"(x));
    return __uint_as_float(u);
}
__device__ __forceinline__ void split4(float4 v, float4& h, float4& l) {
    h.x = tf32r(v.x); h.y = tf32r(v.y); h.z = tf32r(v.z); h.w = tf32r(v.w);
    l.x = tf32r(v.x - h.x); l.y = tf32r(v.y - h.y);
    l.z = tf32r(v.z - h.z); l.w = tf32r(v.w - h.w);
}
__device__ __forceinline__ void mma8(float* c, const uint32_t* a, const uint32_t* b) {
    asm volatile(
        "mma.sync.aligned.m16n8k8.row.col.f32.tf32.tf32.f32 "
        "{%0,%1,%2,%3}, {%4,%5,%6,%7}, {%8,%9}, {%0,%1,%2,%3};"
        : "+f"(c[0]), "+f"(c[1]), "+f"(c[2]), "+f"(c[3])
        : "r"(a[0]), "r"(a[1]), "r"(a[2]), "r"(a[3]), "r"(b[0]), "r"(b[1]));
}
__device__ __forceinline__ float sigm(float x) { return 1.0f / (1.0f + expf(-x)); }

// STS with tf32 hi/lo split (both operands), standard 128x16 tile layout
__device__ __forceinline__ void sts_split(float* S, int tid,
                                          const float4* av, const float4* bv) {
    float* AHI = S;
    float* ALO = S + MSL;
    float* BHI = S + 2 * MSL;
    float* BLO = S + 3 * MSL;
#pragma unroll
    for (int j = 0; j < 2; j++) {
        int idx = j * 256 + tid;
        int row = idx >> 2, kq = idx & 3;
        int o = row * SR + kq * 4;
        float4 h, l;
        split4(av[j], h, l);
        *(float4*)&AHI[o] = h; *(float4*)&ALO[o] = l;
        split4(bv[j], h, l);
        *(float4*)&BHI[o] = h; *(float4*)&BLO[o] = l;
    }
}

// 3-pass fragment compute for one K=16 chunk (BM=128, BN=128, 8 warps 2x4)
__device__ __forceinline__ void mma_block(const float* S, int wm, int wn,
                                          int g, int tig, float acc[4][4][4]) {
    const float* AHI = S;
    const float* ALO = S + MSL;
    const float* BHI = S + 2 * MSL;
    const float* BLO = S + 3 * MSL;
#pragma unroll
    for (int ks = 0; ks < 2; ks++) {
        int kb = ks * 8;
        uint32_t ah[4][4], al[4][4], bh[4][2], bl[4][2];
#pragma unroll
        for (int m = 0; m < 4; m++) {
            int r0 = (wm * 64 + m * 16 + g) * SR + kb + tig;
            int r1 = r0 + 8 * SR;
            ah[m][0] = __float_as_uint(AHI[r0]);
            ah[m][1] = __float_as_uint(AHI[r1]);
            ah[m][2] = __float_as_uint(AHI[r0 + 4]);
            ah[m][3] = __float_as_uint(AHI[r1 + 4]);
            al[m][0] = __float_as_uint(ALO[r0]);
            al[m][1] = __float_as_uint(ALO[r1]);
            al[m][2] = __float_as_uint(ALO[r0 + 4]);
            al[m][3] = __float_as_uint(ALO[r1 + 4]);
        }
#pragma unroll
        for (int n = 0; n < 4; n++) {
            int n0 = (wn * 32 + n * 8 + g) * SR + kb + tig;
            bh[n][0] = __float_as_uint(BHI[n0]);
            bh[n][1] = __float_as_uint(BHI[n0 + 4]);
            bl[n][0] = __float_as_uint(BLO[n0]);
            bl[n][1] = __float_as_uint(BLO[n0 + 4]);
        }
#pragma unroll
        for (int m = 0; m < 4; m++)
#pragma unroll
            for (int n = 0; n < 4; n++) mma8(acc[m][n], ah[m], bh[n]);
#pragma unroll
        for (int m = 0; m < 4; m++)
#pragma unroll
            for (int n = 0; n < 4; n++) mma8(acc[m][n], ah[m], bl[n]);
#pragma unroll
        for (int m = 0; m < 4; m++)
#pragma unroll
            for (int n = 0; n < 4; n++) mma8(acc[m][n], al[m], bh[n]);
    }
}

#define ACC_ZERO(acc)                                   \
    _Pragma("unroll")                                   \
    for (int a_ = 0; a_ < 4; a_++)                      \
        _Pragma("unroll")                               \
        for (int b_ = 0; b_ < 4; b_++)                  \
            _Pragma("unroll")                           \
            for (int c_ = 0; c_ < 4; c_++) acc[a_][b_][c_] = 0.0f;

// ---------------- init / scan -------------------------------------------------
__global__ void k_init() {
    int idx = blockIdx.x * 256 + threadIdx.x;
    if (idx < BB * HH) { g_h[idx] = 0.0f; g_c[idx] = 0.0f; }
}
__global__ void k_scan(const int* __restrict__ seq_lens) {
    int tid = threadIdx.x;   // 256
    if (tid == 0) {
        int acc = 0;
        for (int b = 0; b < BB; b++) { g_off[b] = acc; acc += seq_lens[b]; }
        g_nrows = acc;
    }
    if (tid < TT) {
        int c = 0;
        for (int b = 0; b < BB; b++) c += (seq_lens[b] > tid) ? 1 : 0;
        g_nb[tid] = c;
    }
    __syncthreads();
    {   // row LUT: thread b fills its packed range
        int b = tid;
        int o = g_off[b], len = seq_lens[b];
        for (int t = 0; t < len; t++) g_rbt[o + t] = (b << 6) | t;
    }
}
__global__ void k_I0(const float* __restrict__ init_t,
                     const float* __restrict__ W_ih) {
    int j = blockIdx.x * 256 + threadIdx.x;   // 4096
    const float* w = W_ih + (size_t)j * (DIN + EE) + DIN;
    float s = 0.0f;
    for (int e = 0; e < EE; e++) s += init_t[e] * w[e];
    g_I0[j] = s;
}

// ================= Phase A1: XW = x_t @ W_ih_x^T (packed rows) ================
__global__ __launch_bounds__(256, 1)
void kA_x(const float* __restrict__ enc, const float* __restrict__ W_ih) {
    const int bm = blockIdx.y * 128;
    if (bm >= g_nrows) return;
    const int bn = blockIdx.x * 128;

    __shared__ float S[4 * MSL];
    const int tid = threadIdx.x;
    const int wid = tid >> 5;
    const int wm  = wid >> 2, wn = wid & 3;
    const int g   = (tid & 31) >> 2, tig = tid & 3;
    const int kq  = tid & 3;

    const float* pa[2];
    const float* pb[2];
#pragma unroll
    for (int j = 0; j < 2; j++) {
        int row = ((j * 256 + tid) >> 2);
        int bt = g_rbt[bm + row];          // rows >= nrows read LUT 0 -> (0,0)
        int b = bt >> 6, t = bt & 63;
        pa[j] = enc + ((size_t)b * TT + t) * DIN;
        pb[j] = W_ih + (size_t)(bn + row) * (DIN + EE);
    }

    float acc[4][4][4];
    ACC_ZERO(acc)
    float4 av[2], bv[2];
#pragma unroll
    for (int j = 0; j < 2; j++) {
        av[j] = *(const float4*)(pa[j] + kq * 4);
        bv[j] = *(const float4*)(pb[j] + kq * 4);
    }
    for (int i = 0; i < DIN / BK; i++) {
        __syncthreads();
        sts_split(S, tid, av, bv);
        __syncthreads();
        if (i + 1 < DIN / BK) {
            int kkb = (i + 1) * BK + kq * 4;
#pragma unroll
            for (int j = 0; j < 2; j++) {
                av[j] = *(const float4*)(pa[j] + kkb);
                bv[j] = *(const float4*)(pb[j] + kkb);
            }
        }
        mma_block(S, wm, wn, g, tig, acc);
    }
#pragma unroll
    for (int m = 0; m < 4; m++) {
        int lr0 = wm * 64 + m * 16 + g, lr1 = lr0 + 8;
#pragma unroll
        for (int n = 0; n < 4; n++) {
            int col = bn + wn * 32 + n * 8 + 2 * tig;
            *(float2*)&g_XW[(size_t)(bm + lr0) * FOURH + col] =
                make_float2(acc[m][n][0], acc[m][n][1]);
            *(float2*)&g_XW[(size_t)(bm + lr1) * FOURH + col] =
                make_float2(acc[m][n][2], acc[m][n][3]);
        }
    }
}

// ================= Phase A2: EW = emb @ W_ih_e^T ==============================
__global__ __launch_bounds__(256, 1)
void kA_e(const float* __restrict__ emb, const float* __restrict__ W_ih) {
    const int bm = blockIdx.y * 128;   // vocab tile
    const int bn = blockIdx.x * 128;

    __shared__ float S[4 * MSL];
    const int tid = threadIdx.x;
    const int wid = tid >> 5;
    const int wm  = wid >> 2, wn = wid & 3;
    const int g   = (tid & 31) >> 2, tig = tid & 3;
    const int kq  = tid & 3;

    const float* pa[2];
    const float* pb[2];
#pragma unroll
    for (int j = 0; j < 2; j++) {
        int row = ((j * 256 + tid) >> 2);
        pa[j] = emb + (size_t)(bm + row) * EE;
        pb[j] = W_ih + (size_t)(bn + row) * (DIN + EE) + DIN;
    }

    float acc[4][4][4];
    ACC_ZERO(acc)
    float4 av[2], bv[2];
#pragma unroll
    for (int j = 0; j < 2; j++) {
        av[j] = *(const float4*)(pa[j] + kq * 4);
        bv[j] = *(const float4*)(pb[j] + kq * 4);
    }
    for (int i = 0; i < EE / BK; i++) {
        __syncthreads();
        sts_split(S, tid, av, bv);
        __syncthreads();
        if (i + 1 < EE / BK) {
            int kkb = (i + 1) * BK + kq * 4;
#pragma unroll
            for (int j = 0; j < 2; j++) {
                av[j] = *(const float4*)(pa[j] + kkb);
                bv[j] = *(const float4*)(pb[j] + kkb);
            }
        }
        mma_block(S, wm, wn, g, tig, acc);
    }
#pragma unroll
    for (int m = 0; m < 4; m++) {
        int lr0 = wm * 64 + m * 16 + g, lr1 = lr0 + 8;
#pragma unroll
        for (int n = 0; n < 4; n++) {
            int col = bn + wn * 32 + n * 8 + 2 * tig;
            *(float2*)&g_EW[(size_t)(bm + lr0) * FOURH + col] =
                make_float2(acc[m][n][0], acc[m][n][1]);
            *(float2*)&g_EW[(size_t)(bm + lr1) * FOURH + col] =
                make_float2(acc[m][n][2], acc[m][n][3]);
        }
    }
}

// ================= GEMM 1 (in-loop): h @ W_hh^T, mode-adaptive split-K ========
// grid (32, 2, 2). full: m-tile=by, K half=kz (32 chunks). split: m0, quarter q.
__global__ __launch_bounds__(256, 1)
void k_gates(int t) {
    const int nbt = g_nb[t];
    const int q   = blockIdx.y * 2 + blockIdx.z;
    int bm, kbeg, nch;
    if (nbt > 128) {
        bm = blockIdx.y * 128;
        kbeg = blockIdx.z * (HH / 2);
        nch = (HH / 2) / BK;     // 32
    } else {
        bm = 0;
        kbeg = q * (HH / 4);
        nch = (HH / 4) / BK;     // 16
    }
    const int bn = blockIdx.x * 128;

    __shared__ float S[4 * MSL];
    const int tid = threadIdx.x;
    const int wid = tid >> 5;
    const int wm  = wid >> 2, wn = wid & 3;
    const int g   = (tid & 31) >> 2, tig = tid & 3;
    const int kq  = tid & 3;

    extern __device__ float g_Whh_alias[];   // unused; keep simple
    const float* pa[2];
    const float* pb[2];
#pragma unroll
    for (int j = 0; j < 2; j++) {
        int row = ((j * 256 + tid) >> 2);
        pa[j] = g_h + (size_t)(bm + row) * HH + kbeg;
        pb[j] = nullptr;  // set below (needs W_hh parameter)
    }
    // W_hh passed via const pointer parameter trick: declared below
    (void)pb;

    // NOTE: W_hh pointer comes in through a __device__ variable set at launch? No —
    // keep it simple: this kernel takes W_hh as an argument.
    // (see actual signature below)
    // -- placeholder removed in real signature --
}

// real gates kernel (with W_hh argument)
__global__ __launch_bounds__(256, 1)
void k_gates2(const float* __restrict__ W_hh, int t) {
    const int nbt = g_nb[t];
    const int q   = blockIdx.y * 2 + blockIdx.z;
    int bm, kbeg, nch;
    if (nbt > 128) {
        bm = blockIdx.y * 128;
        kbeg = blockIdx.z * (HH / 2);
        nch = (HH / 2) / BK;
    } else {
        bm = 0;
        kbeg = q * (HH / 4);
        nch = (HH / 4) / BK;
    }
    const int bn = blockIdx.x * 128;

    __shared__ float S[4 * MSL];
    const int tid = threadIdx.x;
    const int wid = tid >> 5;
    const int wm  = wid >> 2, wn = wid & 3;
    const int g   = (tid & 31) >> 2, tig = tid & 3;
    const int kq  = tid & 3;

    const float* pa[2];
    const float* pb[2];
#pragma unroll
    for (int j = 0; j < 2; j++) {
        int row = ((j * 256 + tid) >> 2);
        pa[j] = g_h + (size_t)(bm + row) * HH + kbeg;
        pb[j] = W_hh + (size_t)(bn + row) * HH + kbeg;
    }

    float acc[4][4][4];
    ACC_ZERO(acc)
    float4 av[2], bv[2];
#pragma unroll
    for (int j = 0; j < 2; j++) {
        av[j] = *(const float4*)(pa[j] + kq * 4);
        bv[j] = *(const float4*)(pb[j] + kq * 4);
    }
    for (int i = 0; i < nch; i++) {
        __syncthreads();
        sts_split(S, tid, av, bv);
        __syncthreads();
        if (i + 1 < nch) {
            int kkb = (i + 1) * BK + kq * 4;
#pragma unroll
            for (int j = 0; j < 2; j++) {
                av[j] = *(const float4*)(pa[j] + kkb);
                bv[j] = *(const float4*)(pb[j] + kkb);
            }
        }
        mma_block(S, wm, wn, g, tig, acc);
    }
#pragma unroll
    for (int m = 0; m < 4; m++) {
        int lr0 = wm * 64 + m * 16 + g, lr1 = lr0 + 8;
#pragma unroll
        for (int n = 0; n < 4; n++) {
            int col = bn + wn * 32 + n * 8 + 2 * tig;
            *(float2*)&g_P[q][lr0][col] = make_float2(acc[m][n][0], acc[m][n][1]);
            *(float2*)&g_P[q][lr1][col] = make_float2(acc[m][n][2], acc[m][n][3]);
        }
    }
}

// ---------------- LSTM cell: partials + XW + EW lookup + biases ---------------
__global__ void k_cell(const float* __restrict__ b_ih,
                       const float* __restrict__ b_hh,
                       const int* __restrict__ seq_lens,
                       int t) {
    int idx = blockIdx.x * 256 + threadIdx.x;
    int b = idx >> 10, j = idx & 1023;
    int nbt = g_nb[t];
    if (nbt <= 128 && b >= 128) return;
    if (t >= seq_lens[b]) return;

    float i_, f_, gg, o_;
    if (nbt > 128) {
        int q0 = (b >> 7) * 2, lr = b & 127;
        const float* P0 = g_P[q0][lr];
        const float* P1 = g_P[q0 + 1][lr];
        i_ = P0[j] + P1[j];
        f_ = P0[1024 + j] + P1[1024 + j];
        gg = P0[2048 + j] + P1[2048 + j];
        o_ = P0[3072 + j] + P1[3072 + j];
    } else {
        const float* P0 = g_P[0][b];
        const float* P1 = g_P[1][b];
        const float* P2 = g_P[2][b];
        const float* P3 = g_P[3][b];
        i_ = (P0[j] + P1[j]) + (P2[j] + P3[j]);
        f_ = (P0[1024 + j] + P1[1024 + j]) + (P2[1024 + j] + P3[1024 + j]);
        gg = (P0[2048 + j] + P1[2048 + j]) + (P2[2048 + j] + P3[2048 + j]);
        o_ = (P0[3072 + j] + P1[3072 + j]) + (P2[3072 + j] + P3[3072 + j]);
    }
    const float* XW = g_XW + (size_t)(g_off[b] + t) * FOURH;
    const float* EW = (t == 0) ? g_I0 : g_EW + (size_t)g_amax[b] * FOURH;
    i_ += XW[j]        + EW[j]        + b_ih[j]        + b_hh[j];
    f_ += XW[1024 + j] + EW[1024 + j] + b_ih[1024 + j] + b_hh[1024 + j];
    gg += XW[2048 + j] + EW[2048 + j] + b_ih[2048 + j] + b_hh[2048 + j];
    o_ += XW[3072 + j] + EW[3072 + j] + b_ih[3072 + j] + b_hh[3072 + j];
    float c = sigm(f_) * g_c[idx] + sigm(i_) * tanhf(gg);
    float h = sigm(o_) * tanhf(c);
    g_c[idx] = c;
    g_h[idx] = h;
}

// ================= GEMM 2: logits + ragged out + fused argmax =================
__device__ __forceinline__ void logits_out(
    float acc[4][4][4], const float* OP,
    const float* __restrict__ lin_b, const int* __restrict__ seq_lens,
    float* __restrict__ out, int t,
    int bm, int bn, int wm, int wn, int g, int tig, int bx) {
#pragma unroll
    for (int half = 0; half < 2; half++) {
#pragma unroll
        for (int mt = 0; mt < 4; mt++) {
            int lr = wm * 64 + mt * 16 + g + half * 8;
            int gm = bm + lr;
            int len = seq_lens[gm];
            bool wr = (t < len);
            float* orow = out + (size_t)(g_off[gm] + t) * VV;

            float bvv = -3.4e38f;
            int   bii = 0;
#pragma unroll
            for (int nt = 0; nt < 4; nt++) {
                int col = bn + wn * 32 + nt * 8 + 2 * tig;
                float v0 = acc[mt][nt][half * 2 + 0];
                float v1 = acc[mt][nt][half * 2 + 1];
                if (OP) {
                    v0 += __ldcg(&OP[(size_t)lr * VV + col]);
                    v1 += __ldcg(&OP[(size_t)lr * VV + col + 1]);
                }
                v0 += lin_b[col];
                v1 += lin_b[col + 1];
                if (wr) *(float2*)&orow[col] = make_float2(v0, v1);
                if (v0 > bvv) { bvv = v0; bii = col; }
                if (v1 > bvv) { bvv = v1; bii = col + 1; }
            }
#pragma unroll
            for (int off = 1; off < 4; off <<= 1) {
                float ov = __shfl_xor_sync(0xffffffffu, bvv, off, 4);
                int   oi = __shfl_xor_sync(0xffffffffu, bii, off, 4);
                if (ov > bvv || (ov == bvv && oi < bii)) { bvv = ov; bii = oi; }
            }
            if (tig == 0) {
                int slot = bx * 4 + wn;
                g_pval[(size_t)gm * 256 + slot] = bvv;
                g_pidx[(size_t)gm * 256 + slot] = bii;
            }
        }
    }
}

__global__ __launch_bounds__(256, 1)
void k_logits(const float* __restrict__ lin_W,
              const float* __restrict__ lin_b,
              const int*   __restrict__ seq_lens,
              float* __restrict__ out,
              int t) {
    const int nbt = g_nb[t];
    const bool split = (nbt <= 128);
    const int by = blockIdx.y;
    const int bm = split ? 0 : by * 128;
    const int kbeg = split ? by * (HH / 2) : 0;
    const int nch = (split ? (HH / 2) : HH) / BK;
    const int bn = blockIdx.x * 128;

    __shared__ float S[4 * MSL];
    const int tid = threadIdx.x;
    const int wid = tid >> 5;
    const int wm  = wid >> 2, wn = wid & 3;
    const int g   = (tid & 31) >> 2, tig = tid & 3;
    const int kq  = tid & 3;

    const float* pa[2];
    const float* pb[2];
#pragma unroll
    for (int j = 0; j < 2; j++) {
        int row = ((j * 256 + tid) >> 2);
        pa[j] = g_h + (size_t)(bm + row) * HH + kbeg;
        pb[j] = lin_W + (size_t)(bn + row) * HH + kbeg;
    }

    float acc[4][4][4];
    ACC_ZERO(acc)
    float4 av[2], bv[2];
#pragma unroll
    for (int j = 0; j < 2; j++) {
        av[j] = *(const float4*)(pa[j] + kq * 4);
        bv[j] = *(const float4*)(pb[j] + kq * 4);
    }
    for (int i = 0; i < nch; i++) {
        __syncthreads();
        sts_split(S, tid, av, bv);
        __syncthreads();
        if (i + 1 < nch) {
            int kkb = (i + 1) * BK + kq * 4;
#pragma unroll
            for (int j = 0; j < 2; j++) {
                av[j] = *(const float4*)(pa[j] + kkb);
                bv[j] = *(const float4*)(pb[j] + kkb);
            }
        }
        mma_block(S, wm, wn, g, tig, acc);
    }

    if (!split) {
        logits_out(acc, nullptr, lin_b, seq_lens, out, t,
                   bm, bn, wm, wn, g, tig, blockIdx.x);
    } else {
        float* MP = &g_logP[by][0][0];
#pragma unroll
        for (int half = 0; half < 2; half++)
#pragma unroll
            for (int mt = 0; mt < 4; mt++) {
                int lr = wm * 64 + mt * 16 + g + half * 8;
#pragma unroll
                for (int nt = 0; nt < 4; nt++) {
                    int col = bn + wn * 32 + nt * 8 + 2 * tig;
                    *(float2*)&MP[(size_t)lr * VV + col] =
                        make_float2(acc[mt][nt][half * 2], acc[mt][nt][half * 2 + 1]);
                }
            }
        __syncthreads();
        __shared__ int swin;
        if (tid == 0) {
            __threadfence();
            int old = atomicAdd(&g_lcnt[blockIdx.x], 1);
            swin = (old == 1);
            if (old == 1) g_lcnt[blockIdx.x] = 0;
        }
        __syncthreads();
        if (!swin) return;
        __threadfence();
        const float* OP = &g_logP[1 - by][0][0];
        logits_out(acc, OP, lin_b, seq_lens, out, t,
                   bm, bn, wm, wn, g, tig, blockIdx.x);
    }

    // ---- fused final argmax: store greedy index for next step ----
    __syncthreads();
    __shared__ int lastf;
    if (tid == 0) {
        __threadfence();
        int fi = split ? 0 : by;
        int old = atomicAdd(&g_fcnt[fi], 1);
        lastf = (old == 63);
        if (old == 63) g_fcnt[fi] = 0;
    }
    __syncthreads();
    if (!lastf) return;
    __threadfence();

    {
        int wv = tid >> 5, lane = tid & 31;
#pragma unroll 1
        for (int i = 0; i < 16; i++) {
            int b = bm + wv * 16 + i;
            float v = -3.4e38f;
            int   bi = 0x7fffffff;
            for (int s = lane; s < 256; s += 32) {
                float pv = __ldcg(&g_pval[(size_t)b * 256 + s]);
                int   pi = __ldcg(&g_pidx[(size_t)b * 256 + s]);
                if (pv > v || (pv == v && pi < bi)) { v = pv; bi = pi; }
            }
#pragma unroll
            for (int off = 16; off; off >>= 1) {
                float ov = __shfl_xor_sync(0xffffffffu, v, off);
                int   oi = __shfl_xor_sync(0xffffffffu, bi, off);
                if (ov > v || (ov == v && oi < bi)) { v = ov; bi = oi; }
            }
            if (lane == 0) g_amax[b] = bi;
        }
    }
}

// ---------------- launch ------------------------------------------------------
extern "C" void kernel_launch(void* const* d_in, const int* in_sizes, int n_in,
                              void* d_out, int out_size) {
    const float* enc      = (const float*)d_in[0];
    const float* emb      = (const float*)d_in[1];
    const float* init_t   = (const float*)d_in[2];
    const float* W_ih     = (const float*)d_in[3];
    const float* W_hh     = (const float*)d_in[4];
    const float* b_ih     = (const float*)d_in[5];
    const float* b_hh     = (const float*)d_in[6];
    const float* lin_W    = (const float*)d_in[7];
    const float* lin_b    = (const float*)d_in[8];
    const int*   seq_lens = (const int*)d_in[9];
    float*       out      = (float*)d_out;

    k_init<<<(BB * HH + 255) / 256, 256>>>();
    k_scan<<<1, 256>>>(seq_lens);
    k_I0<<<FOURH / 256, 256>>>(init_t, W_ih);
    kA_e<<<dim3(32, VV / 128), 256>>>(emb, W_ih);
    kA_x<<<dim3(32, (BB * TT) / 128), 256>>>(enc, W_ih);

    for (int t = 0; t < TT; t++) {
        k_gates2<<<dim3(32, 2, 2), 256>>>(W_hh, t);
        k_cell<<<(BB * HH + 255) / 256, 256>>>(b_ih, b_hh, seq_lens, t);
        k_logits<<<dim3(64, 2), 256>>>(lin_W, lin_b, seq_lens, out, t);
    }
}

// round 9
// speedup vs baseline: 1.4897x; 1.0091x over previous
#include <cuda_runtime.h>
#include <cstdint>
#include <cstddef>

// Problem dims (fixed)
#define BB    256
#define TT    64
#define DIN   1024
#define HH    1024
#define EE    256
#define VV    8192
#define FOURH 4096
#define BK    16
#define SR    20              // smem row stride (floats), bank-perfect
#define MSL   (128 * SR)

// ---------------- scratch ----------------------------------------------------
__device__ float g_h[BB * HH];
__device__ float g_c[BB * HH];
__device__ float g_XW[BB * TT * FOURH];   // packed x_t @ W_ih_x^T
__device__ float g_EW[VV * FOURH];        // emb @ W_ih_e^T
__device__ float g_I0[FOURH];             // init_tensor @ W_ih_e^T
__device__ int   g_amax[BB];
__device__ float g_P[8][128][FOURH];      // gates partials (8-way max)
__device__ float g_logP[4][128][VV];      // logits split-K partials (4-way max)
__device__ int   g_lcnt[128];             // logits combine counters (zero-init)
__device__ int   g_fcnt[2];
__device__ float g_pval[BB * 256];
__device__ int   g_pidx[BB * 256];
__device__ int   g_off[BB];
__device__ int   g_nb[TT];
__device__ int   g_nrows;
__device__ int   g_rbt[BB * TT];          // packed row -> (b<<6)|t

// ---------------- helpers -----------------------------------------------------
__device__ __forceinline__ float tf32r(float x) {
    uint32_t u;
    asm("cvt.rna.tf32.f32 %0, %1;" : "=r"(u) : "f"(x));
    return __uint_as_float(u);
}
__device__ __forceinline__ void split4(float4 v, float4& h, float4& l) {
    h.x = tf32r(v.x); h.y = tf32r(v.y); h.z = tf32r(v.z); h.w = tf32r(v.w);
    l.x = tf32r(v.x - h.x); l.y = tf32r(v.y - h.y);
    l.z = tf32r(v.z - h.z); l.w = tf32r(v.w - h.w);
}
__device__ __forceinline__ void mma8(float* c, const uint32_t* a, const uint32_t* b) {
    asm volatile(
        "mma.sync.aligned.m16n8k8.row.col.f32.tf32.tf32.f32 "
        "{%0,%1,%2,%3}, {%4,%5,%6,%7}, {%8,%9}, {%0,%1,%2,%3};"
        : "+f"(c[0]), "+f"(c[1]), "+f"(c[2]), "+f"(c[3])
        : "r"(a[0]), "r"(a[1]), "r"(a[2]), "r"(a[3]), "r"(b[0]), "r"(b[1]));
}
__device__ __forceinline__ float sigm(float x) { return 1.0f / (1.0f + expf(-x)); }

__device__ __forceinline__ void sts_split(float* S, int tid,
                                          const float4* av, const float4* bv) {
    float* AHI = S;
    float* ALO = S + MSL;
    float* BHI = S + 2 * MSL;
    float* BLO = S + 3 * MSL;
#pragma unroll
    for (int j = 0; j < 2; j++) {
        int idx = j * 256 + tid;
        int row = idx >> 2, kq = idx & 3;
        int o = row * SR + kq * 4;
        float4 h, l;
        split4(av[j], h, l);
        *(float4*)&AHI[o] = h; *(float4*)&ALO[o] = l;
        split4(bv[j], h, l);
        *(float4*)&BHI[o] = h; *(float4*)&BLO[o] = l;
    }
}

// 3-pass fragment compute with STAGED fragment loads (reduced live registers):
// pass1 ah*bh, pass2 ah*bl (reload b-frags), pass3 al*bh (reload both).
__device__ __forceinline__ void mma_block(const float* S, int wm, int wn,
                                          int g, int tig, float acc[4][4][4]) {
    const float* AHI = S;
    const float* ALO = S + MSL;
    const float* BHI = S + 2 * MSL;
    const float* BLO = S + 3 * MSL;
#pragma unroll
    for (int ks = 0; ks < 2; ks++) {
        int kb = ks * 8;
        uint32_t af[4][4], bf[4][2];
#pragma unroll
        for (int m = 0; m < 4; m++) {
            int r0 = (wm * 64 + m * 16 + g) * SR + kb + tig;
            af[m][0] = __float_as_uint(AHI[r0]);
            af[m][1] = __float_as_uint(AHI[r0 + 8 * SR]);
            af[m][2] = __float_as_uint(AHI[r0 + 4]);
            af[m][3] = __float_as_uint(AHI[r0 + 8 * SR + 4]);
        }
#pragma unroll
        for (int n = 0; n < 4; n++) {
            int n0 = (wn * 32 + n * 8 + g) * SR + kb + tig;
            bf[n][0] = __float_as_uint(BHI[n0]);
            bf[n][1] = __float_as_uint(BHI[n0 + 4]);
        }
#pragma unroll
        for (int m = 0; m < 4; m++)
#pragma unroll
            for (int n = 0; n < 4; n++) mma8(acc[m][n], af[m], bf[n]);
#pragma unroll
        for (int n = 0; n < 4; n++) {
            int n0 = (wn * 32 + n * 8 + g) * SR + kb + tig;
            bf[n][0] = __float_as_uint(BLO[n0]);
            bf[n][1] = __float_as_uint(BLO[n0 + 4]);
        }
#pragma unroll
        for (int m = 0; m < 4; m++)
#pragma unroll
            for (int n = 0; n < 4; n++) mma8(acc[m][n], af[m], bf[n]);
#pragma unroll
        for (int m = 0; m < 4; m++) {
            int r0 = (wm * 64 + m * 16 + g) * SR + kb + tig;
            af[m][0] = __float_as_uint(ALO[r0]);
            af[m][1] = __float_as_uint(ALO[r0 + 8 * SR]);
            af[m][2] = __float_as_uint(ALO[r0 + 4]);
            af[m][3] = __float_as_uint(ALO[r0 + 8 * SR + 4]);
        }
#pragma unroll
        for (int n = 0; n < 4; n++) {
            int n0 = (wn * 32 + n * 8 + g) * SR + kb + tig;
            bf[n][0] = __float_as_uint(BHI[n0]);
            bf[n][1] = __float_as_uint(BHI[n0 + 4]);
        }
#pragma unroll
        for (int m = 0; m < 4; m++)
#pragma unroll
            for (int n = 0; n < 4; n++) mma8(acc[m][n], af[m], bf[n]);
    }
}

#define ACC_ZERO(acc)                                   \
    _Pragma("unroll")                                   \
    for (int a_ = 0; a_ < 4; a_++)                      \
        _Pragma("unroll")                               \
        for (int b_ = 0; b_ < 4; b_++)                  \
            _Pragma("unroll")                           \
            for (int c_ = 0; c_ < 4; c_++) acc[a_][b_][c_] = 0.0f;

// ---------------- init / scan -------------------------------------------------
__global__ void k_init() {
    int idx = blockIdx.x * 256 + threadIdx.x;
    if (idx < BB * HH) { g_h[idx] = 0.0f; g_c[idx] = 0.0f; }
}
__global__ void k_scan(const int* __restrict__ seq_lens) {
    int tid = threadIdx.x;   // 256
    if (tid == 0) {
        int acc = 0;
        for (int b = 0; b < BB; b++) { g_off[b] = acc; acc += seq_lens[b]; }
        g_nrows = acc;
    }
    if (tid < TT) {
        int c = 0;
        for (int b = 0; b < BB; b++) c += (seq_lens[b] > tid) ? 1 : 0;
        g_nb[tid] = c;
    }
    __syncthreads();
    {
        int b = tid;
        int o = g_off[b], len = seq_lens[b];
        for (int t = 0; t < len; t++) g_rbt[o + t] = (b << 6) | t;
    }
}
__global__ void k_I0(const float* __restrict__ init_t,
                     const float* __restrict__ W_ih) {
    int j = blockIdx.x * 256 + threadIdx.x;   // 4096
    const float* w = W_ih + (size_t)j * (DIN + EE) + DIN;
    float s = 0.0f;
    for (int e = 0; e < EE; e++) s += init_t[e] * w[e];
    g_I0[j] = s;
}

// ================= Phase A1: XW = x_t @ W_ih_x^T (packed rows) ================
__global__ __launch_bounds__(256, 2)
void kA_x(const float* __restrict__ enc, const float* __restrict__ W_ih) {
    const int bm = blockIdx.y * 128;
    if (bm >= g_nrows) return;
    const int bn = blockIdx.x * 128;

    __shared__ float S[4 * MSL];
    const int tid = threadIdx.x;
    const int wid = tid >> 5;
    const int wm  = wid >> 2, wn = wid & 3;
    const int g   = (tid & 31) >> 2, tig = tid & 3;
    const int kq  = tid & 3;

    const float* pa[2];
    const float* pb[2];
#pragma unroll
    for (int j = 0; j < 2; j++) {
        int row = ((j * 256 + tid) >> 2);
        int bt = g_rbt[bm + row];
        int b = bt >> 6, t = bt & 63;
        pa[j] = enc + ((size_t)b * TT + t) * DIN;
        pb[j] = W_ih + (size_t)(bn + row) * (DIN + EE);
    }

    float acc[4][4][4];
    ACC_ZERO(acc)
    float4 av[2], bv[2];
#pragma unroll
    for (int j = 0; j < 2; j++) {
        av[j] = *(const float4*)(pa[j] + kq * 4);
        bv[j] = *(const float4*)(pb[j] + kq * 4);
    }
    for (int i = 0; i < DIN / BK; i++) {
        __syncthreads();
        sts_split(S, tid, av, bv);
        __syncthreads();
        if (i + 1 < DIN / BK) {
            int kkb = (i + 1) * BK + kq * 4;
#pragma unroll
            for (int j = 0; j < 2; j++) {
                av[j] = *(const float4*)(pa[j] + kkb);
                bv[j] = *(const float4*)(pb[j] + kkb);
            }
        }
        mma_block(S, wm, wn, g, tig, acc);
    }
#pragma unroll
    for (int m = 0; m < 4; m++) {
        int lr0 = wm * 64 + m * 16 + g, lr1 = lr0 + 8;
#pragma unroll
        for (int n = 0; n < 4; n++) {
            int col = bn + wn * 32 + n * 8 + 2 * tig;
            *(float2*)&g_XW[(size_t)(bm + lr0) * FOURH + col] =
                make_float2(acc[m][n][0], acc[m][n][1]);
            *(float2*)&g_XW[(size_t)(bm + lr1) * FOURH + col] =
                make_float2(acc[m][n][2], acc[m][n][3]);
        }
    }
}

// ================= Phase A2: EW = emb @ W_ih_e^T ==============================
__global__ __launch_bounds__(256, 2)
void kA_e(const float* __restrict__ emb, const float* __restrict__ W_ih) {
    const int bm = blockIdx.y * 128;
    const int bn = blockIdx.x * 128;

    __shared__ float S[4 * MSL];
    const int tid = threadIdx.x;
    const int wid = tid >> 5;
    const int wm  = wid >> 2, wn = wid & 3;
    const int g   = (tid & 31) >> 2, tig = tid & 3;
    const int kq  = tid & 3;

    const float* pa[2];
    const float* pb[2];
#pragma unroll
    for (int j = 0; j < 2; j++) {
        int row = ((j * 256 + tid) >> 2);
        pa[j] = emb + (size_t)(bm + row) * EE;
        pb[j] = W_ih + (size_t)(bn + row) * (DIN + EE) + DIN;
    }

    float acc[4][4][4];
    ACC_ZERO(acc)
    float4 av[2], bv[2];
#pragma unroll
    for (int j = 0; j < 2; j++) {
        av[j] = *(const float4*)(pa[j] + kq * 4);
        bv[j] = *(const float4*)(pb[j] + kq * 4);
    }
    for (int i = 0; i < EE / BK; i++) {
        __syncthreads();
        sts_split(S, tid, av, bv);
        __syncthreads();
        if (i + 1 < EE / BK) {
            int kkb = (i + 1) * BK + kq * 4;
#pragma unroll
            for (int j = 0; j < 2; j++) {
                av[j] = *(const float4*)(pa[j] + kkb);
                bv[j] = *(const float4*)(pb[j] + kkb);
            }
        }
        mma_block(S, wm, wn, g, tig, acc);
    }
#pragma unroll
    for (int m = 0; m < 4; m++) {
        int lr0 = wm * 64 + m * 16 + g, lr1 = lr0 + 8;
#pragma unroll
        for (int n = 0; n < 4; n++) {
            int col = bn + wn * 32 + n * 8 + 2 * tig;
            *(float2*)&g_EW[(size_t)(bm + lr0) * FOURH + col] =
                make_float2(acc[m][n][0], acc[m][n][1]);
            *(float2*)&g_EW[(size_t)(bm + lr1) * FOURH + col] =
                make_float2(acc[m][n][2], acc[m][n][3]);
        }
    }
}

// ================= GEMM 1 (in-loop): h @ W_hh^T ===============================
// grid (32, 4, 2) = 256 CTAs, occ 2.
// full (nbt>128): m-tile = bz, K-quarter = by, slot = bz*4+by, 16 chunks.
// split:          m-tile 0, K-eighth = by*2+bz, slot = same,   8 chunks.
__global__ __launch_bounds__(256, 2)
void k_gates(const float* __restrict__ W_hh, int t) {
    const int nbt = g_nb[t];
    int bm, kbeg, nch, slot;
    if (nbt > 128) {
        bm = blockIdx.z * 128;
        kbeg = blockIdx.y * (HH / 4);
        nch = (HH / 4) / BK;   // 16
        slot = blockIdx.z * 4 + blockIdx.y;
    } else {
        bm = 0;
        int ks = blockIdx.y * 2 + blockIdx.z;
        kbeg = ks * (HH / 8);
        nch = (HH / 8) / BK;   // 8
        slot = ks;
    }
    const int bn = blockIdx.x * 128;

    __shared__ float S[4 * MSL];
    const int tid = threadIdx.x;
    const int wid = tid >> 5;
    const int wm  = wid >> 2, wn = wid & 3;
    const int g   = (tid & 31) >> 2, tig = tid & 3;
    const int kq  = tid & 3;

    const float* pa[2];
    const float* pb[2];
#pragma unroll
    for (int j = 0; j < 2; j++) {
        int row = ((j * 256 + tid) >> 2);
        pa[j] = g_h + (size_t)(bm + row) * HH + kbeg;
        pb[j] = W_hh + (size_t)(bn + row) * HH + kbeg;
    }

    float acc[4][4][4];
    ACC_ZERO(acc)
    float4 av[2], bv[2];
#pragma unroll
    for (int j = 0; j < 2; j++) {
        av[j] = *(const float4*)(pa[j] + kq * 4);
        bv[j] = *(const float4*)(pb[j] + kq * 4);
    }
    for (int i = 0; i < nch; i++) {
        __syncthreads();
        sts_split(S, tid, av, bv);
        __syncthreads();
        if (i + 1 < nch) {
            int kkb = (i + 1) * BK + kq * 4;
#pragma unroll
            for (int j = 0; j < 2; j++) {
                av[j] = *(const float4*)(pa[j] + kkb);
                bv[j] = *(const float4*)(pb[j] + kkb);
            }
        }
        mma_block(S, wm, wn, g, tig, acc);
    }
#pragma unroll
    for (int m = 0; m < 4; m++) {
        int lr0 = wm * 64 + m * 16 + g, lr1 = lr0 + 8;
#pragma unroll
        for (int n = 0; n < 4; n++) {
            int col = bn + wn * 32 + n * 8 + 2 * tig;
            *(float2*)&g_P[slot][lr0][col] = make_float2(acc[m][n][0], acc[m][n][1]);
            *(float2*)&g_P[slot][lr1][col] = make_float2(acc[m][n][2], acc[m][n][3]);
        }
    }
}

// ---------------- LSTM cell (4/8-way partial gather, fixed trees) -------------
__global__ void k_cell(const float* __restrict__ b_ih,
                       const float* __restrict__ b_hh,
                       const int* __restrict__ seq_lens,
                       int t) {
    int idx = blockIdx.x * 256 + threadIdx.x;
    int b = idx >> 10, j = idx & 1023;
    int nbt = g_nb[t];
    if (nbt <= 128 && b >= 128) return;
    if (t >= seq_lens[b]) return;

    float gate[4];
#pragma unroll
    for (int q = 0; q < 4; q++) {
        int jj = q * 1024 + j;
        float v;
        if (nbt > 128) {
            int s0 = (b >> 7) * 4, lr = b & 127;
            v = (g_P[s0][lr][jj] + g_P[s0 + 1][lr][jj]) +
                (g_P[s0 + 2][lr][jj] + g_P[s0 + 3][lr][jj]);
        } else {
            v = ((g_P[0][b][jj] + g_P[1][b][jj]) + (g_P[2][b][jj] + g_P[3][b][jj])) +
                ((g_P[4][b][jj] + g_P[5][b][jj]) + (g_P[6][b][jj] + g_P[7][b][jj]));
        }
        gate[q] = v;
    }
    const float* XW = g_XW + (size_t)(g_off[b] + t) * FOURH;
    const float* EW = (t == 0) ? g_I0 : g_EW + (size_t)g_amax[b] * FOURH;
    float i_ = gate[0] + XW[j]        + EW[j]        + b_ih[j]        + b_hh[j];
    float f_ = gate[1] + XW[1024 + j] + EW[1024 + j] + b_ih[1024 + j] + b_hh[1024 + j];
    float gg = gate[2] + XW[2048 + j] + EW[2048 + j] + b_ih[2048 + j] + b_hh[2048 + j];
    float o_ = gate[3] + XW[3072 + j] + EW[3072 + j] + b_ih[3072 + j] + b_hh[3072 + j];
    float c = sigm(f_) * g_c[idx] + sigm(i_) * tanhf(gg);
    float h = sigm(o_) * tanhf(c);
    g_c[idx] = c;
    g_h[idx] = h;
}

// ================= GEMM 2: logits (always split-K) + fused argmax =============
// Deterministic combine: fixed trees; own acc value == stored value (exact).
__device__ __forceinline__ void logits_out(
    float acc[4][4][4], int own, int slot0, int nop,
    const float* __restrict__ lin_b, const int* __restrict__ seq_lens,
    float* __restrict__ out, int t,
    int bm, int bn, int wm, int wn, int g, int tig, int bx) {
#pragma unroll
    for (int half = 0; half < 2; half++) {
#pragma unroll
        for (int mt = 0; mt < 4; mt++) {
            int lr = wm * 64 + mt * 16 + g + half * 8;
            int gm = bm + lr;
            int len = seq_lens[gm];
            bool wr = (t < len);
            float* orow = out + (size_t)(g_off[gm] + t) * VV;

            float bvv = -3.4e38f;
            int   bii = 0;
#pragma unroll
            for (int nt = 0; nt < 4; nt++) {
                int col = bn + wn * 32 + nt * 8 + 2 * tig;
                float a0 = acc[mt][nt][half * 2 + 0];
                float a1 = acc[mt][nt][half * 2 + 1];
                float v0, v1;
                if (nop == 2) {
                    int oth = (own == slot0) ? slot0 + 1 : slot0;
                    v0 = a0 + __ldcg(&g_logP[oth][lr][col]);
                    v1 = a1 + __ldcg(&g_logP[oth][lr][col + 1]);
                } else {
                    float x0 = (own == 0) ? a0 : __ldcg(&g_logP[0][lr][col]);
                    float x1 = (own == 1) ? a0 : __ldcg(&g_logP[1][lr][col]);
                    float x2 = (own == 2) ? a0 : __ldcg(&g_logP[2][lr][col]);
                    float x3 = (own == 3) ? a0 : __ldcg(&g_logP[3][lr][col]);
                    v0 = (x0 + x1) + (x2 + x3);
                    float y0 = (own == 0) ? a1 : __ldcg(&g_logP[0][lr][col + 1]);
                    float y1 = (own == 1) ? a1 : __ldcg(&g_logP[1][lr][col + 1]);
                    float y2 = (own == 2) ? a1 : __ldcg(&g_logP[2][lr][col + 1]);
                    float y3 = (own == 3) ? a1 : __ldcg(&g_logP[3][lr][col + 1]);
                    v1 = (y0 + y1) + (y2 + y3);
                }
                v0 += lin_b[col];
                v1 += lin_b[col + 1];
                if (wr) *(float2*)&orow[col] = make_float2(v0, v1);
                if (v0 > bvv) { bvv = v0; bii = col; }
                if (v1 > bvv) { bvv = v1; bii = col + 1; }
            }
#pragma unroll
            for (int off = 1; off < 4; off <<= 1) {
                float ov = __shfl_xor_sync(0xffffffffu, bvv, off, 4);
                int   oi = __shfl_xor_sync(0xffffffffu, bii, off, 4);
                if (ov > bvv || (ov == bvv && oi < bii)) { bvv = ov; bii = oi; }
            }
            if (tig == 0) {
                int slot = bx * 4 + wn;
                g_pval[(size_t)gm * 256 + slot] = bvv;
                g_pidx[(size_t)gm * 256 + slot] = bii;
            }
        }
    }
}

// grid (64, 2, 2) = 256 CTAs, occ 2.
// full: m-tile = bz, K-half = by, pslot = bz*2+by; combine pair per (bx,bz).
// split: m 0, K-quarter q = by*2+bz, pslot = q; 4-way combine per bx.
__global__ __launch_bounds__(256, 2)
void k_logits(const float* __restrict__ lin_W,
              const float* __restrict__ lin_b,
              const int*   __restrict__ seq_lens,
              float* __restrict__ out,
              int t) {
    const int nbt = g_nb[t];
    const bool split = (nbt <= 128);
    const int bx = blockIdx.x, by = blockIdx.y, bz = blockIdx.z;
    int bm, kbeg, nch, own, slot0, nop, cidx, cthr, fi;
    if (!split) {
        bm = bz * 128; kbeg = by * (HH / 2); nch = (HH / 2) / BK;  // 32
        own = bz * 2 + by; slot0 = bz * 2; nop = 2;
        cidx = bx * 2 + bz; cthr = 2; fi = bz;
    } else {
        int q = by * 2 + bz;
        bm = 0; kbeg = q * (HH / 4); nch = (HH / 4) / BK;          // 16
        own = q; slot0 = 0; nop = 4;
        cidx = bx; cthr = 4; fi = 0;
    }
    const int bn = bx * 128;

    __shared__ float S[4 * MSL];
    const int tid = threadIdx.x;
    const int wid = tid >> 5;
    const int wm  = wid >> 2, wn = wid & 3;
    const int g   = (tid & 31) >> 2, tig = tid & 3;
    const int kq  = tid & 3;

    const float* pa[2];
    const float* pb[2];
#pragma unroll
    for (int j = 0; j < 2; j++) {
        int row = ((j * 256 + tid) >> 2);
        pa[j] = g_h + (size_t)(bm + row) * HH + kbeg;
        pb[j] = lin_W + (size_t)(bn + row) * HH + kbeg;
    }

    float acc[4][4][4];
    ACC_ZERO(acc)
    float4 av[2], bv[2];
#pragma unroll
    for (int j = 0; j < 2; j++) {
        av[j] = *(const float4*)(pa[j] + kq * 4);
        bv[j] = *(const float4*)(pb[j] + kq * 4);
    }
    for (int i = 0; i < nch; i++) {
        __syncthreads();
        sts_split(S, tid, av, bv);
        __syncthreads();
        if (i + 1 < nch) {
            int kkb = (i + 1) * BK + kq * 4;
#pragma unroll
            for (int j = 0; j < 2; j++) {
                av[j] = *(const float4*)(pa[j] + kkb);
                bv[j] = *(const float4*)(pb[j] + kkb);
            }
        }
        mma_block(S, wm, wn, g, tig, acc);
    }

    // store my partial
#pragma unroll
    for (int half = 0; half < 2; half++)
#pragma unroll
        for (int mt = 0; mt < 4; mt++) {
            int lr = wm * 64 + mt * 16 + g + half * 8;
#pragma unroll
            for (int nt = 0; nt < 4; nt++) {
                int col = bn + wn * 32 + nt * 8 + 2 * tig;
                *(float2*)&g_logP[own][lr][col] =
                    make_float2(acc[mt][nt][half * 2], acc[mt][nt][half * 2 + 1]);
            }
        }
    __syncthreads();
    __shared__ int swin;
    if (tid == 0) {
        __threadfence();
        int old = atomicAdd(&g_lcnt[cidx], 1);
        swin = (old == cthr - 1);
        if (old == cthr - 1) g_lcnt[cidx] = 0;
    }
    __syncthreads();
    if (!swin) return;
    __threadfence();
    logits_out(acc, own, slot0, nop, lin_b, seq_lens, out, t,
               bm, bn, wm, wn, g, tig, bx);

    // ---- fused final argmax: 64 winners per m-tile ----
    __syncthreads();
    __shared__ int lastf;
    if (tid == 0) {
        __threadfence();
        int old = atomicAdd(&g_fcnt[fi], 1);
        lastf = (old == 63);
        if (old == 63) g_fcnt[fi] = 0;
    }
    __syncthreads();
    if (!lastf) return;
    __threadfence();

    {
        int wv = tid >> 5, lane = tid & 31;
#pragma unroll 1
        for (int i = 0; i < 16; i++) {
            int b = bm + wv * 16 + i;
            float v = -3.4e38f;
            int   bi = 0x7fffffff;
            for (int s = lane; s < 256; s += 32) {
                float pv = __ldcg(&g_pval[(size_t)b * 256 + s]);
                int   pi = __ldcg(&g_pidx[(size_t)b * 256 + s]);
                if (pv > v || (pv == v && pi < bi)) { v = pv; bi = pi; }
            }
#pragma unroll
            for (int off = 16; off; off >>= 1) {
                float ov = __shfl_xor_sync(0xffffffffu, v, off);
                int   oi = __shfl_xor_sync(0xffffffffu, bi, off);
                if (ov > v || (ov == v && oi < bi)) { v = ov; bi = oi; }
            }
            if (lane == 0) g_amax[b] = bi;
        }
    }
}

// ---------------- launch ------------------------------------------------------
extern "C" void kernel_launch(void* const* d_in, const int* in_sizes, int n_in,
                              void* d_out, int out_size) {
    const float* enc      = (const float*)d_in[0];
    const float* emb      = (const float*)d_in[1];
    const float* init_t   = (const float*)d_in[2];
    const float* W_ih     = (const float*)d_in[3];
    const float* W_hh     = (const float*)d_in[4];
    const float* b_ih     = (const float*)d_in[5];
    const float* b_hh     = (const float*)d_in[6];
    const float* lin_W    = (const float*)d_in[7];
    const float* lin_b    = (const float*)d_in[8];
    const int*   seq_lens = (const int*)d_in[9];
    float*       out      = (float*)d_out;

    k_init<<<(BB * HH + 255) / 256, 256>>>();
    k_scan<<<1, 256>>>(seq_lens);
    k_I0<<<FOURH / 256, 256>>>(init_t, W_ih);
    kA_e<<<dim3(32, VV / 128), 256>>>(emb, W_ih);
    kA_x<<<dim3(32, (BB * TT) / 128), 256>>>(enc, W_ih);

    for (int t = 0; t < TT; t++) {
        k_gates<<<dim3(32, 4, 2), 256>>>(W_hh, t);
        k_cell<<<(BB * HH + 255) / 256, 256>>>(b_ih, b_hh, seq_lens, t);
        k_logits<<<dim3(64, 2, 2), 256>>>(lin_W, lin_b, seq_lens, out, t);
    }
}

// round 10
// speedup vs baseline: 1.5685x; 1.0529x over previous
#include <cuda_runtime.h>
#include <cstdint>
#include <cstddef>

// Problem dims (fixed)
#define BB    256
#define TT    64
#define DIN   1024
#define HH    1024
#define EE    256
#define VV    8192
#define FOURH 4096
#define BK    16
#define SR    20              // smem row stride (floats), bank-perfect
#define MSL   (128 * SR)
#define STAGE_F (4 * MSL)     // floats per pipeline stage
#define SMEM_B  (2 * STAGE_F * 4)   // dynamic smem bytes (81920)

// ---------------- scratch ----------------------------------------------------
__device__ float g_h[BB * HH];
__device__ float g_c[BB * HH];
__device__ float g_XW[BB * TT * FOURH];   // packed x_t @ W_ih_x^T
__device__ float g_EW[VV * FOURH];        // emb @ W_ih_e^T
__device__ float g_I0[FOURH];             // init_tensor @ W_ih_e^T
__device__ int   g_amax[BB];
__device__ float g_P[8][128][FOURH];      // gates partials (8-way max)
__device__ float g_logP[4][128][VV];      // logits split-K partials (4-way max)
__device__ int   g_lcnt[128];             // combine counters (zero-init)
__device__ int   g_fcnt[2];
__device__ float g_pval[BB * 256];
__device__ int   g_pidx[BB * 256];
__device__ int   g_off[BB];
__device__ int   g_nb[TT];
__device__ int   g_nrows;
__device__ int   g_rbt[BB * TT];          // packed row -> (b<<6)|t

// ---------------- helpers -----------------------------------------------------
__device__ __forceinline__ float tf32r(float x) {
    uint32_t u;
    asm("cvt.rna.tf32.f32 %0, %1;" : "=r"(u) : "f"(x));
    return __uint_as_float(u);
}
__device__ __forceinline__ void split4(float4 v, float4& h, float4& l) {
    h.x = tf32r(v.x); h.y = tf32r(v.y); h.z = tf32r(v.z); h.w = tf32r(v.w);
    l.x = tf32r(v.x - h.x); l.y = tf32r(v.y - h.y);
    l.z = tf32r(v.z - h.z); l.w = tf32r(v.w - h.w);
}
__device__ __forceinline__ void mma8(float* c, const uint32_t* a, const uint32_t* b) {
    asm volatile(
        "mma.sync.aligned.m16n8k8.row.col.f32.tf32.tf32.f32 "
        "{%0,%1,%2,%3}, {%4,%5,%6,%7}, {%8,%9}, {%0,%1,%2,%3};"
        : "+f"(c[0]), "+f"(c[1]), "+f"(c[2]), "+f"(c[3])
        : "r"(a[0]), "r"(a[1]), "r"(a[2]), "r"(a[3]), "r"(b[0]), "r"(b[1]));
}
__device__ __forceinline__ float sigm(float x) { return 1.0f / (1.0f + expf(-x)); }

__device__ __forceinline__ void sts_split(float* S, int tid,
                                          const float4* av, const float4* bv) {
    float* AHI = S;
    float* ALO = S + MSL;
    float* BHI = S + 2 * MSL;
    float* BLO = S + 3 * MSL;
#pragma unroll
    for (int j = 0; j < 2; j++) {
        int idx = j * 256 + tid;
        int row = idx >> 2, kq = idx & 3;
        int o = row * SR + kq * 4;
        float4 h, l;
        split4(av[j], h, l);
        *(float4*)&AHI[o] = h; *(float4*)&ALO[o] = l;
        split4(bv[j], h, l);
        *(float4*)&BHI[o] = h; *(float4*)&BLO[o] = l;
    }
}

// 3-pass fragment compute with staged fragment loads (register-lean)
__device__ __forceinline__ void mma_block(const float* S, int wm, int wn,
                                          int g, int tig, float acc[4][4][4]) {
    const float* AHI = S;
    const float* ALO = S + MSL;
    const float* BHI = S + 2 * MSL;
    const float* BLO = S + 3 * MSL;
#pragma unroll
    for (int ks = 0; ks < 2; ks++) {
        int kb = ks * 8;
        uint32_t af[4][4], bf[4][2];
#pragma unroll
        for (int m = 0; m < 4; m++) {
            int r0 = (wm * 64 + m * 16 + g) * SR + kb + tig;
            af[m][0] = __float_as_uint(AHI[r0]);
            af[m][1] = __float_as_uint(AHI[r0 + 8 * SR]);
            af[m][2] = __float_as_uint(AHI[r0 + 4]);
            af[m][3] = __float_as_uint(AHI[r0 + 8 * SR + 4]);
        }
#pragma unroll
        for (int n = 0; n < 4; n++) {
            int n0 = (wn * 32 + n * 8 + g) * SR + kb + tig;
            bf[n][0] = __float_as_uint(BHI[n0]);
            bf[n][1] = __float_as_uint(BHI[n0 + 4]);
        }
#pragma unroll
        for (int m = 0; m < 4; m++)
#pragma unroll
            for (int n = 0; n < 4; n++) mma8(acc[m][n], af[m], bf[n]);
#pragma unroll
        for (int n = 0; n < 4; n++) {
            int n0 = (wn * 32 + n * 8 + g) * SR + kb + tig;
            bf[n][0] = __float_as_uint(BLO[n0]);
            bf[n][1] = __float_as_uint(BLO[n0 + 4]);
        }
#pragma unroll
        for (int m = 0; m < 4; m++)
#pragma unroll
            for (int n = 0; n < 4; n++) mma8(acc[m][n], af[m], bf[n]);
#pragma unroll
        for (int m = 0; m < 4; m++) {
            int r0 = (wm * 64 + m * 16 + g) * SR + kb + tig;
            af[m][0] = __float_as_uint(ALO[r0]);
            af[m][1] = __float_as_uint(ALO[r0 + 8 * SR]);
            af[m][2] = __float_as_uint(ALO[r0 + 4]);
            af[m][3] = __float_as_uint(ALO[r0 + 8 * SR + 4]);
        }
#pragma unroll
        for (int n = 0; n < 4; n++) {
            int n0 = (wn * 32 + n * 8 + g) * SR + kb + tig;
            bf[n][0] = __float_as_uint(BHI[n0]);
            bf[n][1] = __float_as_uint(BHI[n0 + 4]);
        }
#pragma unroll
        for (int m = 0; m < 4; m++)
#pragma unroll
            for (int n = 0; n < 4; n++) mma8(acc[m][n], af[m], bf[n]);
    }
}

#define ACC_ZERO(acc)                                   \
    _Pragma("unroll")                                   \
    for (int a_ = 0; a_ < 4; a_++)                      \
        _Pragma("unroll")                               \
        for (int b_ = 0; b_ < 4; b_++)                  \
            _Pragma("unroll")                           \
            for (int c_ = 0; c_ < 4; c_++) acc[a_][b_][c_] = 0.0f;

// Double-buffered mainloop: 1 sync per chunk, STS overlapped with MMA.
#define GEMM_PIPELINE(S, nch, LOADG)                          \
    LOADG(0);                                                 \
    sts_split(S, tid, av, bv);                                \
    __syncthreads();                                          \
    for (int i = 0; i < (nch); i++) {                         \
        float* cur_ = (S) + (i & 1) * STAGE_F;                \
        bool more_ = (i + 1 < (nch));                         \
        if (more_) LOADG(i + 1);                              \
        mma_block(cur_, wm, wn, g, tig, acc);                 \
        if (more_) sts_split((S) + ((i + 1) & 1) * STAGE_F, tid, av, bv); \
        __syncthreads();                                      \
    }

// ---------------- init / scan -------------------------------------------------
__global__ void k_init() {
    int idx = blockIdx.x * 256 + threadIdx.x;
    if (idx < BB * HH) { g_h[idx] = 0.0f; g_c[idx] = 0.0f; }
}
__global__ void k_scan(const int* __restrict__ seq_lens) {
    int tid = threadIdx.x;   // 256
    if (tid == 0) {
        int acc = 0;
        for (int b = 0; b < BB; b++) { g_off[b] = acc; acc += seq_lens[b]; }
        g_nrows = acc;
    }
    if (tid < TT) {
        int c = 0;
        for (int b = 0; b < BB; b++) c += (seq_lens[b] > tid) ? 1 : 0;
        g_nb[tid] = c;
    }
    __syncthreads();
    {
        int b = tid;
        int o = g_off[b], len = seq_lens[b];
        for (int t = 0; t < len; t++) g_rbt[o + t] = (b << 6) | t;
    }
}
__global__ void k_I0(const float* __restrict__ init_t,
                     const float* __restrict__ W_ih) {
    int j = blockIdx.x * 256 + threadIdx.x;   // 4096
    const float* w = W_ih + (size_t)j * (DIN + EE) + DIN;
    float s = 0.0f;
    for (int e = 0; e < EE; e++) s += init_t[e] * w[e];
    g_I0[j] = s;
}

// ================= Phase A1: XW = x_t @ W_ih_x^T (packed rows) ================
__global__ __launch_bounds__(256, 2)
void kA_x(const float* __restrict__ enc, const float* __restrict__ W_ih) {
    const int bm = blockIdx.y * 128;
    if (bm >= g_nrows) return;
    const int bn = blockIdx.x * 128;

    extern __shared__ float S[];
    const int tid = threadIdx.x;
    const int wid = tid >> 5;
    const int wm  = wid >> 2, wn = wid & 3;
    const int g   = (tid & 31) >> 2, tig = tid & 3;
    const int kq  = tid & 3;

    const float* pa[2];
    const float* pb[2];
#pragma unroll
    for (int j = 0; j < 2; j++) {
        int row = ((j * 256 + tid) >> 2);
        int bt = g_rbt[bm + row];
        int b = bt >> 6, t = bt & 63;
        pa[j] = enc + ((size_t)b * TT + t) * DIN;
        pb[j] = W_ih + (size_t)(bn + row) * (DIN + EE);
    }

    float acc[4][4][4];
    ACC_ZERO(acc)
    float4 av[2], bv[2];
#define LG(ch)                                                    \
    { int kkb = (ch) * BK + kq * 4;                               \
      _Pragma("unroll")                                           \
      for (int j = 0; j < 2; j++) {                               \
          av[j] = *(const float4*)(pa[j] + kkb);                  \
          bv[j] = *(const float4*)(pb[j] + kkb); } }
    GEMM_PIPELINE(S, DIN / BK, LG)
#undef LG
#pragma unroll
    for (int m = 0; m < 4; m++) {
        int lr0 = wm * 64 + m * 16 + g, lr1 = lr0 + 8;
#pragma unroll
        for (int n = 0; n < 4; n++) {
            int col = bn + wn * 32 + n * 8 + 2 * tig;
            *(float2*)&g_XW[(size_t)(bm + lr0) * FOURH + col] =
                make_float2(acc[m][n][0], acc[m][n][1]);
            *(float2*)&g_XW[(size_t)(bm + lr1) * FOURH + col] =
                make_float2(acc[m][n][2], acc[m][n][3]);
        }
    }
}

// ================= Phase A2: EW = emb @ W_ih_e^T ==============================
__global__ __launch_bounds__(256, 2)
void kA_e(const float* __restrict__ emb, const float* __restrict__ W_ih) {
    const int bm = blockIdx.y * 128;
    const int bn = blockIdx.x * 128;

    extern __shared__ float S[];
    const int tid = threadIdx.x;
    const int wid = tid >> 5;
    const int wm  = wid >> 2, wn = wid & 3;
    const int g   = (tid & 31) >> 2, tig = tid & 3;
    const int kq  = tid & 3;

    const float* pa[2];
    const float* pb[2];
#pragma unroll
    for (int j = 0; j < 2; j++) {
        int row = ((j * 256 + tid) >> 2);
        pa[j] = emb + (size_t)(bm + row) * EE;
        pb[j] = W_ih + (size_t)(bn + row) * (DIN + EE) + DIN;
    }

    float acc[4][4][4];
    ACC_ZERO(acc)
    float4 av[2], bv[2];
#define LG(ch)                                                    \
    { int kkb = (ch) * BK + kq * 4;                               \
      _Pragma("unroll")                                           \
      for (int j = 0; j < 2; j++) {                               \
          av[j] = *(const float4*)(pa[j] + kkb);                  \
          bv[j] = *(const float4*)(pb[j] + kkb); } }
    GEMM_PIPELINE(S, EE / BK, LG)
#undef LG
#pragma unroll
    for (int m = 0; m < 4; m++) {
        int lr0 = wm * 64 + m * 16 + g, lr1 = lr0 + 8;
#pragma unroll
        for (int n = 0; n < 4; n++) {
            int col = bn + wn * 32 + n * 8 + 2 * tig;
            *(float2*)&g_EW[(size_t)(bm + lr0) * FOURH + col] =
                make_float2(acc[m][n][0], acc[m][n][1]);
            *(float2*)&g_EW[(size_t)(bm + lr1) * FOURH + col] =
                make_float2(acc[m][n][2], acc[m][n][3]);
        }
    }
}

// ================= GEMM 1 (in-loop): h @ W_hh^T ===============================
// grid (32, 4, 2) = 256 CTAs, occ 2.
__global__ __launch_bounds__(256, 2)
void k_gates(const float* __restrict__ W_hh, int t) {
    const int nbt = g_nb[t];
    int bm, kbeg, nch, slot;
    if (nbt > 128) {
        bm = blockIdx.z * 128;
        kbeg = blockIdx.y * (HH / 4);
        nch = (HH / 4) / BK;   // 16
        slot = blockIdx.z * 4 + blockIdx.y;
    } else {
        bm = 0;
        int ks = blockIdx.y * 2 + blockIdx.z;
        kbeg = ks * (HH / 8);
        nch = (HH / 8) / BK;   // 8
        slot = ks;
    }
    const int bn = blockIdx.x * 128;

    extern __shared__ float S[];
    const int tid = threadIdx.x;
    const int wid = tid >> 5;
    const int wm  = wid >> 2, wn = wid & 3;
    const int g   = (tid & 31) >> 2, tig = tid & 3;
    const int kq  = tid & 3;

    const float* pa[2];
    const float* pb[2];
#pragma unroll
    for (int j = 0; j < 2; j++) {
        int row = ((j * 256 + tid) >> 2);
        pa[j] = g_h + (size_t)(bm + row) * HH + kbeg;
        pb[j] = W_hh + (size_t)(bn + row) * HH + kbeg;
    }

    float acc[4][4][4];
    ACC_ZERO(acc)
    float4 av[2], bv[2];
#define LG(ch)                                                    \
    { int kkb = (ch) * BK + kq * 4;                               \
      _Pragma("unroll")                                           \
      for (int j = 0; j < 2; j++) {                               \
          av[j] = *(const float4*)(pa[j] + kkb);                  \
          bv[j] = *(const float4*)(pb[j] + kkb); } }
    GEMM_PIPELINE(S, nch, LG)
#undef LG
#pragma unroll
    for (int m = 0; m < 4; m++) {
        int lr0 = wm * 64 + m * 16 + g, lr1 = lr0 + 8;
#pragma unroll
        for (int n = 0; n < 4; n++) {
            int col = bn + wn * 32 + n * 8 + 2 * tig;
            *(float2*)&g_P[slot][lr0][col] = make_float2(acc[m][n][0], acc[m][n][1]);
            *(float2*)&g_P[slot][lr1][col] = make_float2(acc[m][n][2], acc[m][n][3]);
        }
    }
}

// ---------------- LSTM cell (4/8-way partial gather, fixed trees) -------------
__global__ void k_cell(const float* __restrict__ b_ih,
                       const float* __restrict__ b_hh,
                       const int* __restrict__ seq_lens,
                       int t) {
    int idx = blockIdx.x * 256 + threadIdx.x;
    int b = idx >> 10, j = idx & 1023;
    int nbt = g_nb[t];
    if (nbt <= 128 && b >= 128) return;
    if (t >= seq_lens[b]) return;

    float gate[4];
#pragma unroll
    for (int q = 0; q < 4; q++) {
        int jj = q * 1024 + j;
        float v;
        if (nbt > 128) {
            int s0 = (b >> 7) * 4, lr = b & 127;
            v = (g_P[s0][lr][jj] + g_P[s0 + 1][lr][jj]) +
                (g_P[s0 + 2][lr][jj] + g_P[s0 + 3][lr][jj]);
        } else {
            v = ((g_P[0][b][jj] + g_P[1][b][jj]) + (g_P[2][b][jj] + g_P[3][b][jj])) +
                ((g_P[4][b][jj] + g_P[5][b][jj]) + (g_P[6][b][jj] + g_P[7][b][jj]));
        }
        gate[q] = v;
    }
    const float* XW = g_XW + (size_t)(g_off[b] + t) * FOURH;
    const float* EW = (t == 0) ? g_I0 : g_EW + (size_t)g_amax[b] * FOURH;
    float i_ = gate[0] + XW[j]        + EW[j]        + b_ih[j]        + b_hh[j];
    float f_ = gate[1] + XW[1024 + j] + EW[1024 + j] + b_ih[1024 + j] + b_hh[1024 + j];
    float gg = gate[2] + XW[2048 + j] + EW[2048 + j] + b_ih[2048 + j] + b_hh[2048 + j];
    float o_ = gate[3] + XW[3072 + j] + EW[3072 + j] + b_ih[3072 + j] + b_hh[3072 + j];
    float c = sigm(f_) * g_c[idx] + sigm(i_) * tanhf(gg);
    float h = sigm(o_) * tanhf(c);
    g_c[idx] = c;
    g_h[idx] = h;
}

// ================= GEMM 2: logits (split-K) + fused argmax ====================
__device__ __forceinline__ void logits_out(
    float acc[4][4][4], int own, int slot0, int nop,
    const float* __restrict__ lin_b, const int* __restrict__ seq_lens,
    float* __restrict__ out, int t,
    int bm, int bn, int wm, int wn, int g, int tig, int bx) {
#pragma unroll
    for (int half = 0; half < 2; half++) {
#pragma unroll
        for (int mt = 0; mt < 4; mt++) {
            int lr = wm * 64 + mt * 16 + g + half * 8;
            int gm = bm + lr;
            int len = seq_lens[gm];
            bool wr = (t < len);
            float* orow = out + (size_t)(g_off[gm] + t) * VV;

            float bvv = -3.4e38f;
            int   bii = 0;
#pragma unroll
            for (int nt = 0; nt < 4; nt++) {
                int col = bn + wn * 32 + nt * 8 + 2 * tig;
                float a0 = acc[mt][nt][half * 2 + 0];
                float a1 = acc[mt][nt][half * 2 + 1];
                float v0, v1;
                if (nop == 2) {
                    int oth = (own == slot0) ? slot0 + 1 : slot0;
                    v0 = a0 + __ldcg(&g_logP[oth][lr][col]);
                    v1 = a1 + __ldcg(&g_logP[oth][lr][col + 1]);
                } else {
                    float x0 = (own == 0) ? a0 : __ldcg(&g_logP[0][lr][col]);
                    float x1 = (own == 1) ? a0 : __ldcg(&g_logP[1][lr][col]);
                    float x2 = (own == 2) ? a0 : __ldcg(&g_logP[2][lr][col]);
                    float x3 = (own == 3) ? a0 : __ldcg(&g_logP[3][lr][col]);
                    v0 = (x0 + x1) + (x2 + x3);
                    float y0 = (own == 0) ? a1 : __ldcg(&g_logP[0][lr][col + 1]);
                    float y1 = (own == 1) ? a1 : __ldcg(&g_logP[1][lr][col + 1]);
                    float y2 = (own == 2) ? a1 : __ldcg(&g_logP[2][lr][col + 1]);
                    float y3 = (own == 3) ? a1 : __ldcg(&g_logP[3][lr][col + 1]);
                    v1 = (y0 + y1) + (y2 + y3);
                }
                v0 += lin_b[col];
                v1 += lin_b[col + 1];
                if (wr) *(float2*)&orow[col] = make_float2(v0, v1);
                if (v0 > bvv) { bvv = v0; bii = col; }
                if (v1 > bvv) { bvv = v1; bii = col + 1; }
            }
#pragma unroll
            for (int off = 1; off < 4; off <<= 1) {
                float ov = __shfl_xor_sync(0xffffffffu, bvv, off, 4);
                int   oi = __shfl_xor_sync(0xffffffffu, bii, off, 4);
                if (ov > bvv || (ov == bvv && oi < bii)) { bvv = ov; bii = oi; }
            }
            if (tig == 0) {
                int slot = bx * 4 + wn;
                g_pval[(size_t)gm * 256 + slot] = bvv;
                g_pidx[(size_t)gm * 256 + slot] = bii;
            }
        }
    }
}

// grid (64, 2, 2) = 256 CTAs, occ 2.
__global__ __launch_bounds__(256, 2)
void k_logits(const float* __restrict__ lin_W,
              const float* __restrict__ lin_b,
              const int*   __restrict__ seq_lens,
              float* __restrict__ out,
              int t) {
    const int nbt = g_nb[t];
    const bool split = (nbt <= 128);
    const int bx = blockIdx.x, by = blockIdx.y, bz = blockIdx.z;
    int bm, kbeg, nch, own, slot0, nop, cidx, cthr, fi;
    if (!split) {
        bm = bz * 128; kbeg = by * (HH / 2); nch = (HH / 2) / BK;  // 32
        own = bz * 2 + by; slot0 = bz * 2; nop = 2;
        cidx = bx * 2 + bz; cthr = 2; fi = bz;
    } else {
        int q = by * 2 + bz;
        bm = 0; kbeg = q * (HH / 4); nch = (HH / 4) / BK;          // 16
        own = q; slot0 = 0; nop = 4;
        cidx = bx; cthr = 4; fi = 0;
    }
    const int bn = bx * 128;

    extern __shared__ float S[];
    const int tid = threadIdx.x;
    const int wid = tid >> 5;
    const int wm  = wid >> 2, wn = wid & 3;
    const int g   = (tid & 31) >> 2, tig = tid & 3;
    const int kq  = tid & 3;

    const float* pa[2];
    const float* pb[2];
#pragma unroll
    for (int j = 0; j < 2; j++) {
        int row = ((j * 256 + tid) >> 2);
        pa[j] = g_h + (size_t)(bm + row) * HH + kbeg;
        pb[j] = lin_W + (size_t)(bn + row) * HH + kbeg;
    }

    float acc[4][4][4];
    ACC_ZERO(acc)
    float4 av[2], bv[2];
#define LG(ch)                                                    \
    { int kkb = (ch) * BK + kq * 4;                               \
      _Pragma("unroll")                                           \
      for (int j = 0; j < 2; j++) {                               \
          av[j] = *(const float4*)(pa[j] + kkb);                  \
          bv[j] = *(const float4*)(pb[j] + kkb); } }
    GEMM_PIPELINE(S, nch, LG)
#undef LG

    // store my partial
#pragma unroll
    for (int half = 0; half < 2; half++)
#pragma unroll
        for (int mt = 0; mt < 4; mt++) {
            int lr = wm * 64 + mt * 16 + g + half * 8;
#pragma unroll
            for (int nt = 0; nt < 4; nt++) {
                int col = bn + wn * 32 + nt * 8 + 2 * tig;
                *(float2*)&g_logP[own][lr][col] =
                    make_float2(acc[mt][nt][half * 2], acc[mt][nt][half * 2 + 1]);
            }
        }
    __syncthreads();
    __shared__ int swin;
    if (tid == 0) {
        __threadfence();
        int old = atomicAdd(&g_lcnt[cidx], 1);
        swin = (old == cthr - 1);
        if (old == cthr - 1) g_lcnt[cidx] = 0;
    }
    __syncthreads();
    if (!swin) return;
    __threadfence();
    logits_out(acc, own, slot0, nop, lin_b, seq_lens, out, t,
               bm, bn, wm, wn, g, tig, bx);

    // ---- fused final argmax: 64 winners per m-tile ----
    __syncthreads();
    __shared__ int lastf;
    if (tid == 0) {
        __threadfence();
        int old = atomicAdd(&g_fcnt[fi], 1);
        lastf = (old == 63);
        if (old == 63) g_fcnt[fi] = 0;
    }
    __syncthreads();
    if (!lastf) return;
    __threadfence();

    {
        int wv = tid >> 5, lane = tid & 31;
#pragma unroll 1
        for (int i = 0; i < 16; i++) {
            int b = bm + wv * 16 + i;
            float v = -3.4e38f;
            int   bi = 0x7fffffff;
            for (int s = lane; s < 256; s += 32) {
                float pv = __ldcg(&g_pval[(size_t)b * 256 + s]);
                int   pi = __ldcg(&g_pidx[(size_t)b * 256 + s]);
                if (pv > v || (pv == v && pi < bi)) { v = pv; bi = pi; }
            }
#pragma unroll
            for (int off = 16; off; off >>= 1) {
                float ov = __shfl_xor_sync(0xffffffffu, v, off);
                int   oi = __shfl_xor_sync(0xffffffffu, bi, off);
                if (ov > v || (ov == v && oi < bi)) { v = ov; bi = oi; }
            }
            if (lane == 0) g_amax[b] = bi;
        }
    }
}

// ---------------- launch ------------------------------------------------------
extern "C" void kernel_launch(void* const* d_in, const int* in_sizes, int n_in,
                              void* d_out, int out_size) {
    const float* enc      = (const float*)d_in[0];
    const float* emb      = (const float*)d_in[1];
    const float* init_t   = (const float*)d_in[2];
    const float* W_ih     = (const float*)d_in[3];
    const float* W_hh     = (const float*)d_in[4];
    const float* b_ih     = (const float*)d_in[5];
    const float* b_hh     = (const float*)d_in[6];
    const float* lin_W    = (const float*)d_in[7];
    const float* lin_b    = (const float*)d_in[8];
    const int*   seq_lens = (const int*)d_in[9];
    float*       out      = (float*)d_out;

    cudaFuncSetAttribute(kA_x,     cudaFuncAttributeMaxDynamicSharedMemorySize, SMEM_B);
    cudaFuncSetAttribute(kA_e,     cudaFuncAttributeMaxDynamicSharedMemorySize, SMEM_B);
    cudaFuncSetAttribute(k_gates,  cudaFuncAttributeMaxDynamicSharedMemorySize, SMEM_B);
    cudaFuncSetAttribute(k_logits, cudaFuncAttributeMaxDynamicSharedMemorySize, SMEM_B);

    k_init<<<(BB * HH + 255) / 256, 256>>>();
    k_scan<<<1, 256>>>(seq_lens);
    k_I0<<<FOURH / 256, 256>>>(init_t, W_ih);
    kA_e<<<dim3(32, VV / 128), 256, SMEM_B>>>(emb, W_ih);
    kA_x<<<dim3(32, (BB * TT) / 128), 256, SMEM_B>>>(enc, W_ih);

    for (int t = 0; t < TT; t++) {
        k_gates<<<dim3(32, 4, 2), 256, SMEM_B>>>(W_hh, t);
        k_cell<<<(BB * HH + 255) / 256, 256>>>(b_ih, b_hh, seq_lens, t);
        k_logits<<<dim3(64, 2, 2), 256, SMEM_B>>>(lin_W, lin_b, seq_lens, out, t);
    }
}

// round 11
// speedup vs baseline: 1.6204x; 1.0331x over previous
#include <cuda_runtime.h>
#include <cstdint>
#include <cstddef>

// Problem dims (fixed)
#define BB    256
#define TT    64
#define DIN   1024
#define HH    1024
#define EE    256
#define VV    8192
#define FOURH 4096
#define BK    16
#define SR    20              // smem row stride (floats); 80B rows -> LDSM conflict-free
#define MSL   (128 * SR)
#define STAGE_F (4 * MSL)     // floats per pipeline stage
#define SMEM_B  (2 * STAGE_F * 4)   // dynamic smem bytes (81920)

// ---------------- scratch ----------------------------------------------------
__device__ float g_h[BB * HH];
__device__ float g_c[BB * HH];
__device__ float g_XW[BB * TT * FOURH];   // packed x_t @ W_ih_x^T
__device__ float g_EW[VV * FOURH];        // emb @ W_ih_e^T
__device__ float g_I0[FOURH];             // init_tensor @ W_ih_e^T
__device__ int   g_amax[BB];
__device__ float g_P[8][128][FOURH];      // gates partials (8-way max)
__device__ float g_logP[4][128][VV];      // logits split-K partials (4-way max)
__device__ int   g_lcnt[128];             // combine counters (zero-init)
__device__ int   g_fcnt[2];
__device__ float g_pval[BB * 256];
__device__ int   g_pidx[BB * 256];
__device__ int   g_off[BB];
__device__ int   g_nb[TT];
__device__ int   g_nrows;
__device__ int   g_rbt[BB * TT];          // packed row -> (b<<6)|t

// ---------------- helpers -----------------------------------------------------
__device__ __forceinline__ float tf32r(float x) {
    uint32_t u;
    asm("cvt.rna.tf32.f32 %0, %1;" : "=r"(u) : "f"(x));
    return __uint_as_float(u);
}
__device__ __forceinline__ void split4(float4 v, float4& h, float4& l) {
    h.x = tf32r(v.x); h.y = tf32r(v.y); h.z = tf32r(v.z); h.w = tf32r(v.w);
    l.x = tf32r(v.x - h.x); l.y = tf32r(v.y - h.y);
    l.z = tf32r(v.z - h.z); l.w = tf32r(v.w - h.w);
}
__device__ __forceinline__ void mma8(float* c, const uint32_t* a, const uint32_t* b) {
    asm volatile(
        "mma.sync.aligned.m16n8k8.row.col.f32.tf32.tf32.f32 "
        "{%0,%1,%2,%3}, {%4,%5,%6,%7}, {%8,%9}, {%0,%1,%2,%3};"
        : "+f"(c[0]), "+f"(c[1]), "+f"(c[2]), "+f"(c[3])
        : "r"(a[0]), "r"(a[1]), "r"(a[2]), "r"(a[3]), "r"(b[0]), "r"(b[1]));
}
__device__ __forceinline__ void ldsm4(uint32_t* r, uint32_t addr) {
    asm volatile("ldmatrix.sync.aligned.m8n8.x4.shared.b16 {%0,%1,%2,%3}, [%4];"
        : "=r"(r[0]), "=r"(r[1]), "=r"(r[2]), "=r"(r[3]) : "r"(addr));
}
__device__ __forceinline__ void ldsm2(uint32_t* r, uint32_t addr) {
    asm volatile("ldmatrix.sync.aligned.m8n8.x2.shared.b16 {%0,%1}, [%2];"
        : "=r"(r[0]), "=r"(r[1]) : "r"(addr));
}
__device__ __forceinline__ float sigm(float x) { return 1.0f / (1.0f + expf(-x)); }

__device__ __forceinline__ void sts_split(float* S, int tid,
                                          const float4* av, const float4* bv) {
    float* AHI = S;
    float* ALO = S + MSL;
    float* BHI = S + 2 * MSL;
    float* BLO = S + 3 * MSL;
#pragma unroll
    for (int j = 0; j < 2; j++) {
        int idx = j * 256 + tid;
        int row = idx >> 2, kq = idx & 3;
        int o = row * SR + kq * 4;
        float4 h, l;
        split4(av[j], h, l);
        *(float4*)&AHI[o] = h; *(float4*)&ALO[o] = l;
        split4(bv[j], h, l);
        *(float4*)&BHI[o] = h; *(float4*)&BLO[o] = l;
    }
}

// 3-pass fragment compute using ldmatrix (b16 tiles == tf32 fragments).
// aoff/boff are per-thread byte offsets (lane-dependent) within a stage.
__device__ __forceinline__ void mma_block(uint32_t sbase, uint32_t aoff, uint32_t boff,
                                          float acc[4][4][4]) {
    const uint32_t aHi = sbase + aoff;
    const uint32_t bHi = sbase + 2u * (MSL * 4u) + boff;
#pragma unroll
    for (int ks = 0; ks < 2; ks++) {
        uint32_t ka = aHi + ks * 32u;   // +8 floats per ks
        uint32_t kb = bHi + ks * 32u;
        uint32_t af[4][4], bf[4][2];
        // pass 1: ah * bh
#pragma unroll
        for (int m = 0; m < 4; m++) ldsm4(af[m], ka + m * (16u * SR * 4u));
#pragma unroll
        for (int n = 0; n < 4; n++) ldsm2(bf[n], kb + n * (8u * SR * 4u));
#pragma unroll
        for (int m = 0; m < 4; m++)
#pragma unroll
            for (int n = 0; n < 4; n++) mma8(acc[m][n], af[m], bf[n]);
        // pass 2: ah * bl
#pragma unroll
        for (int n = 0; n < 4; n++) ldsm2(bf[n], kb + (MSL * 4u) + n * (8u * SR * 4u));
#pragma unroll
        for (int m = 0; m < 4; m++)
#pragma unroll
            for (int n = 0; n < 4; n++) mma8(acc[m][n], af[m], bf[n]);
        // pass 3: al * bh
#pragma unroll
        for (int m = 0; m < 4; m++) ldsm4(af[m], ka + (MSL * 4u) + m * (16u * SR * 4u));
#pragma unroll
        for (int n = 0; n < 4; n++) ldsm2(bf[n], kb + n * (8u * SR * 4u));
#pragma unroll
        for (int m = 0; m < 4; m++)
#pragma unroll
            for (int n = 0; n < 4; n++) mma8(acc[m][n], af[m], bf[n]);
    }
}

#define ACC_ZERO(acc)                                   \
    _Pragma("unroll")                                   \
    for (int a_ = 0; a_ < 4; a_++)                      \
        _Pragma("unroll")                               \
        for (int b_ = 0; b_ < 4; b_++)                  \
            _Pragma("unroll")                           \
            for (int c_ = 0; c_ < 4; c_++) acc[a_][b_][c_] = 0.0f;

// Per-thread ldmatrix address offsets (bytes) within a stage.
// A x4: lanes<16 -> row (wm*64 + L), col 0; lanes>=16 -> row (L-16), col +4.
// B x2: Lb=L&15: row (wn*32 + (Lb&7)), col (Lb>>3)*4.
#define LDSM_OFFSETS()                                                        \
    const int L_ = tid & 31;                                                  \
    const uint32_t aoff = ((uint32_t)((L_ & 15) + wm * 64) * SR) * 4u +       \
                          (uint32_t)(L_ >> 4) * 16u;                          \
    const uint32_t boff = ((uint32_t)(((L_ & 15) & 7) + wn * 32) * SR) * 4u + \
                          (uint32_t)(((L_ & 15) >> 3) & 1) * 16u;

// Double-buffered mainloop: 1 sync per chunk, STS overlapped with MMA.
#define GEMM_PIPELINE(S, sb, nch, LOADG)                      \
    LOADG(0);                                                 \
    sts_split(S, tid, av, bv);                                \
    __syncthreads();                                          \
    for (int i = 0; i < (nch); i++) {                         \
        bool more_ = (i + 1 < (nch));                         \
        if (more_) LOADG(i + 1);                              \
        mma_block((sb) + (uint32_t)(i & 1) * (STAGE_F * 4u), aoff, boff, acc); \
        if (more_) sts_split((S) + ((i + 1) & 1) * STAGE_F, tid, av, bv); \
        __syncthreads();                                      \
    }

// ---------------- init / scan -------------------------------------------------
__global__ void k_init() {
    int idx = blockIdx.x * 256 + threadIdx.x;
    if (idx < BB * HH) { g_h[idx] = 0.0f; g_c[idx] = 0.0f; }
}
__global__ void k_scan(const int* __restrict__ seq_lens) {
    int tid = threadIdx.x;   // 256
    if (tid == 0) {
        int acc = 0;
        for (int b = 0; b < BB; b++) { g_off[b] = acc; acc += seq_lens[b]; }
        g_nrows = acc;
    }
    if (tid < TT) {
        int c = 0;
        for (int b = 0; b < BB; b++) c += (seq_lens[b] > tid) ? 1 : 0;
        g_nb[tid] = c;
    }
    __syncthreads();
    {
        int b = tid;
        int o = g_off[b], len = seq_lens[b];
        for (int t = 0; t < len; t++) g_rbt[o + t] = (b << 6) | t;
    }
}
__global__ void k_I0(const float* __restrict__ init_t,
                     const float* __restrict__ W_ih) {
    int j = blockIdx.x * 256 + threadIdx.x;   // 4096
    const float* w = W_ih + (size_t)j * (DIN + EE) + DIN;
    float s = 0.0f;
    for (int e = 0; e < EE; e++) s += init_t[e] * w[e];
    g_I0[j] = s;
}

// ================= Phase A1: XW = x_t @ W_ih_x^T (packed rows) ================
__global__ __launch_bounds__(256, 2)
void kA_x(const float* __restrict__ enc, const float* __restrict__ W_ih) {
    const int bm = blockIdx.y * 128;
    if (bm >= g_nrows) return;
    const int bn = blockIdx.x * 128;

    extern __shared__ float S[];
    const uint32_t sb = (uint32_t)__cvta_generic_to_shared(S);
    const int tid = threadIdx.x;
    const int wid = tid >> 5;
    const int wm  = wid >> 2, wn = wid & 3;
    const int g   = (tid & 31) >> 2, tig = tid & 3;
    const int kq  = tid & 3;
    LDSM_OFFSETS()

    const float* pa[2];
    const float* pb[2];
#pragma unroll
    for (int j = 0; j < 2; j++) {
        int row = ((j * 256 + tid) >> 2);
        int bt = g_rbt[bm + row];
        int b = bt >> 6, t = bt & 63;
        pa[j] = enc + ((size_t)b * TT + t) * DIN;
        pb[j] = W_ih + (size_t)(bn + row) * (DIN + EE);
    }

    float acc[4][4][4];
    ACC_ZERO(acc)
    float4 av[2], bv[2];
#define LG(ch)                                                    \
    { int kkb = (ch) * BK + kq * 4;                               \
      _Pragma("unroll")                                           \
      for (int j = 0; j < 2; j++) {                               \
          av[j] = *(const float4*)(pa[j] + kkb);                  \
          bv[j] = *(const float4*)(pb[j] + kkb); } }
    GEMM_PIPELINE(S, sb, DIN / BK, LG)
#undef LG
#pragma unroll
    for (int m = 0; m < 4; m++) {
        int lr0 = wm * 64 + m * 16 + g, lr1 = lr0 + 8;
#pragma unroll
        for (int n = 0; n < 4; n++) {
            int col = bn + wn * 32 + n * 8 + 2 * tig;
            *(float2*)&g_XW[(size_t)(bm + lr0) * FOURH + col] =
                make_float2(acc[m][n][0], acc[m][n][1]);
            *(float2*)&g_XW[(size_t)(bm + lr1) * FOURH + col] =
                make_float2(acc[m][n][2], acc[m][n][3]);
        }
    }
}

// ================= Phase A2: EW = emb @ W_ih_e^T ==============================
__global__ __launch_bounds__(256, 2)
void kA_e(const float* __restrict__ emb, const float* __restrict__ W_ih) {
    const int bm = blockIdx.y * 128;
    const int bn = blockIdx.x * 128;

    extern __shared__ float S[];
    const uint32_t sb = (uint32_t)__cvta_generic_to_shared(S);
    const int tid = threadIdx.x;
    const int wid = tid >> 5;
    const int wm  = wid >> 2, wn = wid & 3;
    const int g   = (tid & 31) >> 2, tig = tid & 3;
    const int kq  = tid & 3;
    LDSM_OFFSETS()

    const float* pa[2];
    const float* pb[2];
#pragma unroll
    for (int j = 0; j < 2; j++) {
        int row = ((j * 256 + tid) >> 2);
        pa[j] = emb + (size_t)(bm + row) * EE;
        pb[j] = W_ih + (size_t)(bn + row) * (DIN + EE) + DIN;
    }

    float acc[4][4][4];
    ACC_ZERO(acc)
    float4 av[2], bv[2];
#define LG(ch)                                                    \
    { int kkb = (ch) * BK + kq * 4;                               \
      _Pragma("unroll")                                           \
      for (int j = 0; j < 2; j++) {                               \
          av[j] = *(const float4*)(pa[j] + kkb);                  \
          bv[j] = *(const float4*)(pb[j] + kkb); } }
    GEMM_PIPELINE(S, sb, EE / BK, LG)
#undef LG
#pragma unroll
    for (int m = 0; m < 4; m++) {
        int lr0 = wm * 64 + m * 16 + g, lr1 = lr0 + 8;
#pragma unroll
        for (int n = 0; n < 4; n++) {
            int col = bn + wn * 32 + n * 8 + 2 * tig;
            *(float2*)&g_EW[(size_t)(bm + lr0) * FOURH + col] =
                make_float2(acc[m][n][0], acc[m][n][1]);
            *(float2*)&g_EW[(size_t)(bm + lr1) * FOURH + col] =
                make_float2(acc[m][n][2], acc[m][n][3]);
        }
    }
}

// ================= GEMM 1 (in-loop): h @ W_hh^T ===============================
// grid (32, 4, 2) = 256 CTAs, occ 2.
__global__ __launch_bounds__(256, 2)
void k_gates(const float* __restrict__ W_hh, int t) {
    const int nbt = g_nb[t];
    int bm, kbeg, nch, slot;
    if (nbt > 128) {
        bm = blockIdx.z * 128;
        kbeg = blockIdx.y * (HH / 4);
        nch = (HH / 4) / BK;   // 16
        slot = blockIdx.z * 4 + blockIdx.y;
    } else {
        bm = 0;
        int ks = blockIdx.y * 2 + blockIdx.z;
        kbeg = ks * (HH / 8);
        nch = (HH / 8) / BK;   // 8
        slot = ks;
    }
    const int bn = blockIdx.x * 128;

    extern __shared__ float S[];
    const uint32_t sb = (uint32_t)__cvta_generic_to_shared(S);
    const int tid = threadIdx.x;
    const int wid = tid >> 5;
    const int wm  = wid >> 2, wn = wid & 3;
    const int g   = (tid & 31) >> 2, tig = tid & 3;
    const int kq  = tid & 3;
    LDSM_OFFSETS()

    const float* pa[2];
    const float* pb[2];
#pragma unroll
    for (int j = 0; j < 2; j++) {
        int row = ((j * 256 + tid) >> 2);
        pa[j] = g_h + (size_t)(bm + row) * HH + kbeg;
        pb[j] = W_hh + (size_t)(bn + row) * HH + kbeg;
    }

    float acc[4][4][4];
    ACC_ZERO(acc)
    float4 av[2], bv[2];
#define LG(ch)                                                    \
    { int kkb = (ch) * BK + kq * 4;                               \
      _Pragma("unroll")                                           \
      for (int j = 0; j < 2; j++) {                               \
          av[j] = *(const float4*)(pa[j] + kkb);                  \
          bv[j] = *(const float4*)(pb[j] + kkb); } }
    GEMM_PIPELINE(S, sb, nch, LG)
#undef LG
#pragma unroll
    for (int m = 0; m < 4; m++) {
        int lr0 = wm * 64 + m * 16 + g, lr1 = lr0 + 8;
#pragma unroll
        for (int n = 0; n < 4; n++) {
            int col = bn + wn * 32 + n * 8 + 2 * tig;
            *(float2*)&g_P[slot][lr0][col] = make_float2(acc[m][n][0], acc[m][n][1]);
            *(float2*)&g_P[slot][lr1][col] = make_float2(acc[m][n][2], acc[m][n][3]);
        }
    }
}

// ---------------- LSTM cell (4/8-way partial gather, fixed trees) -------------
__global__ void k_cell(const float* __restrict__ b_ih,
                       const float* __restrict__ b_hh,
                       const int* __restrict__ seq_lens,
                       int t) {
    int idx = blockIdx.x * 256 + threadIdx.x;
    int b = idx >> 10, j = idx & 1023;
    int nbt = g_nb[t];
    if (nbt <= 128 && b >= 128) return;
    if (t >= seq_lens[b]) return;

    float gate[4];
#pragma unroll
    for (int q = 0; q < 4; q++) {
        int jj = q * 1024 + j;
        float v;
        if (nbt > 128) {
            int s0 = (b >> 7) * 4, lr = b & 127;
            v = (g_P[s0][lr][jj] + g_P[s0 + 1][lr][jj]) +
                (g_P[s0 + 2][lr][jj] + g_P[s0 + 3][lr][jj]);
        } else {
            v = ((g_P[0][b][jj] + g_P[1][b][jj]) + (g_P[2][b][jj] + g_P[3][b][jj])) +
                ((g_P[4][b][jj] + g_P[5][b][jj]) + (g_P[6][b][jj] + g_P[7][b][jj]));
        }
        gate[q] = v;
    }
    const float* XW = g_XW + (size_t)(g_off[b] + t) * FOURH;
    const float* EW = (t == 0) ? g_I0 : g_EW + (size_t)g_amax[b] * FOURH;
    float i_ = gate[0] + XW[j]        + EW[j]        + b_ih[j]        + b_hh[j];
    float f_ = gate[1] + XW[1024 + j] + EW[1024 + j] + b_ih[1024 + j] + b_hh[1024 + j];
    float gg = gate[2] + XW[2048 + j] + EW[2048 + j] + b_ih[2048 + j] + b_hh[2048 + j];
    float o_ = gate[3] + XW[3072 + j] + EW[3072 + j] + b_ih[3072 + j] + b_hh[3072 + j];
    float c = sigm(f_) * g_c[idx] + sigm(i_) * tanhf(gg);
    float h = sigm(o_) * tanhf(c);
    g_c[idx] = c;
    g_h[idx] = h;
}

// ================= GEMM 2: logits (split-K) + fused argmax ====================
__device__ __forceinline__ void logits_out(
    float acc[4][4][4], int own, int slot0, int nop,
    const float* __restrict__ lin_b, const int* __restrict__ seq_lens,
    float* __restrict__ out, int t,
    int bm, int bn, int wm, int wn, int g, int tig, int bx) {
#pragma unroll
    for (int half = 0; half < 2; half++) {
#pragma unroll
        for (int mt = 0; mt < 4; mt++) {
            int lr = wm * 64 + mt * 16 + g + half * 8;
            int gm = bm + lr;
            int len = seq_lens[gm];
            bool wr = (t < len);
            float* orow = out + (size_t)(g_off[gm] + t) * VV;

            float bvv = -3.4e38f;
            int   bii = 0;
#pragma unroll
            for (int nt = 0; nt < 4; nt++) {
                int col = bn + wn * 32 + nt * 8 + 2 * tig;
                float a0 = acc[mt][nt][half * 2 + 0];
                float a1 = acc[mt][nt][half * 2 + 1];
                float v0, v1;
                if (nop == 2) {
                    int oth = (own == slot0) ? slot0 + 1 : slot0;
                    v0 = a0 + __ldcg(&g_logP[oth][lr][col]);
                    v1 = a1 + __ldcg(&g_logP[oth][lr][col + 1]);
                } else {
                    float x0 = (own == 0) ? a0 : __ldcg(&g_logP[0][lr][col]);
                    float x1 = (own == 1) ? a0 : __ldcg(&g_logP[1][lr][col]);
                    float x2 = (own == 2) ? a0 : __ldcg(&g_logP[2][lr][col]);
                    float x3 = (own == 3) ? a0 : __ldcg(&g_logP[3][lr][col]);
                    v0 = (x0 + x1) + (x2 + x3);
                    float y0 = (own == 0) ? a1 : __ldcg(&g_logP[0][lr][col + 1]);
                    float y1 = (own == 1) ? a1 : __ldcg(&g_logP[1][lr][col + 1]);
                    float y2 = (own == 2) ? a1 : __ldcg(&g_logP[2][lr][col + 1]);
                    float y3 = (own == 3) ? a1 : __ldcg(&g_logP[3][lr][col + 1]);
                    v1 = (y0 + y1) + (y2 + y3);
                }
                v0 += lin_b[col];
                v1 += lin_b[col + 1];
                if (wr) *(float2*)&orow[col] = make_float2(v0, v1);
                if (v0 > bvv) { bvv = v0; bii = col; }
                if (v1 > bvv) { bvv = v1; bii = col + 1; }
            }
#pragma unroll
            for (int off = 1; off < 4; off <<= 1) {
                float ov = __shfl_xor_sync(0xffffffffu, bvv, off, 4);
                int   oi = __shfl_xor_sync(0xffffffffu, bii, off, 4);
                if (ov > bvv || (ov == bvv && oi < bii)) { bvv = ov; bii = oi; }
            }
            if (tig == 0) {
                int slot = bx * 4 + wn;
                g_pval[(size_t)gm * 256 + slot] = bvv;
                g_pidx[(size_t)gm * 256 + slot] = bii;
            }
        }
    }
}

// grid (64, 2, 2) = 256 CTAs, occ 2.
__global__ __launch_bounds__(256, 2)
void k_logits(const float* __restrict__ lin_W,
              const float* __restrict__ lin_b,
              const int*   __restrict__ seq_lens,
              float* __restrict__ out,
              int t) {
    const int nbt = g_nb[t];
    const bool split = (nbt <= 128);
    const int bx = blockIdx.x, by = blockIdx.y, bz = blockIdx.z;
    int bm, kbeg, nch, own, slot0, nop, cidx, cthr, fi;
    if (!split) {
        bm = bz * 128; kbeg = by * (HH / 2); nch = (HH / 2) / BK;  // 32
        own = bz * 2 + by; slot0 = bz * 2; nop = 2;
        cidx = bx * 2 + bz; cthr = 2; fi = bz;
    } else {
        int q = by * 2 + bz;
        bm = 0; kbeg = q * (HH / 4); nch = (HH / 4) / BK;          // 16
        own = q; slot0 = 0; nop = 4;
        cidx = bx; cthr = 4; fi = 0;
    }
    const int bn = bx * 128;

    extern __shared__ float S[];
    const uint32_t sb = (uint32_t)__cvta_generic_to_shared(S);
    const int tid = threadIdx.x;
    const int wid = tid >> 5;
    const int wm  = wid >> 2, wn = wid & 3;
    const int g   = (tid & 31) >> 2, tig = tid & 3;
    const int kq  = tid & 3;
    LDSM_OFFSETS()

    const float* pa[2];
    const float* pb[2];
#pragma unroll
    for (int j = 0; j < 2; j++) {
        int row = ((j * 256 + tid) >> 2);
        pa[j] = g_h + (size_t)(bm + row) * HH + kbeg;
        pb[j] = lin_W + (size_t)(bn + row) * HH + kbeg;
    }

    float acc[4][4][4];
    ACC_ZERO(acc)
    float4 av[2], bv[2];
#define LG(ch)                                                    \
    { int kkb = (ch) * BK + kq * 4;                               \
      _Pragma("unroll")                                           \
      for (int j = 0; j < 2; j++) {                               \
          av[j] = *(const float4*)(pa[j] + kkb);                  \
          bv[j] = *(const float4*)(pb[j] + kkb); } }
    GEMM_PIPELINE(S, sb, nch, LG)
#undef LG

    // store my partial
#pragma unroll
    for (int half = 0; half < 2; half++)
#pragma unroll
        for (int mt = 0; mt < 4; mt++) {
            int lr = wm * 64 + mt * 16 + g + half * 8;
#pragma unroll
            for (int nt = 0; nt < 4; nt++) {
                int col = bn + wn * 32 + nt * 8 + 2 * tig;
                *(float2*)&g_logP[own][lr][col] =
                    make_float2(acc[mt][nt][half * 2], acc[mt][nt][half * 2 + 1]);
            }
        }
    __syncthreads();
    __shared__ int swin;
    if (tid == 0) {
        __threadfence();
        int old = atomicAdd(&g_lcnt[cidx], 1);
        swin = (old == cthr - 1);
        if (old == cthr - 1) g_lcnt[cidx] = 0;
    }
    __syncthreads();
    if (!swin) return;
    __threadfence();
    logits_out(acc, own, slot0, nop, lin_b, seq_lens, out, t,
               bm, bn, wm, wn, g, tig, bx);

    // ---- fused final argmax: 64 winners per m-tile ----
    __syncthreads();
    __shared__ int lastf;
    if (tid == 0) {
        __threadfence();
        int old = atomicAdd(&g_fcnt[fi], 1);
        lastf = (old == 63);
        if (old == 63) g_fcnt[fi] = 0;
    }
    __syncthreads();
    if (!lastf) return;
    __threadfence();

    {
        int wv = tid >> 5, lane = tid & 31;
#pragma unroll 1
        for (int i = 0; i < 16; i++) {
            int b = bm + wv * 16 + i;
            float v = -3.4e38f;
            int   bi = 0x7fffffff;
            for (int s = lane; s < 256; s += 32) {
                float pv = __ldcg(&g_pval[(size_t)b * 256 + s]);
                int   pi = __ldcg(&g_pidx[(size_t)b * 256 + s]);
                if (pv > v || (pv == v && pi < bi)) { v = pv; bi = pi; }
            }
#pragma unroll
            for (int off = 16; off; off >>= 1) {
                float ov = __shfl_xor_sync(0xffffffffu, v, off);
                int   oi = __shfl_xor_sync(0xffffffffu, bi, off);
                if (ov > v || (ov == v && oi < bi)) { v = ov; bi = oi; }
            }
            if (lane == 0) g_amax[b] = bi;
        }
    }
}

// ---------------- launch ------------------------------------------------------
extern "C" void kernel_launch(void* const* d_in, const int* in_sizes, int n_in,
                              void* d_out, int out_size) {
    const float* enc      = (const float*)d_in[0];
    const float* emb      = (const float*)d_in[1];
    const float* init_t   = (const float*)d_in[2];
    const float* W_ih     = (const float*)d_in[3];
    const float* W_hh     = (const float*)d_in[4];
    const float* b_ih     = (const float*)d_in[5];
    const float* b_hh     = (const float*)d_in[6];
    const float* lin_W    = (const float*)d_in[7];
    const float* lin_b    = (const float*)d_in[8];
    const int*   seq_lens = (const int*)d_in[9];
    float*       out      = (float*)d_out;

    cudaFuncSetAttribute(kA_x,     cudaFuncAttributeMaxDynamicSharedMemorySize, SMEM_B);
    cudaFuncSetAttribute(kA_e,     cudaFuncAttributeMaxDynamicSharedMemorySize, SMEM_B);
    cudaFuncSetAttribute(k_gates,  cudaFuncAttributeMaxDynamicSharedMemorySize, SMEM_B);
    cudaFuncSetAttribute(k_logits, cudaFuncAttributeMaxDynamicSharedMemorySize, SMEM_B);

    k_init<<<(BB * HH + 255) / 256, 256>>>();
    k_scan<<<1, 256>>>(seq_lens);
    k_I0<<<FOURH / 256, 256>>>(init_t, W_ih);
    kA_e<<<dim3(32, VV / 128), 256, SMEM_B>>>(emb, W_ih);
    kA_x<<<dim3(32, (BB * TT) / 128), 256, SMEM_B>>>(enc, W_ih);

    for (int t = 0; t < TT; t++) {
        k_gates<<<dim3(32, 4, 2), 256, SMEM_B>>>(W_hh, t);
        k_cell<<<(BB * HH + 255) / 256, 256>>>(b_ih, b_hh, seq_lens, t);
        k_logits<<<dim3(64, 2, 2), 256, SMEM_B>>>(lin_W, lin_b, seq_lens, out, t);
    }
}

// round 13
// speedup vs baseline: 1.6771x; 1.0350x over previous
#include <cuda_runtime.h>
#include <cstdint>
#include <cstddef>

// Problem dims (fixed)
#define BB    256
#define TT    64
#define DIN   1024
#define HH    1024
#define EE    256
#define VV    8192
#define FOURH 4096
#define BK    16
#define SR    20              // smem row stride (floats); 80B rows -> LDSM conflict-free
#define MSL   (128 * SR)
#define STAGE_F (4 * MSL)     // floats per pipeline stage
#define SMEM_B  (2 * STAGE_F * 4)   // dynamic smem bytes (81920)

// ---------------- scratch ----------------------------------------------------
__device__ float g_h[BB * HH];
__device__ float g_c[BB * HH];
__device__ float g_XW[BB * TT * FOURH];   // packed x_t @ W_ih_x^T
__device__ float g_EW[VV * FOURH];        // emb @ W_ih_e^T
__device__ float g_I0[FOURH];             // init_tensor @ W_ih_e^T
__device__ int   g_amax[BB];
__device__ float g_P[8][128][FOURH];      // gates partials (8-way max)
__device__ float g_logP[4][128][VV];      // logits split-K partials (4-way max)
__device__ int   g_lcnt[128];             // combine counters (zero-init)
__device__ int   g_fcnt[2];
__device__ float g_pval[BB * 256];
__device__ int   g_pidx[BB * 256];
__device__ int   g_off[BB];
__device__ int   g_nb[TT];
__device__ int   g_nrows;
__device__ int   g_rbt[BB * TT];          // packed row -> (b<<6)|t

// ---------------- helpers -----------------------------------------------------
__device__ __forceinline__ float tf32r(float x) {
    uint32_t u;
    asm("cvt.rna.tf32.f32 %0, %1;" : "=r"(u) : "f"(x));
    return __uint_as_float(u);
}
__device__ __forceinline__ void split4(float4 v, float4& h, float4& l) {
    h.x = tf32r(v.x); h.y = tf32r(v.y); h.z = tf32r(v.z); h.w = tf32r(v.w);
    l.x = tf32r(v.x - h.x); l.y = tf32r(v.y - h.y);
    l.z = tf32r(v.z - h.z); l.w = tf32r(v.w - h.w);
}
__device__ __forceinline__ void mma8(float* c, const uint32_t* a, const uint32_t* b) {
    asm volatile(
        "mma.sync.aligned.m16n8k8.row.col.f32.tf32.tf32.f32 "
        "{%0,%1,%2,%3}, {%4,%5,%6,%7}, {%8,%9}, {%0,%1,%2,%3};"
        : "+f"(c[0]), "+f"(c[1]), "+f"(c[2]), "+f"(c[3])
        : "r"(a[0]), "r"(a[1]), "r"(a[2]), "r"(a[3]), "r"(b[0]), "r"(b[1]));
}
__device__ __forceinline__ void ldsm4(uint32_t* r, uint32_t addr) {
    asm volatile("ldmatrix.sync.aligned.m8n8.x4.shared.b16 {%0,%1,%2,%3}, [%4];"
        : "=r"(r[0]), "=r"(r[1]), "=r"(r[2]), "=r"(r[3]) : "r"(addr));
}
__device__ __forceinline__ float sigm(float x) { return 1.0f / (1.0f + expf(-x)); }

__device__ __forceinline__ void sts_split(float* S, int tid,
                                          const float4* av, const float4* bv) {
    float* AHI = S;
    float* ALO = S + MSL;
    float* BHI = S + 2 * MSL;
    float* BLO = S + 3 * MSL;
#pragma unroll
    for (int j = 0; j < 2; j++) {
        int idx = j * 256 + tid;
        int row = idx >> 2, kq = idx & 3;
        int o = row * SR + kq * 4;
        float4 h, l;
        split4(av[j], h, l);
        *(float4*)&AHI[o] = h; *(float4*)&ALO[o] = l;
        split4(bv[j], h, l);
        *(float4*)&BHI[o] = h; *(float4*)&BLO[o] = l;
    }
}

// 3-pass fragment compute; A via ldsm.x4, B via PAIRED ldsm.x4 (2 n-groups/ld).
__device__ __forceinline__ void mma_block(uint32_t sbase, uint32_t aoff, uint32_t boff,
                                          float acc[4][4][4]) {
    const uint32_t aHi = sbase + aoff;
    const uint32_t bHi = sbase + 2u * (MSL * 4u) + boff;
#pragma unroll
    for (int ks = 0; ks < 2; ks++) {
        uint32_t ka = aHi + ks * 32u;   // +8 floats per ks
        uint32_t kb = bHi + ks * 32u;
        uint32_t af[4][4], bf[4][2];
        // pass 1: ah * bh
#pragma unroll
        for (int m = 0; m < 4; m++) ldsm4(af[m], ka + m * (16u * SR * 4u));
#pragma unroll
        for (int np = 0; np < 2; np++) ldsm4(bf[2 * np], kb + np * (16u * SR * 4u));
#pragma unroll
        for (int m = 0; m < 4; m++)
#pragma unroll
            for (int n = 0; n < 4; n++) mma8(acc[m][n], af[m], bf[n]);
        // pass 2: ah * bl
#pragma unroll
        for (int np = 0; np < 2; np++)
            ldsm4(bf[2 * np], kb + (MSL * 4u) + np * (16u * SR * 4u));
#pragma unroll
        for (int m = 0; m < 4; m++)
#pragma unroll
            for (int n = 0; n < 4; n++) mma8(acc[m][n], af[m], bf[n]);
        // pass 3: al * bh
#pragma unroll
        for (int m = 0; m < 4; m++) ldsm4(af[m], ka + (MSL * 4u) + m * (16u * SR * 4u));
#pragma unroll
        for (int np = 0; np < 2; np++) ldsm4(bf[2 * np], kb + np * (16u * SR * 4u));
#pragma unroll
        for (int m = 0; m < 4; m++)
#pragma unroll
            for (int n = 0; n < 4; n++) mma8(acc[m][n], af[m], bf[n]);
    }
}

#define ACC_ZERO(acc)                                   \
    _Pragma("unroll")                                   \
    for (int a_ = 0; a_ < 4; a_++)                      \
        _Pragma("unroll")                               \
        for (int b_ = 0; b_ < 4; b_++)                  \
            _Pragma("unroll")                           \
            for (int c_ = 0; c_ < 4; c_++) acc[a_][b_][c_] = 0.0f;

// Per-thread ldmatrix address offsets (bytes) within a stage.
#define LDSM_OFFSETS()                                                        \
    const int L_ = tid & 31;                                                  \
    const uint32_t aoff = ((uint32_t)((L_ & 15) + wm * 64) * SR) * 4u +       \
                          (uint32_t)(L_ >> 4) * 16u;                          \
    const uint32_t boff = ((uint32_t)((((L_ >> 4) & 1) * 8) + (L_ & 7) + wn * 32) * SR) * 4u + \
                          (uint32_t)((L_ >> 3) & 1) * 16u;

// Double-buffered mainloop: 1 sync per chunk, STS overlapped with MMA.
#define GEMM_PIPELINE(S, sb, nch, LOADG)                      \
    LOADG(0);                                                 \
    sts_split(S, tid, av, bv);                                \
    __syncthreads();                                          \
    for (int i = 0; i < (nch); i++) {                         \
        bool more_ = (i + 1 < (nch));                         \
        if (more_) LOADG(i + 1);                              \
        mma_block((sb) + (uint32_t)(i & 1) * (STAGE_F * 4u), aoff, boff, acc); \
        if (more_) sts_split((S) + ((i + 1) & 1) * STAGE_F, tid, av, bv); \
        __syncthreads();                                      \
    }

// ---------------- init / scan -------------------------------------------------
__global__ void k_init() {
    int idx = blockIdx.x * 256 + threadIdx.x;
    if (idx < BB * HH) { g_h[idx] = 0.0f; g_c[idx] = 0.0f; }
}
__global__ void k_scan(const int* __restrict__ seq_lens) {
    int tid = threadIdx.x;   // 256
    if (tid == 0) {
        int acc = 0;
        for (int b = 0; b < BB; b++) { g_off[b] = acc; acc += seq_lens[b]; }
        g_nrows = acc;
    }
    if (tid < TT) {
        int c = 0;
        for (int b = 0; b < BB; b++) c += (seq_lens[b] > tid) ? 1 : 0;
        g_nb[tid] = c;
    }
    __syncthreads();
    {
        int b = tid;
        int o = g_off[b], len = seq_lens[b];
        for (int t = 0; t < len; t++) g_rbt[o + t] = (b << 6) | t;
    }
}
__global__ void k_I0(const float* __restrict__ init_t,
                     const float* __restrict__ W_ih) {
    int j = blockIdx.x * 256 + threadIdx.x;   // 4096
    const float* w = W_ih + (size_t)j * (DIN + EE) + DIN;
    float s = 0.0f;
    for (int e = 0; e < EE; e++) s += init_t[e] * w[e];
    g_I0[j] = s;
}

// ================= Phase A1: XW = x_t @ W_ih_x^T (packed rows) ================
__global__ __launch_bounds__(256, 2)
void kA_x(const float* __restrict__ enc, const float* __restrict__ W_ih) {
    const int bm = blockIdx.y * 128;
    if (bm >= g_nrows) return;
    const int bn = blockIdx.x * 128;

    extern __shared__ float S[];
    const uint32_t sb = (uint32_t)__cvta_generic_to_shared(S);
    const int tid = threadIdx.x;
    const int wid = tid >> 5;
    const int wm  = wid >> 2, wn = wid & 3;
    const int g   = (tid & 31) >> 2, tig = tid & 3;
    const int kq  = tid & 3;
    LDSM_OFFSETS()

    const float* pa[2];
    const float* pb[2];
#pragma unroll
    for (int j = 0; j < 2; j++) {
        int row = ((j * 256 + tid) >> 2);
        int bt = g_rbt[bm + row];
        int b = bt >> 6, t = bt & 63;
        pa[j] = enc + ((size_t)b * TT + t) * DIN;
        pb[j] = W_ih + (size_t)(bn + row) * (DIN + EE);
    }

    float acc[4][4][4];
    ACC_ZERO(acc)
    float4 av[2], bv[2];
#define LG(ch)                                                    \
    { int kkb = (ch) * BK + kq * 4;                               \
      _Pragma("unroll")                                           \
      for (int j = 0; j < 2; j++) {                               \
          av[j] = *(const float4*)(pa[j] + kkb);                  \
          bv[j] = *(const float4*)(pb[j] + kkb); } }
    GEMM_PIPELINE(S, sb, DIN / BK, LG)
#undef LG
#pragma unroll
    for (int m = 0; m < 4; m++) {
        int lr0 = wm * 64 + m * 16 + g, lr1 = lr0 + 8;
#pragma unroll
        for (int n = 0; n < 4; n++) {
            int col = bn + wn * 32 + n * 8 + 2 * tig;
            *(float2*)&g_XW[(size_t)(bm + lr0) * FOURH + col] =
                make_float2(acc[m][n][0], acc[m][n][1]);
            *(float2*)&g_XW[(size_t)(bm + lr1) * FOURH + col] =
                make_float2(acc[m][n][2], acc[m][n][3]);
        }
    }
}

// ================= Phase A2: EW = emb @ W_ih_e^T ==============================
__global__ __launch_bounds__(256, 2)
void kA_e(const float* __restrict__ emb, const float* __restrict__ W_ih) {
    const int bm = blockIdx.y * 128;
    const int bn = blockIdx.x * 128;

    extern __shared__ float S[];
    const uint32_t sb = (uint32_t)__cvta_generic_to_shared(S);
    const int tid = threadIdx.x;
    const int wid = tid >> 5;
    const int wm  = wid >> 2, wn = wid & 3;
    const int g   = (tid & 31) >> 2, tig = tid & 3;
    const int kq  = tid & 3;
    LDSM_OFFSETS()

    const float* pa[2];
    const float* pb[2];
#pragma unroll
    for (int j = 0; j < 2; j++) {
        int row = ((j * 256 + tid) >> 2);
        pa[j] = emb + (size_t)(bm + row) * EE;
        pb[j] = W_ih + (size_t)(bn + row) * (DIN + EE) + DIN;
    }

    float acc[4][4][4];
    ACC_ZERO(acc)
    float4 av[2], bv[2];
#define LG(ch)                                                    \
    { int kkb = (ch) * BK + kq * 4;                               \
      _Pragma("unroll")                                           \
      for (int j = 0; j < 2; j++) {                               \
          av[j] = *(const float4*)(pa[j] + kkb);                  \
          bv[j] = *(const float4*)(pb[j] + kkb); } }
    GEMM_PIPELINE(S, sb, EE / BK, LG)
#undef LG
#pragma unroll
    for (int m = 0; m < 4; m++) {
        int lr0 = wm * 64 + m * 16 + g, lr1 = lr0 + 8;
#pragma unroll
        for (int n = 0; n < 4; n++) {
            int col = bn + wn * 32 + n * 8 + 2 * tig;
            *(float2*)&g_EW[(size_t)(bm + lr0) * FOURH + col] =
                make_float2(acc[m][n][0], acc[m][n][1]);
            *(float2*)&g_EW[(size_t)(bm + lr1) * FOURH + col] =
                make_float2(acc[m][n][2], acc[m][n][3]);
        }
    }
}

// ================= gates body: h @ W_hh^T (for step tg) =======================
__device__ __forceinline__ void gates_body(float* S, uint32_t sbda,
                                           const float* __restrict__ W_hh,
                                           int tg, int bx, int by, int bz) {
    const int nbt = g_nb[tg];
    int bm, kbeg, nch, slot;
    if (nbt > 128) {
        bm = bz * 128;
        kbeg = by * (HH / 4);
        nch = (HH / 4) / BK;   // 16
        slot = bz * 4 + by;
    } else {
        bm = 0;
        int ks = by * 2 + bz;
        kbeg = ks * (HH / 8);
        nch = (HH / 8) / BK;   // 8
        slot = ks;
    }
    const int bn = bx * 128;
    const uint32_t sb = sbda;

    const int tid = threadIdx.x;
    const int wid = tid >> 5;
    const int wm  = wid >> 2, wn = wid & 3;
    const int g   = (tid & 31) >> 2, tig = tid & 3;
    const int kq  = tid & 3;
    LDSM_OFFSETS()

    const float* pa[2];
    const float* pb[2];
#pragma unroll
    for (int j = 0; j < 2; j++) {
        int row = ((j * 256 + tid) >> 2);
        pa[j] = g_h + (size_t)(bm + row) * HH + kbeg;
        pb[j] = W_hh + (size_t)(bn + row) * HH + kbeg;
    }

    float acc[4][4][4];
    ACC_ZERO(acc)
    float4 av[2], bv[2];
#define LG(ch)                                                    \
    { int kkb = (ch) * BK + kq * 4;                               \
      _Pragma("unroll")                                           \
      for (int j = 0; j < 2; j++) {                               \
          av[j] = *(const float4*)(pa[j] + kkb);                  \
          bv[j] = *(const float4*)(pb[j] + kkb); } }
    GEMM_PIPELINE(S, sb, nch, LG)
#undef LG
#pragma unroll
    for (int m = 0; m < 4; m++) {
        int lr0 = wm * 64 + m * 16 + g, lr1 = lr0 + 8;
#pragma unroll
        for (int n = 0; n < 4; n++) {
            int col = bn + wn * 32 + n * 8 + 2 * tig;
            *(float2*)&g_P[slot][lr0][col] = make_float2(acc[m][n][0], acc[m][n][1]);
            *(float2*)&g_P[slot][lr1][col] = make_float2(acc[m][n][2], acc[m][n][3]);
        }
    }
}

// ================= logits body (step t) + combine + fused argmax ==============
__device__ __forceinline__ void logits_out(
    float acc[4][4][4], int own, int slot0, int nop,
    const float* __restrict__ lin_b, const int* __restrict__ seq_lens,
    float* __restrict__ out, int t,
    int bm, int bn, int wm, int wn, int g, int tig, int bx) {
#pragma unroll
    for (int half = 0; half < 2; half++) {
#pragma unroll
        for (int mt = 0; mt < 4; mt++) {
            int lr = wm * 64 + mt * 16 + g + half * 8;
            int gm = bm + lr;
            int len = seq_lens[gm];
            bool wr = (t < len);
            float* orow = out + (size_t)(g_off[gm] + t) * VV;

            float bvv = -3.4e38f;
            int   bii = 0;
#pragma unroll
            for (int nt = 0; nt < 4; nt++) {
                int col = bn + wn * 32 + nt * 8 + 2 * tig;
                float a0 = acc[mt][nt][half * 2 + 0];
                float a1 = acc[mt][nt][half * 2 + 1];
                float v0, v1;
                if (nop == 2) {
                    int oth = (own == slot0) ? slot0 + 1 : slot0;
                    v0 = a0 + __ldcg(&g_logP[oth][lr][col]);
                    v1 = a1 + __ldcg(&g_logP[oth][lr][col + 1]);
                } else {
                    float x0 = (own == 0) ? a0 : __ldcg(&g_logP[0][lr][col]);
                    float x1 = (own == 1) ? a0 : __ldcg(&g_logP[1][lr][col]);
                    float x2 = (own == 2) ? a0 : __ldcg(&g_logP[2][lr][col]);
                    float x3 = (own == 3) ? a0 : __ldcg(&g_logP[3][lr][col]);
                    v0 = (x0 + x1) + (x2 + x3);
                    float y0 = (own == 0) ? a1 : __ldcg(&g_logP[0][lr][col + 1]);
                    float y1 = (own == 1) ? a1 : __ldcg(&g_logP[1][lr][col + 1]);
                    float y2 = (own == 2) ? a1 : __ldcg(&g_logP[2][lr][col + 1]);
                    float y3 = (own == 3) ? a1 : __ldcg(&g_logP[3][lr][col + 1]);
                    v1 = (y0 + y1) + (y2 + y3);
                }
                v0 += lin_b[col];
                v1 += lin_b[col + 1];
                if (wr) *(float2*)&orow[col] = make_float2(v0, v1);
                if (v0 > bvv) { bvv = v0; bii = col; }
                if (v1 > bvv) { bvv = v1; bii = col + 1; }
            }
#pragma unroll
            for (int off = 1; off < 4; off <<= 1) {
                float ov = __shfl_xor_sync(0xffffffffu, bvv, off, 4);
                int   oi = __shfl_xor_sync(0xffffffffu, bii, off, 4);
                if (ov > bvv || (ov == bvv && oi < bii)) { bvv = ov; bii = oi; }
            }
            if (tig == 0) {
                int slot = bx * 4 + wn;
                g_pval[(size_t)gm * 256 + slot] = bvv;
                g_pidx[(size_t)gm * 256 + slot] = bii;
            }
        }
    }
}

__device__ __forceinline__ void logits_body(float* S, uint32_t sbda,
                                            const float* __restrict__ lin_W,
                                            const float* __restrict__ lin_b,
                                            const int* __restrict__ seq_lens,
                                            float* __restrict__ out,
                                            int t, int bx, int by, int bz) {
    const int nbt = g_nb[t];
    const bool split = (nbt <= 128);
    int bm, kbeg, nch, own, slot0, nop, cidx, cthr, fi;
    if (!split) {
        bm = bz * 128; kbeg = by * (HH / 2); nch = (HH / 2) / BK;  // 32
        own = bz * 2 + by; slot0 = bz * 2; nop = 2;
        cidx = bx * 2 + bz; cthr = 2; fi = bz;
    } else {
        int q = by * 2 + bz;
        bm = 0; kbeg = q * (HH / 4); nch = (HH / 4) / BK;          // 16
        own = q; slot0 = 0; nop = 4;
        cidx = bx; cthr = 4; fi = 0;
    }
    const int bn = bx * 128;
    const uint32_t sb = sbda;

    const int tid = threadIdx.x;
    const int wid = tid >> 5;
    const int wm  = wid >> 2, wn = wid & 3;
    const int g   = (tid & 31) >> 2, tig = tid & 3;
    const int kq  = tid & 3;
    LDSM_OFFSETS()

    const float* pa[2];
    const float* pb[2];
#pragma unroll
    for (int j = 0; j < 2; j++) {
        int row = ((j * 256 + tid) >> 2);
        pa[j] = g_h + (size_t)(bm + row) * HH + kbeg;
        pb[j] = lin_W + (size_t)(bn + row) * HH + kbeg;
    }

    float acc[4][4][4];
    ACC_ZERO(acc)
    float4 av[2], bv[2];
#define LG(ch)                                                    \
    { int kkb = (ch) * BK + kq * 4;                               \
      _Pragma("unroll")                                           \
      for (int j = 0; j < 2; j++) {                               \
          av[j] = *(const float4*)(pa[j] + kkb);                  \
          bv[j] = *(const float4*)(pb[j] + kkb); } }
    GEMM_PIPELINE(S, sb, nch, LG)
#undef LG

    // store my partial
#pragma unroll
    for (int half = 0; half < 2; half++)
#pragma unroll
        for (int mt = 0; mt < 4; mt++) {
            int lr = wm * 64 + mt * 16 + g + half * 8;
#pragma unroll
            for (int nt = 0; nt < 4; nt++) {
                int col = bn + wn * 32 + nt * 8 + 2 * tig;
                *(float2*)&g_logP[own][lr][col] =
                    make_float2(acc[mt][nt][half * 2], acc[mt][nt][half * 2 + 1]);
            }
        }
    __syncthreads();
    __shared__ int swin;
    if (tid == 0) {
        __threadfence();
        int old = atomicAdd(&g_lcnt[cidx], 1);
        swin = (old == cthr - 1);
        if (old == cthr - 1) g_lcnt[cidx] = 0;
    }
    __syncthreads();
    if (!swin) return;
    __threadfence();
    logits_out(acc, own, slot0, nop, lin_b, seq_lens, out, t,
               bm, bn, wm, wn, g, tig, bx);

    // ---- fused final argmax: 64 winners per m-tile ----
    __syncthreads();
    __shared__ int lastf;
    if (tid == 0) {
        __threadfence();
        int old = atomicAdd(&g_fcnt[fi], 1);
        lastf = (old == 63);
        if (old == 63) g_fcnt[fi] = 0;
    }
    __syncthreads();
    if (!lastf) return;
    __threadfence();

    {
        int wv = tid >> 5, lane = tid & 31;
#pragma unroll 1
        for (int i = 0; i < 16; i++) {
            int b = bm + wv * 16 + i;
            float v = -3.4e38f;
            int   bi = 0x7fffffff;
            for (int s = lane; s < 256; s += 32) {
                float pv = __ldcg(&g_pval[(size_t)b * 256 + s]);
                int   pi = __ldcg(&g_pidx[(size_t)b * 256 + s]);
                if (pv > v || (pv == v && pi < bi)) { v = pv; bi = pi; }
            }
#pragma unroll
            for (int off = 16; off; off >>= 1) {
                float ov = __shfl_xor_sync(0xffffffffu, v, off);
                int   oi = __shfl_xor_sync(0xffffffffu, bi, off);
                if (ov > v || (ov == v && oi < bi)) { v = ov; bi = oi; }
            }
            if (lane == 0) g_amax[b] = bi;
        }
    }
}

// ================= fused kernel: logits(t) || gates(t+1), 512 CTAs ============
// Interleaved decode: even CTAs = logits, odd CTAs = gates (balanced wave mix).
__global__ __launch_bounds__(256, 2)
void k_lg(const float* __restrict__ W_hh,
          const float* __restrict__ lin_W,
          const float* __restrict__ lin_b,
          const int*   __restrict__ seq_lens,
          float* __restrict__ out,
          int t) {
    extern __shared__ float S[];
    const uint32_t sbda = (uint32_t)__cvta_generic_to_shared(S);
    int cta = blockIdx.x;
    int kind = cta & 1;
    int idx  = cta >> 1;   // 0..255
    if (kind) {
        if (t + 1 >= TT) return;   // last step: no gates half
        gates_body(S, sbda, W_hh, t + 1,
                   idx & 31, (idx >> 5) & 3, (idx >> 7) & 1);
    } else {
        logits_body(S, sbda, lin_W, lin_b, seq_lens, out, t,
                    idx & 63, (idx >> 6) & 1, (idx >> 7) & 1);
    }
}

// ---------------- LSTM cell (4/8-way partial gather; t==0 -> zero gates) ------
__global__ void k_cell(const float* __restrict__ b_ih,
                       const float* __restrict__ b_hh,
                       const int* __restrict__ seq_lens,
                       int t) {
    int idx = blockIdx.x * 256 + threadIdx.x;
    int b = idx >> 10, j = idx & 1023;
    int nbt = g_nb[t];
    if (nbt <= 128 && b >= 128) return;
    if (t >= seq_lens[b]) return;

    float gate[4];
#pragma unroll
    for (int q = 0; q < 4; q++) {
        int jj = q * 1024 + j;
        float v;
        if (t == 0) {
            v = 0.0f;   // h(0)==0 -> hidden GEMM is exactly zero
        } else if (nbt > 128) {
            int s0 = (b >> 7) * 4, lr = b & 127;
            v = (g_P[s0][lr][jj] + g_P[s0 + 1][lr][jj]) +
                (g_P[s0 + 2][lr][jj] + g_P[s0 + 3][lr][jj]);
        } else {
            v = ((g_P[0][b][jj] + g_P[1][b][jj]) + (g_P[2][b][jj] + g_P[3][b][jj])) +
                ((g_P[4][b][jj] + g_P[5][b][jj]) + (g_P[6][b][jj] + g_P[7][b][jj]));
        }
        gate[q] = v;
    }
    const float* XW = g_XW + (size_t)(g_off[b] + t) * FOURH;
    const float* EW = (t == 0) ? g_I0 : g_EW + (size_t)g_amax[b] * FOURH;
    float i_ = gate[0] + XW[j]        + EW[j]        + b_ih[j]        + b_hh[j];
    float f_ = gate[1] + XW[1024 + j] + EW[1024 + j] + b_ih[1024 + j] + b_hh[1024 + j];
    float gg = gate[2] + XW[2048 + j] + EW[2048 + j] + b_ih[2048 + j] + b_hh[2048 + j];
    float o_ = gate[3] + XW[3072 + j] + EW[3072 + j] + b_ih[3072 + j] + b_hh[3072 + j];
    float c = sigm(f_) * g_c[idx] + sigm(i_) * tanhf(gg);
    float h = sigm(o_) * tanhf(c);
    g_c[idx] = c;
    g_h[idx] = h;
}

// ---------------- launch ------------------------------------------------------
extern "C" void kernel_launch(void* const* d_in, const int* in_sizes, int n_in,
                              void* d_out, int out_size) {
    const float* enc      = (const float*)d_in[0];
    const float* emb      = (const float*)d_in[1];
    const float* init_t   = (const float*)d_in[2];
    const float* W_ih     = (const float*)d_in[3];
    const float* W_hh     = (const float*)d_in[4];
    const float* b_ih     = (const float*)d_in[5];
    const float* b_hh     = (const float*)d_in[6];
    const float* lin_W    = (const float*)d_in[7];
    const float* lin_b    = (const float*)d_in[8];
    const int*   seq_lens = (const int*)d_in[9];
    float*       out      = (float*)d_out;

    cudaFuncSetAttribute(kA_x, cudaFuncAttributeMaxDynamicSharedMemorySize, SMEM_B);
    cudaFuncSetAttribute(kA_e, cudaFuncAttributeMaxDynamicSharedMemorySize, SMEM_B);
    cudaFuncSetAttribute(k_lg, cudaFuncAttributeMaxDynamicSharedMemorySize, SMEM_B);

    k_init<<<(BB * HH + 255) / 256, 256>>>();
    k_scan<<<1, 256>>>(seq_lens);
    k_I0<<<FOURH / 256, 256>>>(init_t, W_ih);
    kA_e<<<dim3(32, VV / 128), 256, SMEM_B>>>(emb, W_ih);
    kA_x<<<dim3(32, (BB * TT) / 128), 256, SMEM_B>>>(enc, W_ih);

    // t = 0: h(0)==0, gates GEMM skipped (cell uses zero-gates path).
    k_cell<<<(BB * HH + 255) / 256, 256>>>(b_ih, b_hh, seq_lens, 0);

    for (int t = 0; t < TT - 1; t++) {
        // fused: logits(t) on even CTAs, gates(t+1) on odd CTAs — independent.
        k_lg<<<512, 256, SMEM_B>>>(W_hh, lin_W, lin_b, seq_lens, out, t);
        k_cell<<<(BB * HH + 255) / 256, 256>>>(b_ih, b_hh, seq_lens, t + 1);
    }
    // final logits (gates half self-disables at t+1 == TT)
    k_lg<<<512, 256, SMEM_B>>>(W_hh, lin_W, lin_b, seq_lens, out, TT - 1);
}